// round 1
// baseline (speedup 1.0000x reference)
#include <cuda_runtime.h>

#define BATCH 64
#define TT 256
#define CC 512
#define NHD 8
#define HD 64
#define MROWS (BATCH*TT)      // 16384
#define FF 2048
#define ATT_SCALE 0.044194173824159216f   // 512^-0.5
#define NEGBIG (-1e9f)

// ---------------- scratch (device globals; no allocations) ----------------
__device__ float g_ln [MROWS*CC];
__device__ float g_q  [MROWS*CC];
__device__ float g_k  [MROWS*CC];
__device__ float g_v  [MROWS*CC];
__device__ float g_att[MROWS*CC];
__device__ float g_x1 [MROWS*CC];
__device__ float g_x2 [MROWS*CC];
__device__ float g_sc [(size_t)BATCH*NHD*TT*TT];   // 128 MB score scratch
__device__ float g_h  [(size_t)MROWS*FF];          // 128 MB FFN hidden

// ---------------- reductions ----------------
__device__ __forceinline__ float warpSum(float v){
    #pragma unroll
    for (int o = 16; o; o >>= 1) v += __shfl_xor_sync(0xffffffffu, v, o);
    return v;
}
__device__ __forceinline__ float warpMax(float v){
    #pragma unroll
    for (int o = 16; o; o >>= 1) v = fmaxf(v, __shfl_xor_sync(0xffffffffu, v, o));
    return v;
}

// ---------------- layernorm: one block (128 thr) per row of 512 ----------------
__global__ void ln_kernel(const float* __restrict__ x, const float* __restrict__ g,
                          const float* __restrict__ be, float* __restrict__ y)
{
    int r = blockIdx.x;
    int t = threadIdx.x;              // 0..127, one float4 each
    const float4* xr = reinterpret_cast<const float4*>(x + (size_t)r*CC);
    float4 v = xr[t];
    float s  = v.x + v.y + v.z + v.w;
    float sq = v.x*v.x + v.y*v.y + v.z*v.z + v.w*v.w;

    __shared__ float rs[4], rq[4];
    int lane = t & 31, wid = t >> 5;
    s = warpSum(s); sq = warpSum(sq);
    if (lane == 0){ rs[wid] = s; rq[wid] = sq; }
    __syncthreads();
    if (t == 0){
        float a = rs[0]+rs[1]+rs[2]+rs[3];
        float b = rq[0]+rq[1]+rq[2]+rq[3];
        rs[0] = a * (1.0f/CC);
        rq[0] = b * (1.0f/CC);
    }
    __syncthreads();
    float mu  = rs[0];
    float var = rq[0] - mu*mu;
    float rstd = rsqrtf(var + 1e-5f);

    const float4* g4  = reinterpret_cast<const float4*>(g);
    const float4* be4 = reinterpret_cast<const float4*>(be);
    float4 gg = g4[t], bb = be4[t];
    float4 o;
    o.x = (v.x - mu)*rstd*gg.x + bb.x;
    o.y = (v.y - mu)*rstd*gg.y + bb.y;
    o.z = (v.z - mu)*rstd*gg.z + bb.z;
    o.w = (v.w - mu)*rstd*gg.w + bb.w;
    reinterpret_cast<float4*>(y + (size_t)r*CC)[t] = o;
}

// ---------------- generic GEMM: C[M,N] = A[M,K] @ W[K,N] (+bias)(+relu)(+res) ---
// BM=128 BN=128 BK=8, 256 threads, 8x8 per-thread microtile. M%128==0, N%128==0, K%8==0.
#define BM 128
#define BN 128
#define BKK 8
template<bool BIAS, bool RELU, bool RES>
__global__ __launch_bounds__(256, 2)
void gemm_k(const float* __restrict__ A, const float* __restrict__ W,
            const float* __restrict__ bias, const float* __restrict__ res,
            float* __restrict__ C, int M, int N, int K)
{
    __shared__ float As[BKK][BM];
    __shared__ float Bs[BKK][BN];
    int tid = threadIdx.x;
    int row0 = blockIdx.y * BM;
    int col0 = blockIdx.x * BN;
    int tx = tid & 15, ty = tid >> 4;

    int ar = tid >> 1;            // 0..127
    int ac = (tid & 1) * 4;       // 0 or 4
    int br = tid >> 5;            // 0..7
    int bc = (tid & 31) * 4;      // 0..124

    float acc[8][8];
    #pragma unroll
    for (int i = 0; i < 8; i++)
        #pragma unroll
        for (int j = 0; j < 8; j++) acc[i][j] = 0.f;

    for (int k0 = 0; k0 < K; k0 += BKK){
        float4 a4 = *reinterpret_cast<const float4*>(A + (size_t)(row0 + ar)*K + k0 + ac);
        As[ac+0][ar] = a4.x; As[ac+1][ar] = a4.y; As[ac+2][ar] = a4.z; As[ac+3][ar] = a4.w;
        float4 b4 = *reinterpret_cast<const float4*>(W + (size_t)(k0 + br)*N + col0 + bc);
        *reinterpret_cast<float4*>(&Bs[br][bc]) = b4;
        __syncthreads();
        #pragma unroll
        for (int k = 0; k < BKK; k++){
            float a8[8], b8[8];
            #pragma unroll
            for (int i = 0; i < 8; i++) a8[i] = As[k][ty*8 + i];
            #pragma unroll
            for (int j = 0; j < 8; j++) b8[j] = Bs[k][tx*8 + j];
            #pragma unroll
            for (int i = 0; i < 8; i++)
                #pragma unroll
                for (int j = 0; j < 8; j++) acc[i][j] += a8[i]*b8[j];
        }
        __syncthreads();
    }

    #pragma unroll
    for (int i = 0; i < 8; i++){
        int r = row0 + ty*8 + i;
        #pragma unroll
        for (int j = 0; j < 8; j++){
            int c = col0 + tx*8 + j;
            float v = acc[i][j];
            if (BIAS) v += bias[c];
            if (RELU) v = fmaxf(v, 0.f);
            if (RES)  v += res[(size_t)r*N + c];
            C[(size_t)r*N + c] = v;
        }
    }
}

// ---------------- QK^T batched: S[bh, i, j] = scale * Q_bh[i,:] . K_bh[j,:] -------
// grid (4,4,512), block 256. Tiles 64x64, full K=64 in smem, transposed [k][m].
__global__ __launch_bounds__(256)
void qk_kernel(const float* __restrict__ Q, const float* __restrict__ Kt,
               float* __restrict__ S)
{
    int bh = blockIdx.z;
    int b = bh >> 3, h = bh & 7;
    int q0 = blockIdx.y * 64;
    int c0 = blockIdx.x * 64;
    const float* Qb = Q + (size_t)b*TT*CC + h*HD;
    const float* Kb = Kt + (size_t)b*TT*CC + h*HD;

    __shared__ float Qs[64][64];   // [k][row]
    __shared__ float Ks[64][64];   // [k][col]
    int tid = threadIdx.x;
    int row = tid >> 2;
    int kb  = (tid & 3) * 16;
    #pragma unroll
    for (int u = 0; u < 16; u += 4){
        float4 v = *reinterpret_cast<const float4*>(Qb + (size_t)(q0 + row)*CC + kb + u);
        Qs[kb+u+0][row] = v.x; Qs[kb+u+1][row] = v.y; Qs[kb+u+2][row] = v.z; Qs[kb+u+3][row] = v.w;
        float4 w = *reinterpret_cast<const float4*>(Kb + (size_t)(c0 + row)*CC + kb + u);
        Ks[kb+u+0][row] = w.x; Ks[kb+u+1][row] = w.y; Ks[kb+u+2][row] = w.z; Ks[kb+u+3][row] = w.w;
    }
    __syncthreads();

    int tx = tid & 15, ty = tid >> 4;
    float acc[4][4];
    #pragma unroll
    for (int i = 0; i < 4; i++)
        #pragma unroll
        for (int j = 0; j < 4; j++) acc[i][j] = 0.f;

    #pragma unroll 8
    for (int k = 0; k < 64; k++){
        float a4[4], b4[4];
        #pragma unroll
        for (int i = 0; i < 4; i++) a4[i] = Qs[k][ty*4 + i];
        #pragma unroll
        for (int j = 0; j < 4; j++) b4[j] = Ks[k][tx*4 + j];
        #pragma unroll
        for (int i = 0; i < 4; i++)
            #pragma unroll
            for (int j = 0; j < 4; j++) acc[i][j] += a4[i]*b4[j];
    }

    float* Sb = S + (size_t)bh*TT*TT;
    #pragma unroll
    for (int i = 0; i < 4; i++)
        #pragma unroll
        for (int j = 0; j < 4; j++)
            Sb[(size_t)(q0 + ty*4 + i)*TT + c0 + tx*4 + j] = acc[i][j] * ATT_SCALE;
}

// ---------------- masked softmax over rows of 256, reference semantics ----------
// grid (T, B*H), block 256. causal!=0 adds j<=i constraint.
__global__ __launch_bounds__(256)
void softmax_kernel(float* __restrict__ S, const int* __restrict__ mask, int causal)
{
    int bh = blockIdx.y;
    int b = bh >> 3;
    int i = blockIdx.x;
    int j = threadIdx.x;
    float* row = S + (size_t)bh*TT*TT + (size_t)i*TT;

    int valid = mask[(size_t)b*TT*TT + (size_t)i*TT + j] != 0;
    if (causal && j > i) valid = 0;
    float v = valid ? row[j] : NEGBIG;

    __shared__ float red[8];
    int lane = j & 31, wid = j >> 5;

    float m = warpMax(v);
    if (lane == 0) red[wid] = m;
    __syncthreads();
    if (wid == 0){
        float t = (lane < 8) ? red[lane] : -3.4e38f;
        t = warpMax(t);
        if (lane == 0) red[0] = t;
    }
    __syncthreads();
    m = red[0];
    __syncthreads();

    float e = expf(v - m);
    float s = warpSum(e);
    if (lane == 0) red[wid] = s;
    __syncthreads();
    if (wid == 0){
        float t = (lane < 8) ? red[lane] : 0.f;
        t = warpSum(t);
        if (lane == 0) red[0] = t;
    }
    __syncthreads();
    row[j] = e / red[0];
}

// ---------------- P@V batched: out[bh, i, d] = sum_j P[i,j] V_bh[j,d] ------------
// grid (4, 512): 64-row q tiles per (b,h). block 256, 4x4 microtile, BK=16.
__global__ __launch_bounds__(256)
void pv_kernel(const float* __restrict__ P, const float* __restrict__ V,
               float* __restrict__ O)
{
    int bh = blockIdx.y;
    int b = bh >> 3, h = bh & 7;
    int q0 = blockIdx.x * 64;
    const float* Pb = P + (size_t)bh*TT*TT;
    const float* Vb = V + (size_t)b*TT*CC + h*HD;

    __shared__ float Ps[16][64];   // [k][m]
    __shared__ float Vs[16][64];   // [k][n]
    int tid = threadIdx.x;
    int tx = tid & 15, ty = tid >> 4;

    float acc[4][4];
    #pragma unroll
    for (int i = 0; i < 4; i++)
        #pragma unroll
        for (int j = 0; j < 4; j++) acc[i][j] = 0.f;

    int prow = tid >> 2;           // 0..63
    int pk   = (tid & 3) * 4;      // 0..12
    int vrow = tid >> 4;           // 0..15
    int vcol = (tid & 15) * 4;     // 0..60

    for (int k0 = 0; k0 < TT; k0 += 16){
        float4 p4 = *reinterpret_cast<const float4*>(Pb + (size_t)(q0 + prow)*TT + k0 + pk);
        Ps[pk+0][prow] = p4.x; Ps[pk+1][prow] = p4.y; Ps[pk+2][prow] = p4.z; Ps[pk+3][prow] = p4.w;
        float4 v4 = *reinterpret_cast<const float4*>(Vb + (size_t)(k0 + vrow)*CC + vcol);
        *reinterpret_cast<float4*>(&Vs[vrow][vcol]) = v4;
        __syncthreads();
        #pragma unroll
        for (int k = 0; k < 16; k++){
            float a4[4], b4[4];
            #pragma unroll
            for (int i = 0; i < 4; i++) a4[i] = Ps[k][ty*4 + i];
            #pragma unroll
            for (int j = 0; j < 4; j++) b4[j] = Vs[k][tx*4 + j];
            #pragma unroll
            for (int i = 0; i < 4; i++)
                #pragma unroll
                for (int j = 0; j < 4; j++) acc[i][j] += a4[i]*b4[j];
        }
        __syncthreads();
    }

    #pragma unroll
    for (int i = 0; i < 4; i++)
        #pragma unroll
        for (int j = 0; j < 4; j++)
            O[(size_t)(b*TT + q0 + ty*4 + i)*CC + h*HD + tx*4 + j] = acc[i][j];
}

// ---------------- host orchestration ----------------
static float* symaddr(const void* sym){
    void* p = nullptr;
    cudaGetSymbolAddress(&p, sym);
    return (float*)p;
}

extern "C" void kernel_launch(void* const* d_in, const int* in_sizes, int n_in,
                              void* d_out, int out_size)
{
    const float* x    = (const float*)d_in[0];
    const float* ca   = (const float*)d_in[1];
    const int*   x_m  = (const int*)  d_in[2];
    const int*   ca_m = (const int*)  d_in[3];
    const float* Wq_s = (const float*)d_in[4];
    const float* Wk_s = (const float*)d_in[5];
    const float* Wv_s = (const float*)d_in[6];
    const float* Wo_s = (const float*)d_in[7];
    const float* bo_s = (const float*)d_in[8];
    const float* Wq_c = (const float*)d_in[9];
    const float* Wk_c = (const float*)d_in[10];
    const float* Wv_c = (const float*)d_in[11];
    const float* Wo_c = (const float*)d_in[12];
    const float* bo_c = (const float*)d_in[13];
    const float* g1   = (const float*)d_in[14];
    const float* be1  = (const float*)d_in[15];
    const float* g2   = (const float*)d_in[16];
    const float* be2  = (const float*)d_in[17];
    const float* g3   = (const float*)d_in[18];
    const float* be3  = (const float*)d_in[19];
    const float* Wf1  = (const float*)d_in[20];
    const float* bf1  = (const float*)d_in[21];
    const float* Wf2  = (const float*)d_in[22];
    const float* bf2  = (const float*)d_in[23];
    float* out = (float*)d_out;

    float* p_ln  = symaddr(g_ln);
    float* p_q   = symaddr(g_q);
    float* p_k   = symaddr(g_k);
    float* p_v   = symaddr(g_v);
    float* p_att = symaddr(g_att);
    float* p_x1  = symaddr(g_x1);
    float* p_x2  = symaddr(g_x2);
    float* p_sc  = symaddr(g_sc);
    float* p_h   = symaddr(g_h);

    dim3 gemmCC(CC/BN, MROWS/BM);       // (4,128)
    dim3 gemmFF(FF/BN, MROWS/BM);       // (16,128)
    dim3 qkG(4, 4, BATCH*NHD);
    dim3 smG(TT, BATCH*NHD);
    dim3 pvG(4, BATCH*NHD);

    // ===== self-attention =====
    ln_kernel<<<MROWS,128>>>(x, g1, be1, p_ln);
    gemm_k<false,false,false><<<gemmCC,256>>>(p_ln, Wq_s, nullptr, nullptr, p_q, MROWS, CC, CC);
    gemm_k<false,false,false><<<gemmCC,256>>>(p_ln, Wk_s, nullptr, nullptr, p_k, MROWS, CC, CC);
    gemm_k<false,false,false><<<gemmCC,256>>>(p_ln, Wv_s, nullptr, nullptr, p_v, MROWS, CC, CC);
    qk_kernel<<<qkG,256>>>(p_q, p_k, p_sc);
    softmax_kernel<<<smG,256>>>(p_sc, x_m, 1);
    pv_kernel<<<pvG,256>>>(p_sc, p_v, p_att);
    gemm_k<true,false,true><<<gemmCC,256>>>(p_att, Wo_s, bo_s, x, p_x1, MROWS, CC, CC);

    // ===== cross-attention (K,V from raw ca) =====
    ln_kernel<<<MROWS,128>>>(p_x1, g2, be2, p_ln);
    gemm_k<false,false,false><<<gemmCC,256>>>(p_ln, Wq_c, nullptr, nullptr, p_q, MROWS, CC, CC);
    gemm_k<false,false,false><<<gemmCC,256>>>(ca,   Wk_c, nullptr, nullptr, p_k, MROWS, CC, CC);
    gemm_k<false,false,false><<<gemmCC,256>>>(ca,   Wv_c, nullptr, nullptr, p_v, MROWS, CC, CC);
    qk_kernel<<<qkG,256>>>(p_q, p_k, p_sc);
    softmax_kernel<<<smG,256>>>(p_sc, ca_m, 0);
    pv_kernel<<<pvG,256>>>(p_sc, p_v, p_att);
    gemm_k<true,false,true><<<gemmCC,256>>>(p_att, Wo_c, bo_c, p_x1, p_x2, MROWS, CC, CC);

    // ===== feed-forward =====
    ln_kernel<<<MROWS,128>>>(p_x2, g3, be3, p_ln);
    gemm_k<true,true,false><<<gemmFF,256>>>(p_ln, Wf1, bf1, nullptr, p_h, MROWS, FF, CC);
    gemm_k<true,false,true><<<gemmCC,256>>>(p_h, Wf2, bf2, p_x2, out, MROWS, CC, FF);

    (void)in_sizes; (void)n_in; (void)out_size;
}

// round 3
// speedup vs baseline: 1.9951x; 1.9951x over previous
#include <cuda_runtime.h>
#include <cstdint>

#define BATCH 64
#define TT 256
#define CC 512
#define NHD 8
#define HD 64
#define MROWS (BATCH*TT)      // 16384
#define FF 2048
#define ATT_SCALE 0.044194173824159216f   // 512^-0.5
#define NEGBIG (-1e9f)

// ---------------- scratch (device globals; no allocations) ----------------
__device__ float g_ln [MROWS*CC];
__device__ float g_q  [MROWS*CC];
__device__ float g_k  [MROWS*CC];
__device__ float g_v  [MROWS*CC];
__device__ float g_att[MROWS*CC];
__device__ float g_x1 [MROWS*CC];
__device__ float g_x2 [MROWS*CC];
__device__ float g_sc [(size_t)BATCH*NHD*TT*TT];   // 64 MB scores
__device__ float g_h  [(size_t)MROWS*FF];          // FFN hidden

// ---------------- helpers ----------------
__device__ __forceinline__ uint32_t f2tf(float f){
    uint32_t r; asm("cvt.rna.tf32.f32 %0, %1;" : "=r"(r) : "f"(f)); return r;
}
__device__ __forceinline__ void mma8(float4& d, const uint32_t* a, const uint32_t* b){
    asm volatile("mma.sync.aligned.m16n8k8.row.col.f32.tf32.tf32.f32 "
        "{%0,%1,%2,%3}, {%4,%5,%6,%7}, {%8,%9}, {%0,%1,%2,%3};"
        : "+f"(d.x), "+f"(d.y), "+f"(d.z), "+f"(d.w)
        : "r"(a[0]), "r"(a[1]), "r"(a[2]), "r"(a[3]), "r"(b[0]), "r"(b[1]));
}
__device__ __forceinline__ float warpSum(float v){
    #pragma unroll
    for (int o = 16; o; o >>= 1) v += __shfl_xor_sync(0xffffffffu, v, o);
    return v;
}
__device__ __forceinline__ float warpMax(float v){
    #pragma unroll
    for (int o = 16; o; o >>= 1) v = fmaxf(v, __shfl_xor_sync(0xffffffffu, v, o));
    return v;
}

// ---------------- layernorm ----------------
__global__ void ln_kernel(const float* __restrict__ x, const float* __restrict__ g,
                          const float* __restrict__ be, float* __restrict__ y)
{
    int r = blockIdx.x;
    int t = threadIdx.x;
    const float4* xr = reinterpret_cast<const float4*>(x + (size_t)r*CC);
    float4 v = xr[t];
    float s  = v.x + v.y + v.z + v.w;
    float sq = v.x*v.x + v.y*v.y + v.z*v.z + v.w*v.w;

    __shared__ float rs[4], rq[4];
    int lane = t & 31, wid = t >> 5;
    s = warpSum(s); sq = warpSum(sq);
    if (lane == 0){ rs[wid] = s; rq[wid] = sq; }
    __syncthreads();
    if (t == 0){
        float a = rs[0]+rs[1]+rs[2]+rs[3];
        float b = rq[0]+rq[1]+rq[2]+rq[3];
        rs[0] = a * (1.0f/CC);
        rq[0] = b * (1.0f/CC);
    }
    __syncthreads();
    float mu  = rs[0];
    float var = rq[0] - mu*mu;
    float rstd = rsqrtf(var + 1e-5f);

    const float4* g4  = reinterpret_cast<const float4*>(g);
    const float4* be4 = reinterpret_cast<const float4*>(be);
    float4 gg = g4[t], bb = be4[t];
    float4 o;
    o.x = (v.x - mu)*rstd*gg.x + bb.x;
    o.y = (v.y - mu)*rstd*gg.y + bb.y;
    o.z = (v.z - mu)*rstd*gg.z + bb.z;
    o.w = (v.w - mu)*rstd*gg.w + bb.w;
    reinterpret_cast<float4*>(y + (size_t)r*CC)[t] = o;
}

// =================== tf32 mma.sync GEMM ===================
// C[M,N] = A[M,K] @ B, A row-major [M][K].
// TRB=false: B global [K][N]; TRB=true: B global [N][K].
// BM=128 fixed; BN = 128 or 64. 256 threads, 8 warps (4M x 2N).
template<int BN, bool TRB, bool BIAS, bool RELU, bool RES, bool SCALE>
__global__ __launch_bounds__(256)
void gemm_mma(const float* __restrict__ A, int lda, long long sAb, long long sAh,
              const float* __restrict__ B, int ldb, long long sBb, long long sBh,
              const float* __restrict__ bias, const float* __restrict__ res,
              float* __restrict__ C, int ldc, long long sCb, long long sCh,
              int K, float scale)
{
    constexpr int NT   = BN/16;           // n-tiles (n8) per warp
    constexpr int WN   = BN/2;            // warp n extent
    constexpr int STRA = 129;
    constexpr int STRB = (BN==128)?129:65;
    constexpr int ABUF = 32*STRA;
    constexpr int BBUF = 32*STRB;
    constexpr int PB   = BN/8;            // B prefetch floats per thread

    extern __shared__ uint32_t sm[];
    uint32_t* As = sm;
    uint32_t* Bs = sm + 2*ABUF;

    const int tid  = threadIdx.x;
    const int w    = tid >> 5, lane = tid & 31;
    const int g    = lane >> 2, c = lane & 3;
    const int row0 = blockIdx.y * 128;
    const int col0 = blockIdx.x * BN;
    {
        const long long zb = blockIdx.z >> 3, zh = blockIdx.z & 7;
        A += zb*sAb + zh*sAh;
        B += zb*sBb + zh*sBh;
        C += zb*sCb + zh*sCh;
    }

    float4 acc[2][NT];
    #pragma unroll
    for (int mt = 0; mt < 2; mt++)
        #pragma unroll
        for (int nt = 0; nt < NT; nt++)
            acc[mt][nt] = make_float4(0.f, 0.f, 0.f, 0.f);

    const int nch = K >> 5;
    const int swzA = (lane & 7) << 3;

    // ---- copy stage helpers ----
    #define LDG_A(k0, r) do { \
        _Pragma("unroll") \
        for (int i = 0; i < 16; i++) \
            (r)[i] = A[(size_t)(row0 + w + 8*i)*lda + (k0) + lane]; \
    } while(0)
    #define STS_A(dst, r) do { \
        _Pragma("unroll") \
        for (int i = 0; i < 16; i++){ \
            int m = w + 8*i; \
            (dst)[lane*STRA + (m ^ swzA)] = f2tf((r)[i]); \
        } \
    } while(0)
    #define LDG_B(k0, r) do { \
        if (TRB){ \
            _Pragma("unroll") \
            for (int i = 0; i < PB; i++) \
                (r)[i] = B[(size_t)(col0 + w + 8*i)*ldb + (k0) + lane]; \
        } else if (BN == 128){ \
            _Pragma("unroll") \
            for (int j = 0; j < 4; j++){ \
                float4 v = *reinterpret_cast<const float4*>(&B[(size_t)((k0) + w + 8*j)*ldb + col0 + lane*4]); \
                (r)[j*4+0]=v.x; (r)[j*4+1]=v.y; (r)[j*4+2]=v.z; (r)[j*4+3]=v.w; \
            } \
        } else { \
            _Pragma("unroll") \
            for (int j = 0; j < 2; j++){ \
                float4 v = *reinterpret_cast<const float4*>(&B[(size_t)((k0) + (tid>>4) + 16*j)*ldb + col0 + (tid&15)*4]); \
                (r)[j*4+0]=v.x; (r)[j*4+1]=v.y; (r)[j*4+2]=v.z; (r)[j*4+3]=v.w; \
            } \
        } \
    } while(0)
    #define STS_B(dst, r) do { \
        if (TRB){ \
            _Pragma("unroll") \
            for (int i = 0; i < PB; i++){ \
                int n = w + 8*i; \
                (dst)[lane*STRB + (n ^ swzA)] = f2tf((r)[i]); \
            } \
        } else if (BN == 128){ \
            _Pragma("unroll") \
            for (int j = 0; j < 4; j++){ \
                int k = w + 8*j; \
                int nb = (lane*4) ^ ((k & 7) << 3); \
                (dst)[k*STRB + nb + 0] = f2tf((r)[j*4+0]); \
                (dst)[k*STRB + nb + 1] = f2tf((r)[j*4+1]); \
                (dst)[k*STRB + nb + 2] = f2tf((r)[j*4+2]); \
                (dst)[k*STRB + nb + 3] = f2tf((r)[j*4+3]); \
            } \
        } else { \
            _Pragma("unroll") \
            for (int j = 0; j < 2; j++){ \
                int k = (tid>>4) + 16*j; \
                int nb = ((tid&15)*4) ^ ((k & 7) << 3); \
                (dst)[k*STRB + nb + 0] = f2tf((r)[j*4+0]); \
                (dst)[k*STRB + nb + 1] = f2tf((r)[j*4+1]); \
                (dst)[k*STRB + nb + 2] = f2tf((r)[j*4+2]); \
                (dst)[k*STRB + nb + 3] = f2tf((r)[j*4+3]); \
            } \
        } \
    } while(0)

    // ---- prologue: chunk 0 ----
    {
        float ra[16], rb[PB];
        LDG_A(0, ra); LDG_B(0, rb);
        STS_A(As, ra); STS_B(Bs, rb);
    }
    __syncthreads();

    const int mwb = (w & 3) * 32;
    const int nwb = (w >> 2) * WN;

    for (int ch = 0; ch < nch; ch++){
        const int p = ch & 1;
        float ra[16], rb[PB];
        const bool more = (ch + 1 < nch);
        if (more){ LDG_A((ch+1)*32, ra); LDG_B((ch+1)*32, rb); }

        const uint32_t* Ab = As + p*ABUF;
        const uint32_t* Bb = Bs + p*BBUF;
        #pragma unroll
        for (int ks = 0; ks < 4; ks++){
            const int kk = ks*8;
            uint32_t af[2][4], bf[NT][2];
            #pragma unroll
            for (int mt = 0; mt < 2; mt++){
                int mb = mwb + mt*16 + g;
                af[mt][0] = Ab[(kk+c  )*STRA + ( mb      ^ ( c    <<3))];
                af[mt][1] = Ab[(kk+c  )*STRA + ((mb + 8) ^ ( c    <<3))];
                af[mt][2] = Ab[(kk+c+4)*STRA + ( mb      ^ ((c+4) <<3))];
                af[mt][3] = Ab[(kk+c+4)*STRA + ((mb + 8) ^ ((c+4) <<3))];
            }
            #pragma unroll
            for (int nt = 0; nt < NT; nt++){
                int nb = nwb + nt*8 + g;
                bf[nt][0] = Bb[(kk+c  )*STRB + (nb ^ ( c    <<3))];
                bf[nt][1] = Bb[(kk+c+4)*STRB + (nb ^ ((c+4) <<3))];
            }
            #pragma unroll
            for (int mt = 0; mt < 2; mt++)
                #pragma unroll
                for (int nt = 0; nt < NT; nt++)
                    mma8(acc[mt][nt], af[mt], bf[nt]);
        }

        if (more){
            STS_A(As + (p^1)*ABUF, ra);
            STS_B(Bs + (p^1)*BBUF, rb);
        }
        __syncthreads();
    }

    // ---- epilogue ----
    #pragma unroll
    for (int mt = 0; mt < 2; mt++){
        int r0 = row0 + mwb + mt*16 + g;
        #pragma unroll
        for (int nt = 0; nt < NT; nt++){
            int cx = col0 + nwb + nt*8 + c*2;
            float4 v = acc[mt][nt];
            if (SCALE){ v.x*=scale; v.y*=scale; v.z*=scale; v.w*=scale; }
            if (BIAS){
                float b0 = bias[cx], b1 = bias[cx+1];
                v.x += b0; v.y += b1; v.z += b0; v.w += b1;
            }
            if (RELU){
                v.x = fmaxf(v.x, 0.f); v.y = fmaxf(v.y, 0.f);
                v.z = fmaxf(v.z, 0.f); v.w = fmaxf(v.w, 0.f);
            }
            if (RES){
                float2 r1 = *reinterpret_cast<const float2*>(&res[(size_t)r0*ldc + cx]);
                float2 r2 = *reinterpret_cast<const float2*>(&res[(size_t)(r0+8)*ldc + cx]);
                v.x += r1.x; v.y += r1.y; v.z += r2.x; v.w += r2.y;
            }
            *reinterpret_cast<float2*>(&C[(size_t)r0*ldc + cx])     = make_float2(v.x, v.y);
            *reinterpret_cast<float2*>(&C[(size_t)(r0+8)*ldc + cx]) = make_float2(v.z, v.w);
        }
    }
    #undef LDG_A
    #undef STS_A
    #undef LDG_B
    #undef STS_B
}

// ---------------- masked softmax (reference semantics) ----------------
__global__ __launch_bounds__(256)
void softmax_kernel(float* __restrict__ S, const int* __restrict__ mask, int causal)
{
    int bh = blockIdx.y;
    int b = bh >> 3;
    int i = blockIdx.x;
    int j = threadIdx.x;
    float* row = S + (size_t)bh*TT*TT + (size_t)i*TT;

    int valid = mask[(size_t)b*TT*TT + (size_t)i*TT + j] != 0;
    if (causal && j > i) valid = 0;
    float v = valid ? row[j] : NEGBIG;

    __shared__ float red[8];
    int lane = j & 31, wid = j >> 5;

    float m = warpMax(v);
    if (lane == 0) red[wid] = m;
    __syncthreads();
    if (wid == 0){
        float t = (lane < 8) ? red[lane] : -3.4e38f;
        t = warpMax(t);
        if (lane == 0) red[0] = t;
    }
    __syncthreads();
    m = red[0];
    __syncthreads();

    float e = expf(v - m);
    float s = warpSum(e);
    if (lane == 0) red[wid] = s;
    __syncthreads();
    if (wid == 0){
        float t = (lane < 8) ? red[lane] : 0.f;
        t = warpSum(t);
        if (lane == 0) red[0] = t;
    }
    __syncthreads();
    row[j] = e / red[0];
}

// ---------------- host orchestration ----------------
static float* symaddr(const void* sym){
    void* p = nullptr;
    cudaGetSymbolAddress(&p, sym);
    return (float*)p;
}

#define SMEM128 ((2*32*129 + 2*32*129) * 4)
#define SMEM64  ((2*32*129 + 2*32*65) * 4)

extern "C" void kernel_launch(void* const* d_in, const int* in_sizes, int n_in,
                              void* d_out, int out_size)
{
    const float* x    = (const float*)d_in[0];
    const float* ca   = (const float*)d_in[1];
    const int*   x_m  = (const int*)  d_in[2];
    const int*   ca_m = (const int*)  d_in[3];
    const float* Wq_s = (const float*)d_in[4];
    const float* Wk_s = (const float*)d_in[5];
    const float* Wv_s = (const float*)d_in[6];
    const float* Wo_s = (const float*)d_in[7];
    const float* bo_s = (const float*)d_in[8];
    const float* Wq_c = (const float*)d_in[9];
    const float* Wk_c = (const float*)d_in[10];
    const float* Wv_c = (const float*)d_in[11];
    const float* Wo_c = (const float*)d_in[12];
    const float* bo_c = (const float*)d_in[13];
    const float* g1   = (const float*)d_in[14];
    const float* be1  = (const float*)d_in[15];
    const float* g2   = (const float*)d_in[16];
    const float* be2  = (const float*)d_in[17];
    const float* g3   = (const float*)d_in[18];
    const float* be3  = (const float*)d_in[19];
    const float* Wf1  = (const float*)d_in[20];
    const float* bf1  = (const float*)d_in[21];
    const float* Wf2  = (const float*)d_in[22];
    const float* bf2  = (const float*)d_in[23];
    float* out = (float*)d_out;

    float* p_ln  = symaddr(g_ln);
    float* p_q   = symaddr(g_q);
    float* p_k   = symaddr(g_k);
    float* p_v   = symaddr(g_v);
    float* p_att = symaddr(g_att);
    float* p_x1  = symaddr(g_x1);
    float* p_x2  = symaddr(g_x2);
    float* p_sc  = symaddr(g_sc);
    float* p_h   = symaddr(g_h);

    static bool attrDone = false;
    if (!attrDone){
        cudaFuncSetAttribute(gemm_mma<128,false,false,false,false,false>, cudaFuncAttributeMaxDynamicSharedMemorySize, SMEM128);
        cudaFuncSetAttribute(gemm_mma<128,true, false,false,false,true >, cudaFuncAttributeMaxDynamicSharedMemorySize, SMEM128);
        cudaFuncSetAttribute(gemm_mma<64, false,false,false,false,false>, cudaFuncAttributeMaxDynamicSharedMemorySize, SMEM64);
        cudaFuncSetAttribute(gemm_mma<128,false,true, false,true, false>, cudaFuncAttributeMaxDynamicSharedMemorySize, SMEM128);
        cudaFuncSetAttribute(gemm_mma<128,false,true, true, false,false>, cudaFuncAttributeMaxDynamicSharedMemorySize, SMEM128);
        attrDone = true;
    }

    dim3 gCC(CC/128, MROWS/128, 1);      // (4,128)
    dim3 gFF(FF/128, MROWS/128, 1);      // (16,128)
    dim3 gQK(TT/128, TT/128, BATCH*NHD); // (2,2,512)
    dim3 gPV(1, TT/128, BATCH*NHD);      // (1,2,512)
    dim3 smG(TT, BATCH*NHD);

    const long long sTok = (long long)TT*CC;     // per-batch token-row stride
    const long long sScB = (long long)NHD*TT*TT;
    const long long sScH = (long long)TT*TT;

    // ===== self-attention =====
    ln_kernel<<<MROWS,128>>>(x, g1, be1, p_ln);
    gemm_mma<128,false,false,false,false,false><<<gCC,256,SMEM128>>>(p_ln, CC,0,0, Wq_s, CC,0,0, nullptr,nullptr, p_q, CC,0,0, CC, 1.f);
    gemm_mma<128,false,false,false,false,false><<<gCC,256,SMEM128>>>(p_ln, CC,0,0, Wk_s, CC,0,0, nullptr,nullptr, p_k, CC,0,0, CC, 1.f);
    gemm_mma<128,false,false,false,false,false><<<gCC,256,SMEM128>>>(p_ln, CC,0,0, Wv_s, CC,0,0, nullptr,nullptr, p_v, CC,0,0, CC, 1.f);
    // QK^T per (b,h): A=q [t][d], B=k [t2][d] (TRB)
    gemm_mma<128,true,false,false,false,true><<<gQK,256,SMEM128>>>(
        p_q, CC, sTok, HD, p_k, CC, sTok, HD,
        nullptr, nullptr, p_sc, TT, sScB, sScH, HD, ATT_SCALE);
    softmax_kernel<<<smG,256>>>(p_sc, x_m, 1);
    // P@V per (b,h): A=P [t][t2], B=v [t2][d]
    gemm_mma<64,false,false,false,false,false><<<gPV,256,SMEM64>>>(
        p_sc, TT, sScB, sScH, p_v, CC, sTok, HD,
        nullptr, nullptr, p_att, CC, sTok, HD, TT, 1.f);
    gemm_mma<128,false,true,false,true,false><<<gCC,256,SMEM128>>>(p_att, CC,0,0, Wo_s, CC,0,0, bo_s, x, p_x1, CC,0,0, CC, 1.f);

    // ===== cross-attention =====
    ln_kernel<<<MROWS,128>>>(p_x1, g2, be2, p_ln);
    gemm_mma<128,false,false,false,false,false><<<gCC,256,SMEM128>>>(p_ln, CC,0,0, Wq_c, CC,0,0, nullptr,nullptr, p_q, CC,0,0, CC, 1.f);
    gemm_mma<128,false,false,false,false,false><<<gCC,256,SMEM128>>>(ca,   CC,0,0, Wk_c, CC,0,0, nullptr,nullptr, p_k, CC,0,0, CC, 1.f);
    gemm_mma<128,false,false,false,false,false><<<gCC,256,SMEM128>>>(ca,   CC,0,0, Wv_c, CC,0,0, nullptr,nullptr, p_v, CC,0,0, CC, 1.f);
    gemm_mma<128,true,false,false,false,true><<<gQK,256,SMEM128>>>(
        p_q, CC, sTok, HD, p_k, CC, sTok, HD,
        nullptr, nullptr, p_sc, TT, sScB, sScH, HD, ATT_SCALE);
    softmax_kernel<<<smG,256>>>(p_sc, ca_m, 0);
    gemm_mma<64,false,false,false,false,false><<<gPV,256,SMEM64>>>(
        p_sc, TT, sScB, sScH, p_v, CC, sTok, HD,
        nullptr, nullptr, p_att, CC, sTok, HD, TT, 1.f);
    gemm_mma<128,false,true,false,true,false><<<gCC,256,SMEM128>>>(p_att, CC,0,0, Wo_c, CC,0,0, bo_c, p_x1, p_x2, CC,0,0, CC, 1.f);

    // ===== feed-forward =====
    ln_kernel<<<MROWS,128>>>(p_x2, g3, be3, p_ln);
    gemm_mma<128,false,true,true,false,false><<<gFF,256,SMEM128>>>(p_ln, CC,0,0, Wf1, FF,0,0, bf1, nullptr, p_h, FF,0,0, CC, 1.f);
    gemm_mma<128,false,true,false,true,false><<<gCC,256,SMEM128>>>(p_h, FF,0,0, Wf2, CC,0,0, bf2, p_x2, out, CC,0,0, FF, 1.f);

    (void)in_sizes; (void)n_in; (void)out_size;
}

// round 4
// speedup vs baseline: 3.0443x; 1.5259x over previous
#include <cuda_runtime.h>
#include <cstdint>

#define BATCH 64
#define TT 256
#define CC 512
#define NHD 8
#define HD 64
#define MROWS (BATCH*TT)      // 16384
#define FF 2048
#define ATT_SCALE 0.044194173824159216f   // 512^-0.5
#define NEGBIG (-1e9f)

// ---------------- scratch (device globals; no allocations) ----------------
__device__ float g_ln [MROWS*CC];
__device__ float g_q  [MROWS*CC];
__device__ float g_k  [MROWS*CC];
__device__ float g_v  [MROWS*CC];
__device__ float g_att[MROWS*CC];
__device__ float g_x1 [MROWS*CC];
__device__ float g_x2 [MROWS*CC];
__device__ float g_ca [MROWS*CC];                  // tf32-rounded ca
__device__ float g_sc [(size_t)BATCH*NHD*TT*TT];   // scores
__device__ float g_h  [(size_t)MROWS*FF];          // FFN hidden
__device__ float g_wt [8*CC*CC];                   // rounded attn weights
__device__ float g_wf1[FF*CC];                     // rounded Wf1
__device__ float g_wf2[CC*FF];                     // rounded Wf2

// ---------------- helpers ----------------
__device__ __forceinline__ float f2tf_f(float f){
    uint32_t r; asm("cvt.rna.tf32.f32 %0, %1;" : "=r"(r) : "f"(f));
    return __uint_as_float(r);
}
__device__ __forceinline__ void mma8(float4& d, const uint32_t* a, const uint32_t* b){
    asm volatile("mma.sync.aligned.m16n8k8.row.col.f32.tf32.tf32.f32 "
        "{%0,%1,%2,%3}, {%4,%5,%6,%7}, {%8,%9}, {%0,%1,%2,%3};"
        : "+f"(d.x), "+f"(d.y), "+f"(d.z), "+f"(d.w)
        : "r"(a[0]), "r"(a[1]), "r"(a[2]), "r"(a[3]), "r"(b[0]), "r"(b[1]));
}
#define CP16(d, s) asm volatile("cp.async.cg.shared.global [%0], [%1], 16;" :: "r"(d), "l"(s))
#define CPCOMMIT() asm volatile("cp.async.commit_group;" ::: "memory")
#define CPWAIT(n)  asm volatile("cp.async.wait_group %0;" :: "n"(n) : "memory")

__device__ __forceinline__ float warpSum(float v){
    #pragma unroll
    for (int o = 16; o; o >>= 1) v += __shfl_xor_sync(0xffffffffu, v, o);
    return v;
}
__device__ __forceinline__ float warpMax(float v){
    #pragma unroll
    for (int o = 16; o; o >>= 1) v = fmaxf(v, __shfl_xor_sync(0xffffffffu, v, o));
    return v;
}

// ---------------- tf32 rounding prepass ----------------
__global__ void round_k(const float* __restrict__ src, float* __restrict__ dst, int n4){
    int i = blockIdx.x*256 + threadIdx.x;
    if (i < n4){
        float4 v = reinterpret_cast<const float4*>(src)[i];
        v.x = f2tf_f(v.x); v.y = f2tf_f(v.y); v.z = f2tf_f(v.z); v.w = f2tf_f(v.w);
        reinterpret_cast<float4*>(dst)[i] = v;
    }
}

// ---------------- layernorm (tf32-rounded output) ----------------
__global__ void ln_kernel(const float* __restrict__ x, const float* __restrict__ g,
                          const float* __restrict__ be, float* __restrict__ y)
{
    int r = blockIdx.x;
    int t = threadIdx.x;
    const float4* xr = reinterpret_cast<const float4*>(x + (size_t)r*CC);
    float4 v = xr[t];
    float s  = v.x + v.y + v.z + v.w;
    float sq = v.x*v.x + v.y*v.y + v.z*v.z + v.w*v.w;

    __shared__ float rs[4], rq[4];
    int lane = t & 31, wid = t >> 5;
    s = warpSum(s); sq = warpSum(sq);
    if (lane == 0){ rs[wid] = s; rq[wid] = sq; }
    __syncthreads();
    if (t == 0){
        float a = rs[0]+rs[1]+rs[2]+rs[3];
        float b = rq[0]+rq[1]+rq[2]+rq[3];
        rs[0] = a * (1.0f/CC);
        rq[0] = b * (1.0f/CC);
    }
    __syncthreads();
    float mu  = rs[0];
    float var = rq[0] - mu*mu;
    float rstd = rsqrtf(var + 1e-5f);

    const float4* g4  = reinterpret_cast<const float4*>(g);
    const float4* be4 = reinterpret_cast<const float4*>(be);
    float4 gg = g4[t], bb = be4[t];
    float4 o;
    o.x = f2tf_f((v.x - mu)*rstd*gg.x + bb.x);
    o.y = f2tf_f((v.y - mu)*rstd*gg.y + bb.y);
    o.z = f2tf_f((v.z - mu)*rstd*gg.z + bb.z);
    o.w = f2tf_f((v.w - mu)*rstd*gg.w + bb.w);
    reinterpret_cast<float4*>(y + (size_t)r*CC)[t] = o;
}

// =================== tf32 mma.sync GEMM, cp.async pipeline ===================
// A[M,K] row-major, pre-rounded to tf32. TRB=false: B [K][N]; TRB=true: B [N][K].
// BM=128, BN in {128,64}. 256 threads = 8 warps (4M x 2N). BK=32.
template<int BN, bool TRB, bool BIAS, bool RELU, bool RES, bool SCALE, bool RND>
__global__ __launch_bounds__(256, 2)
void gemm_ca(const float* __restrict__ A, int lda, long long sAb, long long sAh,
             const float* __restrict__ B, int ldb, long long sBb, long long sBh,
             const float* __restrict__ bias, const float* __restrict__ res,
             float* __restrict__ C, int ldc, long long sCb, long long sCh,
             int K, float scale)
{
    constexpr int NT   = BN/16;
    constexpr int WN   = BN/2;
    constexpr int CH   = BN/4;                 // 16B chunks per B k-row (KN layout)
    constexpr int ABYTES = 128*128;            // 16 KB
    constexpr int BBYTES = TRB ? BN*128 : 32*BN*4;
    constexpr int STAGE  = ABYTES + BBYTES;

    extern __shared__ char smp[];
    const uint32_t smem_base = (uint32_t)__cvta_generic_to_shared(smp);

    const int tid  = threadIdx.x;
    const int w    = tid >> 5, lane = tid & 31;
    const int g    = lane >> 2, c = lane & 3;
    const int row0 = blockIdx.y * 128;
    const int col0 = blockIdx.x * BN;
    {
        const long long zb = blockIdx.z >> 3, zh = blockIdx.z & 7;
        A += zb*sAb + zh*sAh;
        B += zb*sBb + zh*sBh;
        C += zb*sCb + zh*sCh;
    }

    float4 acc[2][NT];
    #pragma unroll
    for (int mt = 0; mt < 2; mt++)
        #pragma unroll
        for (int nt = 0; nt < NT; nt++)
            acc[mt][nt] = make_float4(0.f, 0.f, 0.f, 0.f);

    const int nch = K >> 5;
    const int mwb = (w & 3) * 32;
    const int nwb = (w >> 2) * WN;

    #define ISSUE(ch, s) do { \
        const uint32_t sa = smem_base + (s)*STAGE; \
        const float* Ag = A + (size_t)row0*lda + (ch)*32; \
        _Pragma("unroll") \
        for (int i = 0; i < 4; i++){ \
            int t2 = tid + 256*i; int m = t2 >> 3, c2 = t2 & 7; \
            CP16(sa + m*128 + ((c2 ^ (m & 7)) << 4), Ag + (size_t)m*lda + c2*4); \
        } \
        const uint32_t sb2 = smem_base + (s)*STAGE + ABYTES; \
        if (TRB){ \
            const float* Bg = B + (size_t)col0*ldb + (ch)*32; \
            _Pragma("unroll") \
            for (int i = 0; i < BN/32; i++){ \
                int t2 = tid + 256*i; int n = t2 >> 3, c2 = t2 & 7; \
                CP16(sb2 + n*128 + ((c2 ^ (n & 7)) << 4), Bg + (size_t)n*ldb + c2*4); \
            } \
        } else { \
            const float* Bg = B + (size_t)(ch)*32*ldb + col0; \
            _Pragma("unroll") \
            for (int i = 0; i < BN/32; i++){ \
                int t2 = tid + 256*i; int k = t2 / CH, c2 = t2 % CH; \
                CP16(sb2 + k*(BN*4) + (((c2 ^ (2*(k & 7))) & (CH-1)) << 4), \
                     Bg + (size_t)k*ldb + c2*4); \
            } \
        } \
        CPCOMMIT(); \
    } while(0)

    ISSUE(0, 0);

    for (int ch = 0; ch < nch; ch++){
        const int p = ch & 1;
        if (ch + 1 < nch){
            ISSUE(ch+1, p^1);
            CPWAIT(1);
        } else {
            CPWAIT(0);
        }
        __syncthreads();

        const uint32_t* Af = reinterpret_cast<const uint32_t*>(smp + p*STAGE);
        const uint32_t* Bf = reinterpret_cast<const uint32_t*>(smp + p*STAGE + ABYTES);

        #pragma unroll
        for (int ks = 0; ks < 4; ks++){
            uint32_t af[2][4], bf[NT][2];
            const int sw0 = ((2*ks)   ^ g)*4 + c;
            const int sw1 = ((2*ks+1) ^ g)*4 + c;
            #pragma unroll
            for (int mt = 0; mt < 2; mt++){
                int m = mwb + mt*16 + g;
                af[mt][0] = Af[ m   *32 + sw0];
                af[mt][1] = Af[(m+8)*32 + sw0];
                af[mt][2] = Af[ m   *32 + sw1];
                af[mt][3] = Af[(m+8)*32 + sw1];
            }
            #pragma unroll
            for (int nt = 0; nt < NT; nt++){
                int n = nwb + nt*8 + g;
                if (TRB){
                    bf[nt][0] = Bf[n*32 + sw0];
                    bf[nt][1] = Bf[n*32 + sw1];
                } else {
                    int k1 = ks*8 + c;
                    bf[nt][0] = Bf[ k1   *BN + (((n>>2) ^ (2*c  )) & (CH-1))*4 + (n&3)];
                    bf[nt][1] = Bf[(k1+4)*BN + (((n>>2) ^ (2*c+8)) & (CH-1))*4 + (n&3)];
                }
            }
            #pragma unroll
            for (int mt = 0; mt < 2; mt++)
                #pragma unroll
                for (int nt = 0; nt < NT; nt++)
                    mma8(acc[mt][nt], af[mt], bf[nt]);
        }
        __syncthreads();
    }

    // ---- epilogue ----
    #pragma unroll
    for (int mt = 0; mt < 2; mt++){
        int r0 = row0 + mwb + mt*16 + g;
        #pragma unroll
        for (int nt = 0; nt < NT; nt++){
            int cx = col0 + nwb + nt*8 + c*2;
            float4 v = acc[mt][nt];
            if (SCALE){ v.x*=scale; v.y*=scale; v.z*=scale; v.w*=scale; }
            if (BIAS){
                float b0 = bias[cx], b1 = bias[cx+1];
                v.x += b0; v.y += b1; v.z += b0; v.w += b1;
            }
            if (RELU){
                v.x = fmaxf(v.x, 0.f); v.y = fmaxf(v.y, 0.f);
                v.z = fmaxf(v.z, 0.f); v.w = fmaxf(v.w, 0.f);
            }
            if (RES){
                float2 r1 = *reinterpret_cast<const float2*>(&res[(size_t)r0*ldc + cx]);
                float2 r2 = *reinterpret_cast<const float2*>(&res[(size_t)(r0+8)*ldc + cx]);
                v.x += r1.x; v.y += r1.y; v.z += r2.x; v.w += r2.y;
            }
            if (RND){
                v.x = f2tf_f(v.x); v.y = f2tf_f(v.y);
                v.z = f2tf_f(v.z); v.w = f2tf_f(v.w);
            }
            *reinterpret_cast<float2*>(&C[(size_t)r0*ldc + cx])     = make_float2(v.x, v.y);
            *reinterpret_cast<float2*>(&C[(size_t)(r0+8)*ldc + cx]) = make_float2(v.z, v.w);
        }
    }
    #undef ISSUE
}

// ---------------- masked softmax (reference semantics, tf32-rounded out) ----------------
__global__ __launch_bounds__(256)
void softmax_kernel(float* __restrict__ S, const int* __restrict__ mask, int causal)
{
    int bh = blockIdx.y;
    int b = bh >> 3;
    int i = blockIdx.x;
    int j = threadIdx.x;
    float* row = S + (size_t)bh*TT*TT + (size_t)i*TT;

    int valid = mask[(size_t)b*TT*TT + (size_t)i*TT + j] != 0;
    if (causal && j > i) valid = 0;
    float v = valid ? row[j] : NEGBIG;

    __shared__ float red[8];
    int lane = j & 31, wid = j >> 5;

    float m = warpMax(v);
    if (lane == 0) red[wid] = m;
    __syncthreads();
    if (wid == 0){
        float t = (lane < 8) ? red[lane] : -3.4e38f;
        t = warpMax(t);
        if (lane == 0) red[0] = t;
    }
    __syncthreads();
    m = red[0];
    __syncthreads();

    float e = expf(v - m);
    float s = warpSum(e);
    if (lane == 0) red[wid] = s;
    __syncthreads();
    if (wid == 0){
        float t = (lane < 8) ? red[lane] : 0.f;
        t = warpSum(t);
        if (lane == 0) red[0] = t;
    }
    __syncthreads();
    row[j] = f2tf_f(e / red[0]);
}

// ---------------- host orchestration ----------------
static float* symaddr(const void* sym){
    void* p = nullptr;
    cudaGetSymbolAddress(&p, sym);
    return (float*)p;
}

#define S128 (2*(128*128 + 32*128*4))   // 65536
#define S64  (2*(128*128 + 32*64*4))    // 49152

// template aliases for the 6 instantiations
#define G_PROJ  gemm_ca<128,false,false,false,false,false,true >
#define G_QK    gemm_ca<128,true ,false,false,false,true ,false>
#define G_PV    gemm_ca<64 ,false,false,false,false,false,true >
#define G_WO    gemm_ca<128,false,true ,false,true ,false,false>
#define G_FF1   gemm_ca<128,false,true ,true ,false,false,true >

extern "C" void kernel_launch(void* const* d_in, const int* in_sizes, int n_in,
                              void* d_out, int out_size)
{
    const float* x    = (const float*)d_in[0];
    const float* ca   = (const float*)d_in[1];
    const int*   x_m  = (const int*)  d_in[2];
    const int*   ca_m = (const int*)  d_in[3];
    const float* Wq_s = (const float*)d_in[4];
    const float* Wk_s = (const float*)d_in[5];
    const float* Wv_s = (const float*)d_in[6];
    const float* Wo_s = (const float*)d_in[7];
    const float* bo_s = (const float*)d_in[8];
    const float* Wq_c = (const float*)d_in[9];
    const float* Wk_c = (const float*)d_in[10];
    const float* Wv_c = (const float*)d_in[11];
    const float* Wo_c = (const float*)d_in[12];
    const float* bo_c = (const float*)d_in[13];
    const float* g1   = (const float*)d_in[14];
    const float* be1  = (const float*)d_in[15];
    const float* g2   = (const float*)d_in[16];
    const float* be2  = (const float*)d_in[17];
    const float* g3   = (const float*)d_in[18];
    const float* be3  = (const float*)d_in[19];
    const float* Wf1  = (const float*)d_in[20];
    const float* bf1  = (const float*)d_in[21];
    const float* Wf2  = (const float*)d_in[22];
    const float* bf2  = (const float*)d_in[23];
    float* out = (float*)d_out;

    float* p_ln  = symaddr(g_ln);
    float* p_q   = symaddr(g_q);
    float* p_k   = symaddr(g_k);
    float* p_v   = symaddr(g_v);
    float* p_att = symaddr(g_att);
    float* p_x1  = symaddr(g_x1);
    float* p_x2  = symaddr(g_x2);
    float* p_ca  = symaddr(g_ca);
    float* p_sc  = symaddr(g_sc);
    float* p_h   = symaddr(g_h);
    float* p_wt  = symaddr(g_wt);
    float* p_wf1 = symaddr(g_wf1);
    float* p_wf2 = symaddr(g_wf2);

    static bool attrDone = false;
    if (!attrDone){
        cudaFuncSetAttribute(G_PROJ, cudaFuncAttributeMaxDynamicSharedMemorySize, S128);
        cudaFuncSetAttribute(G_QK,   cudaFuncAttributeMaxDynamicSharedMemorySize, S128);
        cudaFuncSetAttribute(G_PV,   cudaFuncAttributeMaxDynamicSharedMemorySize, S64);
        cudaFuncSetAttribute(G_WO,   cudaFuncAttributeMaxDynamicSharedMemorySize, S128);
        cudaFuncSetAttribute(G_FF1,  cudaFuncAttributeMaxDynamicSharedMemorySize, S128);
        attrDone = true;
    }

    // ---- tf32 rounding prepass: weights + ca ----
    const float* Ws[8] = {Wq_s, Wk_s, Wv_s, Wo_s, Wq_c, Wk_c, Wv_c, Wo_c};
    for (int i = 0; i < 8; i++)
        round_k<<<(CC*CC/4+255)/256,256>>>(Ws[i], p_wt + (size_t)i*CC*CC, CC*CC/4);
    round_k<<<(CC*FF/4+255)/256,256>>>(Wf1, p_wf1, CC*FF/4);
    round_k<<<(CC*FF/4+255)/256,256>>>(Wf2, p_wf2, CC*FF/4);
    round_k<<<(MROWS*CC/4+255)/256,256>>>(ca, p_ca, MROWS*CC/4);

    dim3 gCC(CC/128, MROWS/128, 1);      // (4,128)
    dim3 gFF(FF/128, MROWS/128, 1);      // (16,128)
    dim3 gQK(TT/128, TT/128, BATCH*NHD); // (2,2,512)
    dim3 gPV(1, TT/128, BATCH*NHD);      // (1,2,512)
    dim3 smG(TT, BATCH*NHD);

    const long long sTok = (long long)TT*CC;
    const long long sScB = (long long)NHD*TT*TT;
    const long long sScH = (long long)TT*TT;

    // ===== self-attention =====
    ln_kernel<<<MROWS,128>>>(x, g1, be1, p_ln);
    G_PROJ<<<gCC,256,S128>>>(p_ln, CC,0,0, p_wt+0*CC*CC, CC,0,0, nullptr,nullptr, p_q, CC,0,0, CC, 1.f);
    G_PROJ<<<gCC,256,S128>>>(p_ln, CC,0,0, p_wt+1*CC*CC, CC,0,0, nullptr,nullptr, p_k, CC,0,0, CC, 1.f);
    G_PROJ<<<gCC,256,S128>>>(p_ln, CC,0,0, p_wt+2*CC*CC, CC,0,0, nullptr,nullptr, p_v, CC,0,0, CC, 1.f);
    G_QK<<<gQK,256,S128>>>(p_q, CC, sTok, HD, p_k, CC, sTok, HD,
                           nullptr, nullptr, p_sc, TT, sScB, sScH, HD, ATT_SCALE);
    softmax_kernel<<<smG,256>>>(p_sc, x_m, 1);
    G_PV<<<gPV,256,S64>>>(p_sc, TT, sScB, sScH, p_v, CC, sTok, HD,
                          nullptr, nullptr, p_att, CC, sTok, HD, TT, 1.f);
    G_WO<<<gCC,256,S128>>>(p_att, CC,0,0, p_wt+3*CC*CC, CC,0,0, bo_s, x, p_x1, CC,0,0, CC, 1.f);

    // ===== cross-attention =====
    ln_kernel<<<MROWS,128>>>(p_x1, g2, be2, p_ln);
    G_PROJ<<<gCC,256,S128>>>(p_ln, CC,0,0, p_wt+4*CC*CC, CC,0,0, nullptr,nullptr, p_q, CC,0,0, CC, 1.f);
    G_PROJ<<<gCC,256,S128>>>(p_ca, CC,0,0, p_wt+5*CC*CC, CC,0,0, nullptr,nullptr, p_k, CC,0,0, CC, 1.f);
    G_PROJ<<<gCC,256,S128>>>(p_ca, CC,0,0, p_wt+6*CC*CC, CC,0,0, nullptr,nullptr, p_v, CC,0,0, CC, 1.f);
    G_QK<<<gQK,256,S128>>>(p_q, CC, sTok, HD, p_k, CC, sTok, HD,
                           nullptr, nullptr, p_sc, TT, sScB, sScH, HD, ATT_SCALE);
    softmax_kernel<<<smG,256>>>(p_sc, ca_m, 0);
    G_PV<<<gPV,256,S64>>>(p_sc, TT, sScB, sScH, p_v, CC, sTok, HD,
                          nullptr, nullptr, p_att, CC, sTok, HD, TT, 1.f);
    G_WO<<<gCC,256,S128>>>(p_att, CC,0,0, p_wt+7*CC*CC, CC,0,0, bo_c, p_x1, p_x2, CC,0,0, CC, 1.f);

    // ===== feed-forward =====
    ln_kernel<<<MROWS,128>>>(p_x2, g3, be3, p_ln);
    G_FF1<<<gFF,256,S128>>>(p_ln, CC,0,0, p_wf1, FF,0,0, bf1, nullptr, p_h, FF,0,0, CC, 1.f);
    G_WO <<<gCC,256,S128>>>(p_h, FF,0,0, p_wf2, CC,0,0, bf2, p_x2, out, CC,0,0, FF, 1.f);

    (void)in_sizes; (void)n_in; (void)out_size;
}

// round 5
// speedup vs baseline: 3.5278x; 1.1588x over previous
#include <cuda_runtime.h>
#include <cstdint>

#define BATCH 64
#define TT 256
#define CC 512
#define NHD 8
#define HD 64
#define MROWS (BATCH*TT)      // 16384
#define FF 2048
#define QKV 1536
#define ATT_SCALE 0.044194173824159216f   // 512^-0.5
#define NEGBIG (-1e9f)

// ---------------- scratch (device globals; no allocations) ----------------
__device__ float g_ln  [MROWS*CC];
__device__ float g_qkv [(size_t)MROWS*QKV];         // fused q|k|v
__device__ float g_att [MROWS*CC];
__device__ float g_x1  [MROWS*CC];
__device__ float g_x2  [MROWS*CC];
__device__ float g_sc  [(size_t)BATCH*NHD*TT*TT];   // scores
__device__ float g_h   [(size_t)MROWS*FF];          // FFN hidden
__device__ float g_wqkvs[QKV*CC];                   // [1536][512] = Wq_s^T|Wk_s^T|Wv_s^T
__device__ float g_wqkvc[QKV*CC];
__device__ float g_wos [CC*CC];                     // Wo_s^T
__device__ float g_woc [CC*CC];
__device__ float g_wf1t[FF*CC];                     // Wf1^T [2048][512]
__device__ float g_wf2t[CC*FF];                     // Wf2^T [512][2048]

// ---------------- helpers ----------------
__device__ __forceinline__ float f2tf_f(float f){
    uint32_t r; asm("cvt.rna.tf32.f32 %0, %1;" : "=r"(r) : "f"(f));
    return __uint_as_float(r);
}
__device__ __forceinline__ void mma8(float4& d, const uint32_t* a, const uint32_t* b){
    asm volatile("mma.sync.aligned.m16n8k8.row.col.f32.tf32.tf32.f32 "
        "{%0,%1,%2,%3}, {%4,%5,%6,%7}, {%8,%9}, {%0,%1,%2,%3};"
        : "+f"(d.x), "+f"(d.y), "+f"(d.z), "+f"(d.w)
        : "r"(a[0]), "r"(a[1]), "r"(a[2]), "r"(a[3]), "r"(b[0]), "r"(b[1]));
}
__device__ __forceinline__ void ldsm4(uint32_t* r, uint32_t addr){
    asm volatile("ldmatrix.sync.aligned.m8n8.x4.shared.b16 {%0,%1,%2,%3}, [%4];"
        : "=r"(r[0]), "=r"(r[1]), "=r"(r[2]), "=r"(r[3]) : "r"(addr));
}
#define CP16(d, s) asm volatile("cp.async.cg.shared.global [%0], [%1], 16;" :: "r"(d), "l"(s))
#define CPCOMMIT() asm volatile("cp.async.commit_group;" ::: "memory")
#define CPWAIT(n)  asm volatile("cp.async.wait_group %0;" :: "n"(n) : "memory")

__device__ __forceinline__ float warpSum(float v){
    #pragma unroll
    for (int o = 16; o; o >>= 1) v += __shfl_xor_sync(0xffffffffu, v, o);
    return v;
}
__device__ __forceinline__ float warpMax(float v){
    #pragma unroll
    for (int o = 16; o; o >>= 1) v = fmaxf(v, __shfl_xor_sync(0xffffffffu, v, o));
    return v;
}

// ---------------- weight transpose + tf32 round prepass ----------------
__global__ void wtrans8(const float* s0, const float* s1, const float* s2, const float* s3,
                        const float* s4, const float* s5, const float* s6, const float* s7,
                        float* qkvs, float* wos, float* qkvc, float* woc)
{
    int z = blockIdx.z;
    const float* src = (z==0)?s0:(z==1)?s1:(z==2)?s2:(z==3)?s3:(z==4)?s4:(z==5)?s5:(z==6)?s6:s7;
    float* dst = (z<3) ? qkvs + (size_t)z*CC*CC
               : (z==3) ? wos
               : (z<7) ? qkvc + (size_t)(z-4)*CC*CC
               : woc;
    __shared__ float t[32][33];
    int bx = blockIdx.x*32, by = blockIdx.y*32;
    int x = threadIdx.x, y = threadIdx.y;
    #pragma unroll
    for (int i = 0; i < 32; i += 8)
        t[y+i][x] = src[(size_t)(by + y + i)*CC + bx + x];
    __syncthreads();
    #pragma unroll
    for (int i = 0; i < 32; i += 8)
        dst[(size_t)(bx + y + i)*CC + by + x] = f2tf_f(t[x][y+i]);
}

__global__ void ttrans(const float* __restrict__ src, float* __restrict__ dst, int R, int C)
{
    __shared__ float t[32][33];
    int bx = blockIdx.x*32, by = blockIdx.y*32;
    int x = threadIdx.x, y = threadIdx.y;
    #pragma unroll
    for (int i = 0; i < 32; i += 8)
        t[y+i][x] = src[(size_t)(by + y + i)*C + bx + x];
    __syncthreads();
    #pragma unroll
    for (int i = 0; i < 32; i += 8)
        dst[(size_t)(bx + y + i)*R + by + x] = f2tf_f(t[x][y+i]);
}

// ---------------- layernorm (tf32-rounded output) ----------------
__global__ void ln_kernel(const float* __restrict__ x, const float* __restrict__ g,
                          const float* __restrict__ be, float* __restrict__ y)
{
    int r = blockIdx.x;
    int t = threadIdx.x;
    const float4* xr = reinterpret_cast<const float4*>(x + (size_t)r*CC);
    float4 v = xr[t];
    float s  = v.x + v.y + v.z + v.w;
    float sq = v.x*v.x + v.y*v.y + v.z*v.z + v.w*v.w;

    __shared__ float rs[4], rq[4];
    int lane = t & 31, wid = t >> 5;
    s = warpSum(s); sq = warpSum(sq);
    if (lane == 0){ rs[wid] = s; rq[wid] = sq; }
    __syncthreads();
    if (t == 0){
        float a = rs[0]+rs[1]+rs[2]+rs[3];
        float b = rq[0]+rq[1]+rq[2]+rq[3];
        rs[0] = a * (1.0f/CC);
        rq[0] = b * (1.0f/CC);
    }
    __syncthreads();
    float mu  = rs[0];
    float var = rq[0] - mu*mu;
    float rstd = rsqrtf(var + 1e-5f);

    const float4* g4  = reinterpret_cast<const float4*>(g);
    const float4* be4 = reinterpret_cast<const float4*>(be);
    float4 gg = g4[t], bb = be4[t];
    float4 o;
    o.x = f2tf_f((v.x - mu)*rstd*gg.x + bb.x);
    o.y = f2tf_f((v.y - mu)*rstd*gg.y + bb.y);
    o.z = f2tf_f((v.z - mu)*rstd*gg.z + bb.z);
    o.w = f2tf_f((v.w - mu)*rstd*gg.w + bb.w);
    reinterpret_cast<float4*>(y + (size_t)r*CC)[t] = o;
}

// =================== tf32 mma.sync GEMM, cp.async 3-stage + ldmatrix ===================
// A[M,K] row-major. TRB=true: B global [N][K] (ldmatrix path); false: B [K][N] (scalar).
// BM=128, BN in {128,64}. 256 threads = 8 warps (4M x 2N). BK=32, 3 stages.
template<int BN, bool TRB, bool BIAS, bool RELU, bool RES, bool SCALE, bool RND>
__global__ __launch_bounds__(256, 2)
void gemm_ca(const float* __restrict__ A, int lda, long long sAb, long long sAh,
             const float* __restrict__ B, int ldb, long long sBb, long long sBh,
             const float* __restrict__ bias, const float* __restrict__ res,
             float* __restrict__ C, int ldc, long long sCb, long long sCh,
             int K, float scale)
{
    constexpr int NT   = BN/16;
    constexpr int WN   = BN/2;
    constexpr int CH   = BN/4;                 // 16B chunks per B k-row (KN layout)
    constexpr int ABYTES = 128*128;            // 16 KB
    constexpr int BBYTES = TRB ? BN*128 : 32*BN*4;
    constexpr int STAGE  = ABYTES + BBYTES;

    extern __shared__ char smp[];
    const uint32_t smem_base = (uint32_t)__cvta_generic_to_shared(smp);

    const int tid  = threadIdx.x;
    const int w    = tid >> 5, lane = tid & 31;
    const int g    = lane >> 2, c = lane & 3;
    const int row0 = blockIdx.y * 128;
    const int col0 = blockIdx.x * BN;
    {
        const long long zb = blockIdx.z >> 3, zh = blockIdx.z & 7;
        A += zb*sAb + zh*sAh;
        B += zb*sBb + zh*sBh;
        C += zb*sCb + zh*sCh;
    }

    float4 acc[2][NT];
    #pragma unroll
    for (int mt = 0; mt < 2; mt++)
        #pragma unroll
        for (int nt = 0; nt < NT; nt++)
            acc[mt][nt] = make_float4(0.f, 0.f, 0.f, 0.f);

    const int nch = K >> 5;
    const int mwb = (w & 3) * 32;
    const int nwb = (w >> 2) * WN;

    // ldmatrix per-thread address components
    uint32_t aOff[2], aR7[2];
    const uint32_t aHi = lane >> 4;
    #pragma unroll
    for (int mt = 0; mt < 2; mt++){
        int rA = mwb + mt*16 + (lane & 15);
        aOff[mt] = (uint32_t)rA * 128u;
        aR7[mt]  = (uint32_t)(rA & 7);
    }
    uint32_t bOff[NT/2], bR7[NT/2];
    const uint32_t bHi = (lane >> 3) & 1;
    #pragma unroll
    for (int ntp = 0; ntp < NT/2; ntp++){
        int rB = nwb + ntp*16 + (lane & 7) + ((lane >> 4) << 3);
        bOff[ntp] = (uint32_t)rB * 128u;
        bR7[ntp]  = (uint32_t)(rB & 7);
    }

    #define ISSUE(ch, s) do { \
        const uint32_t sa = smem_base + (s)*STAGE; \
        const float* Ag = A + (size_t)row0*lda + (ch)*32; \
        _Pragma("unroll") \
        for (int i = 0; i < 4; i++){ \
            int t2 = tid + 256*i; int m = t2 >> 3, c2 = t2 & 7; \
            CP16(sa + m*128 + ((c2 ^ (m & 7)) << 4), Ag + (size_t)m*lda + c2*4); \
        } \
        const uint32_t sb2 = smem_base + (s)*STAGE + ABYTES; \
        if (TRB){ \
            const float* Bg = B + (size_t)col0*ldb + (ch)*32; \
            _Pragma("unroll") \
            for (int i = 0; i < BN/32; i++){ \
                int t2 = tid + 256*i; int n = t2 >> 3, c2 = t2 & 7; \
                CP16(sb2 + n*128 + ((c2 ^ (n & 7)) << 4), Bg + (size_t)n*ldb + c2*4); \
            } \
        } else { \
            const float* Bg = B + (size_t)(ch)*32*ldb + col0; \
            _Pragma("unroll") \
            for (int i = 0; i < BN/32; i++){ \
                int t2 = tid + 256*i; int k = t2 / CH, c2 = t2 % CH; \
                CP16(sb2 + k*(BN*4) + (((c2 ^ (2*(k & 7))) & (CH-1)) << 4), \
                     Bg + (size_t)k*ldb + c2*4); \
            } \
        } \
        CPCOMMIT(); \
    } while(0)

    ISSUE(0, 0);
    ISSUE(1, 1);

    for (int ch = 0; ch < nch; ch++){
        const int p = ch % 3;
        if (ch + 2 < nch) ISSUE(ch+2, (ch+2)%3); else CPCOMMIT();
        CPWAIT(2);
        __syncthreads();

        const uint32_t sA = smem_base + p*STAGE;
        const uint32_t sB = sA + ABYTES;
        const uint32_t* Bf = reinterpret_cast<const uint32_t*>(smp + p*STAGE + ABYTES);

        #pragma unroll
        for (int ks = 0; ks < 4; ks++){
            uint32_t af[2][4], bfr[NT][2];
            #pragma unroll
            for (int mt = 0; mt < 2; mt++)
                ldsm4(af[mt], sA + aOff[mt] + ((((uint32_t)(2*ks) + aHi) ^ aR7[mt]) << 4));
            if (TRB){
                #pragma unroll
                for (int ntp = 0; ntp < NT/2; ntp++){
                    uint32_t r[4];
                    ldsm4(r, sB + bOff[ntp] + ((((uint32_t)(2*ks) + bHi) ^ bR7[ntp]) << 4));
                    bfr[2*ntp  ][0] = r[0]; bfr[2*ntp  ][1] = r[1];
                    bfr[2*ntp+1][0] = r[2]; bfr[2*ntp+1][1] = r[3];
                }
            } else {
                #pragma unroll
                for (int nt = 0; nt < NT; nt++){
                    int n = nwb + nt*8 + g;
                    int k1 = ks*8 + c;
                    bfr[nt][0] = Bf[ k1   *BN + (((n>>2) ^ (2*c  )) & (CH-1))*4 + (n&3)];
                    bfr[nt][1] = Bf[(k1+4)*BN + (((n>>2) ^ (2*c+8)) & (CH-1))*4 + (n&3)];
                }
            }
            #pragma unroll
            for (int mt = 0; mt < 2; mt++)
                #pragma unroll
                for (int nt = 0; nt < NT; nt++)
                    mma8(acc[mt][nt], af[mt], bfr[nt]);
        }
        __syncthreads();
    }

    // ---- epilogue ----
    #pragma unroll
    for (int mt = 0; mt < 2; mt++){
        int r0 = row0 + mwb + mt*16 + g;
        #pragma unroll
        for (int nt = 0; nt < NT; nt++){
            int cx = col0 + nwb + nt*8 + c*2;
            float4 v = acc[mt][nt];
            if (SCALE){ v.x*=scale; v.y*=scale; v.z*=scale; v.w*=scale; }
            if (BIAS){
                float b0 = bias[cx], b1 = bias[cx+1];
                v.x += b0; v.y += b1; v.z += b0; v.w += b1;
            }
            if (RELU){
                v.x = fmaxf(v.x, 0.f); v.y = fmaxf(v.y, 0.f);
                v.z = fmaxf(v.z, 0.f); v.w = fmaxf(v.w, 0.f);
            }
            if (RES){
                float2 r1 = *reinterpret_cast<const float2*>(&res[(size_t)r0*ldc + cx]);
                float2 r2 = *reinterpret_cast<const float2*>(&res[(size_t)(r0+8)*ldc + cx]);
                v.x += r1.x; v.y += r1.y; v.z += r2.x; v.w += r2.y;
            }
            if (RND){
                v.x = f2tf_f(v.x); v.y = f2tf_f(v.y);
                v.z = f2tf_f(v.z); v.w = f2tf_f(v.w);
            }
            *reinterpret_cast<float2*>(&C[(size_t)r0*ldc + cx])     = make_float2(v.x, v.y);
            *reinterpret_cast<float2*>(&C[(size_t)(r0+8)*ldc + cx]) = make_float2(v.z, v.w);
        }
    }
    #undef ISSUE
}

// ---------------- masked softmax (reference semantics, tf32-rounded out) ----------------
__global__ __launch_bounds__(256)
void softmax_kernel(float* __restrict__ S, const int* __restrict__ mask, int causal)
{
    int bh = blockIdx.y;
    int b = bh >> 3;
    int i = blockIdx.x;
    int j = threadIdx.x;
    float* row = S + (size_t)bh*TT*TT + (size_t)i*TT;

    int valid = mask[(size_t)b*TT*TT + (size_t)i*TT + j] != 0;
    if (causal && j > i) valid = 0;
    float v = valid ? row[j] : NEGBIG;

    __shared__ float red[8];
    int lane = j & 31, wid = j >> 5;

    float m = warpMax(v);
    if (lane == 0) red[wid] = m;
    __syncthreads();
    if (wid == 0){
        float t = (lane < 8) ? red[lane] : -3.4e38f;
        t = warpMax(t);
        if (lane == 0) red[0] = t;
    }
    __syncthreads();
    m = red[0];
    __syncthreads();

    float e = expf(v - m);
    float s = warpSum(e);
    if (lane == 0) red[wid] = s;
    __syncthreads();
    if (wid == 0){
        float t = (lane < 8) ? red[lane] : 0.f;
        t = warpSum(t);
        if (lane == 0) red[0] = t;
    }
    __syncthreads();
    row[j] = f2tf_f(e / red[0]);
}

// ---------------- host orchestration ----------------
static float* symaddr(const void* sym){
    void* p = nullptr;
    cudaGetSymbolAddress(&p, sym);
    return (float*)p;
}

#define S3_128 (3*(128*128 + 128*128))   // 98304: A 16K + B(TRB128) 16K, 3 stages
#define S3_64K (3*(128*128 + 32*64*4))   // 73728: A 16K + B(KN64) 8K, 3 stages

#define G_PROJ gemm_ca<128,true ,false,false,false,false,true >
#define G_QK   gemm_ca<128,true ,false,false,false,true ,false>
#define G_PV   gemm_ca<64 ,false,false,false,false,false,true >
#define G_WO   gemm_ca<128,true ,true ,false,true ,false,false>
#define G_FF1  gemm_ca<128,true ,true ,true ,false,false,true >

extern "C" void kernel_launch(void* const* d_in, const int* in_sizes, int n_in,
                              void* d_out, int out_size)
{
    const float* x    = (const float*)d_in[0];
    const float* ca   = (const float*)d_in[1];
    const int*   x_m  = (const int*)  d_in[2];
    const int*   ca_m = (const int*)  d_in[3];
    const float* Wq_s = (const float*)d_in[4];
    const float* Wk_s = (const float*)d_in[5];
    const float* Wv_s = (const float*)d_in[6];
    const float* Wo_s = (const float*)d_in[7];
    const float* bo_s = (const float*)d_in[8];
    const float* Wq_c = (const float*)d_in[9];
    const float* Wk_c = (const float*)d_in[10];
    const float* Wv_c = (const float*)d_in[11];
    const float* Wo_c = (const float*)d_in[12];
    const float* bo_c = (const float*)d_in[13];
    const float* g1   = (const float*)d_in[14];
    const float* be1  = (const float*)d_in[15];
    const float* g2   = (const float*)d_in[16];
    const float* be2  = (const float*)d_in[17];
    const float* g3   = (const float*)d_in[18];
    const float* be3  = (const float*)d_in[19];
    const float* Wf1  = (const float*)d_in[20];
    const float* bf1  = (const float*)d_in[21];
    const float* Wf2  = (const float*)d_in[22];
    const float* bf2  = (const float*)d_in[23];
    float* out = (float*)d_out;

    float* p_ln   = symaddr(g_ln);
    float* p_qkv  = symaddr(g_qkv);
    float* p_att  = symaddr(g_att);
    float* p_x1   = symaddr(g_x1);
    float* p_x2   = symaddr(g_x2);
    float* p_sc   = symaddr(g_sc);
    float* p_h    = symaddr(g_h);
    float* p_wqs  = symaddr(g_wqkvs);
    float* p_wqc  = symaddr(g_wqkvc);
    float* p_wos  = symaddr(g_wos);
    float* p_woc  = symaddr(g_woc);
    float* p_wf1  = symaddr(g_wf1t);
    float* p_wf2  = symaddr(g_wf2t);

    static bool attrDone = false;
    if (!attrDone){
        cudaFuncSetAttribute(G_PROJ, cudaFuncAttributeMaxDynamicSharedMemorySize, S3_128);
        cudaFuncSetAttribute(G_QK,   cudaFuncAttributeMaxDynamicSharedMemorySize, S3_128);
        cudaFuncSetAttribute(G_PV,   cudaFuncAttributeMaxDynamicSharedMemorySize, S3_64K);
        cudaFuncSetAttribute(G_WO,   cudaFuncAttributeMaxDynamicSharedMemorySize, S3_128);
        cudaFuncSetAttribute(G_FF1,  cudaFuncAttributeMaxDynamicSharedMemorySize, S3_128);
        attrDone = true;
    }

    // ---- prepass: transpose + tf32-round all weights ----
    dim3 tb(32, 8);
    wtrans8<<<dim3(16,16,8), tb>>>(Wq_s, Wk_s, Wv_s, Wo_s, Wq_c, Wk_c, Wv_c, Wo_c,
                                   p_wqs, p_wos, p_wqc, p_woc);
    ttrans<<<dim3(FF/32, CC/32), tb>>>(Wf1, p_wf1, CC, FF);   // -> [2048][512]
    ttrans<<<dim3(CC/32, FF/32), tb>>>(Wf2, p_wf2, FF, CC);   // -> [512][2048]

    dim3 gQKV(QKV/128, MROWS/128, 1);    // (12,128)
    dim3 gQc (CC/128,  MROWS/128, 1);    // (4,128)
    dim3 gKVc(1024/128,MROWS/128, 1);    // (8,128)
    dim3 gCC (CC/128,  MROWS/128, 1);    // (4,128)
    dim3 gFF (FF/128,  MROWS/128, 1);    // (16,128)
    dim3 gQK (TT/128, TT/128, BATCH*NHD);
    dim3 gPV (1, TT/128, BATCH*NHD);
    dim3 smG (TT, BATCH*NHD);

    const long long sTokQ = (long long)TT*QKV;   // qkv buffer per-batch row stride
    const long long sTokC = (long long)TT*CC;
    const long long sScB  = (long long)NHD*TT*TT;
    const long long sScH  = (long long)TT*TT;

    // ===== self-attention =====
    ln_kernel<<<MROWS,128>>>(x, g1, be1, p_ln);
    G_PROJ<<<gQKV,256,S3_128>>>(p_ln, CC,0,0, p_wqs, CC,0,0, nullptr,nullptr, p_qkv, QKV,0,0, CC, 1.f);
    G_QK<<<gQK,256,S3_128>>>(p_qkv, QKV, sTokQ, HD, p_qkv + CC, QKV, sTokQ, HD,
                             nullptr, nullptr, p_sc, TT, sScB, sScH, HD, ATT_SCALE);
    softmax_kernel<<<smG,256>>>(p_sc, x_m, 1);
    G_PV<<<gPV,256,S3_64K>>>(p_sc, TT, sScB, sScH, p_qkv + 1024, QKV, sTokQ, HD,
                             nullptr, nullptr, p_att, CC, sTokC, HD, TT, 1.f);
    G_WO<<<gCC,256,S3_128>>>(p_att, CC,0,0, p_wos, CC,0,0, bo_s, x, p_x1, CC,0,0, CC, 1.f);

    // ===== cross-attention =====
    ln_kernel<<<MROWS,128>>>(p_x1, g2, be2, p_ln);
    G_PROJ<<<gQc,256,S3_128>>>(p_ln, CC,0,0, p_wqc, CC,0,0, nullptr,nullptr, p_qkv, QKV,0,0, CC, 1.f);
    G_PROJ<<<gKVc,256,S3_128>>>(ca, CC,0,0, p_wqc + (size_t)CC*CC, CC,0,0, nullptr,nullptr,
                                p_qkv + CC, QKV,0,0, CC, 1.f);
    G_QK<<<gQK,256,S3_128>>>(p_qkv, QKV, sTokQ, HD, p_qkv + CC, QKV, sTokQ, HD,
                             nullptr, nullptr, p_sc, TT, sScB, sScH, HD, ATT_SCALE);
    softmax_kernel<<<smG,256>>>(p_sc, ca_m, 0);
    G_PV<<<gPV,256,S3_64K>>>(p_sc, TT, sScB, sScH, p_qkv + 1024, QKV, sTokQ, HD,
                             nullptr, nullptr, p_att, CC, sTokC, HD, TT, 1.f);
    G_WO<<<gCC,256,S3_128>>>(p_att, CC,0,0, p_woc, CC,0,0, bo_c, p_x1, p_x2, CC,0,0, CC, 1.f);

    // ===== feed-forward =====
    ln_kernel<<<MROWS,128>>>(p_x2, g3, be3, p_ln);
    G_FF1<<<gFF,256,S3_128>>>(p_ln, CC,0,0, p_wf1, CC,0,0, bf1, nullptr, p_h, FF,0,0, CC, 1.f);
    G_WO <<<gCC,256,S3_128>>>(p_h, FF,0,0, p_wf2, FF,0,0, bf2, p_x2, out, CC,0,0, FF, 1.f);

    (void)in_sizes; (void)n_in; (void)out_size;
}

// round 6
// speedup vs baseline: 4.3518x; 1.2335x over previous
#include <cuda_runtime.h>
#include <cstdint>

#define BATCH 64
#define TT 256
#define CC 512
#define NHD 8
#define HD 64
#define MROWS (BATCH*TT)      // 16384
#define FF 2048
#define QKV 1536
#define ATT_SCALE 0.044194173824159216f   // 512^-0.5
#define NEGBIG (-1e9f)

// ---------------- scratch (device globals; no allocations) ----------------
__device__ float g_ln  [MROWS*CC];
__device__ float g_qkv [(size_t)MROWS*QKV];         // fused q|k|v
__device__ float g_att [MROWS*CC];
__device__ float g_x1  [MROWS*CC];
__device__ float g_x2  [MROWS*CC];
__device__ float g_sc  [(size_t)BATCH*NHD*TT*TT];   // normalized P
__device__ float g_h   [(size_t)MROWS*FF];          // FFN hidden
__device__ float g_wqkvs[QKV*CC];                   // [1536][512]
__device__ float g_wqkvc[QKV*CC];
__device__ float g_wos [CC*CC];
__device__ float g_woc [CC*CC];
__device__ float g_wf1t[FF*CC];
__device__ float g_wf2t[CC*FF];

// ---------------- helpers ----------------
__device__ __forceinline__ float f2tf_f(float f){
    uint32_t r; asm("cvt.rna.tf32.f32 %0, %1;" : "=r"(r) : "f"(f));
    return __uint_as_float(r);
}
__device__ __forceinline__ void mma8(float4& d, const uint32_t* a, const uint32_t* b){
    asm volatile("mma.sync.aligned.m16n8k8.row.col.f32.tf32.tf32.f32 "
        "{%0,%1,%2,%3}, {%4,%5,%6,%7}, {%8,%9}, {%0,%1,%2,%3};"
        : "+f"(d.x), "+f"(d.y), "+f"(d.z), "+f"(d.w)
        : "r"(a[0]), "r"(a[1]), "r"(a[2]), "r"(a[3]), "r"(b[0]), "r"(b[1]));
}
__device__ __forceinline__ void ldsm4(uint32_t* r, uint32_t addr){
    asm volatile("ldmatrix.sync.aligned.m8n8.x4.shared.b16 {%0,%1,%2,%3}, [%4];"
        : "=r"(r[0]), "=r"(r[1]), "=r"(r[2]), "=r"(r[3]) : "r"(addr));
}
#define CP16(d, s) asm volatile("cp.async.cg.shared.global [%0], [%1], 16;" :: "r"(d), "l"(s))
#define CPCOMMIT() asm volatile("cp.async.commit_group;" ::: "memory")
#define CPWAIT(n)  asm volatile("cp.async.wait_group %0;" :: "n"(n) : "memory")

__device__ __forceinline__ float warpSum(float v){
    #pragma unroll
    for (int o = 16; o; o >>= 1) v += __shfl_xor_sync(0xffffffffu, v, o);
    return v;
}
__device__ __forceinline__ float warpMax(float v){
    #pragma unroll
    for (int o = 16; o; o >>= 1) v = fmaxf(v, __shfl_xor_sync(0xffffffffu, v, o));
    return v;
}

// ---------------- weight transpose + tf32 round prepass ----------------
__global__ void wtrans8(const float* s0, const float* s1, const float* s2, const float* s3,
                        const float* s4, const float* s5, const float* s6, const float* s7,
                        float* qkvs, float* wos, float* qkvc, float* woc)
{
    int z = blockIdx.z;
    const float* src = (z==0)?s0:(z==1)?s1:(z==2)?s2:(z==3)?s3:(z==4)?s4:(z==5)?s5:(z==6)?s6:s7;
    float* dst = (z<3) ? qkvs + (size_t)z*CC*CC
               : (z==3) ? wos
               : (z<7) ? qkvc + (size_t)(z-4)*CC*CC
               : woc;
    __shared__ float t[32][33];
    int bx = blockIdx.x*32, by = blockIdx.y*32;
    int x = threadIdx.x, y = threadIdx.y;
    #pragma unroll
    for (int i = 0; i < 32; i += 8)
        t[y+i][x] = src[(size_t)(by + y + i)*CC + bx + x];
    __syncthreads();
    #pragma unroll
    for (int i = 0; i < 32; i += 8)
        dst[(size_t)(bx + y + i)*CC + by + x] = f2tf_f(t[x][y+i]);
}

__global__ void ttrans(const float* __restrict__ src, float* __restrict__ dst, int R, int C)
{
    __shared__ float t[32][33];
    int bx = blockIdx.x*32, by = blockIdx.y*32;
    int x = threadIdx.x, y = threadIdx.y;
    #pragma unroll
    for (int i = 0; i < 32; i += 8)
        t[y+i][x] = src[(size_t)(by + y + i)*C + bx + x];
    __syncthreads();
    #pragma unroll
    for (int i = 0; i < 32; i += 8)
        dst[(size_t)(bx + y + i)*R + by + x] = f2tf_f(t[x][y+i]);
}

// ---------------- layernorm (tf32-rounded output) ----------------
__global__ void ln_kernel(const float* __restrict__ x, const float* __restrict__ g,
                          const float* __restrict__ be, float* __restrict__ y)
{
    int r = blockIdx.x;
    int t = threadIdx.x;
    const float4* xr = reinterpret_cast<const float4*>(x + (size_t)r*CC);
    float4 v = xr[t];
    float s  = v.x + v.y + v.z + v.w;
    float sq = v.x*v.x + v.y*v.y + v.z*v.z + v.w*v.w;

    __shared__ float rs[4], rq[4];
    int lane = t & 31, wid = t >> 5;
    s = warpSum(s); sq = warpSum(sq);
    if (lane == 0){ rs[wid] = s; rq[wid] = sq; }
    __syncthreads();
    if (t == 0){
        float a = rs[0]+rs[1]+rs[2]+rs[3];
        float b = rq[0]+rq[1]+rq[2]+rq[3];
        rs[0] = a * (1.0f/CC);
        rq[0] = b * (1.0f/CC);
    }
    __syncthreads();
    float mu  = rs[0];
    float var = rq[0] - mu*mu;
    float rstd = rsqrtf(var + 1e-5f);

    const float4* g4  = reinterpret_cast<const float4*>(g);
    const float4* be4 = reinterpret_cast<const float4*>(be);
    float4 gg = g4[t], bb = be4[t];
    float4 o;
    o.x = f2tf_f((v.x - mu)*rstd*gg.x + bb.x);
    o.y = f2tf_f((v.y - mu)*rstd*gg.y + bb.y);
    o.z = f2tf_f((v.z - mu)*rstd*gg.z + bb.z);
    o.w = f2tf_f((v.w - mu)*rstd*gg.w + bb.w);
    reinterpret_cast<float4*>(y + (size_t)r*CC)[t] = o;
}

// =================== tf32 mma.sync GEMM, cp.async 3-stage + ldmatrix ===================
template<int BN, bool TRB, bool BIAS, bool RELU, bool RES, bool SCALE, bool RND>
__global__ __launch_bounds__(256, 2)
void gemm_ca(const float* __restrict__ A, int lda, long long sAb, long long sAh,
             const float* __restrict__ B, int ldb, long long sBb, long long sBh,
             const float* __restrict__ bias, const float* __restrict__ res,
             float* __restrict__ C, int ldc, long long sCb, long long sCh,
             int K, float scale)
{
    constexpr int NT   = BN/16;
    constexpr int WN   = BN/2;
    constexpr int CH   = BN/4;
    constexpr int ABYTES = 128*128;
    constexpr int BBYTES = TRB ? BN*128 : 32*BN*4;
    constexpr int STAGE  = ABYTES + BBYTES;

    extern __shared__ char smp[];
    const uint32_t smem_base = (uint32_t)__cvta_generic_to_shared(smp);

    const int tid  = threadIdx.x;
    const int w    = tid >> 5, lane = tid & 31;
    const int g    = lane >> 2, c = lane & 3;
    const int row0 = blockIdx.y * 128;
    const int col0 = blockIdx.x * BN;
    {
        const long long zb = blockIdx.z >> 3, zh = blockIdx.z & 7;
        A += zb*sAb + zh*sAh;
        B += zb*sBb + zh*sBh;
        C += zb*sCb + zh*sCh;
    }

    float4 acc[2][NT];
    #pragma unroll
    for (int mt = 0; mt < 2; mt++)
        #pragma unroll
        for (int nt = 0; nt < NT; nt++)
            acc[mt][nt] = make_float4(0.f, 0.f, 0.f, 0.f);

    const int nch = K >> 5;
    const int mwb = (w & 3) * 32;
    const int nwb = (w >> 2) * WN;

    uint32_t aOff[2], aR7[2];
    const uint32_t aHi = lane >> 4;
    #pragma unroll
    for (int mt = 0; mt < 2; mt++){
        int rA = mwb + mt*16 + (lane & 15);
        aOff[mt] = (uint32_t)rA * 128u;
        aR7[mt]  = (uint32_t)(rA & 7);
    }
    uint32_t bOff[NT/2], bR7[NT/2];
    const uint32_t bHi = (lane >> 3) & 1;
    #pragma unroll
    for (int ntp = 0; ntp < NT/2; ntp++){
        int rB = nwb + ntp*16 + (lane & 7) + ((lane >> 4) << 3);
        bOff[ntp] = (uint32_t)rB * 128u;
        bR7[ntp]  = (uint32_t)(rB & 7);
    }

    #define ISSUE(ch, s) do { \
        const uint32_t sa = smem_base + (s)*STAGE; \
        const float* Ag = A + (size_t)row0*lda + (ch)*32; \
        _Pragma("unroll") \
        for (int i = 0; i < 4; i++){ \
            int t2 = tid + 256*i; int m = t2 >> 3, c2 = t2 & 7; \
            CP16(sa + m*128 + ((c2 ^ (m & 7)) << 4), Ag + (size_t)m*lda + c2*4); \
        } \
        const uint32_t sb2 = smem_base + (s)*STAGE + ABYTES; \
        if (TRB){ \
            const float* Bg = B + (size_t)col0*ldb + (ch)*32; \
            _Pragma("unroll") \
            for (int i = 0; i < BN/32; i++){ \
                int t2 = tid + 256*i; int n = t2 >> 3, c2 = t2 & 7; \
                CP16(sb2 + n*128 + ((c2 ^ (n & 7)) << 4), Bg + (size_t)n*ldb + c2*4); \
            } \
        } else { \
            const float* Bg = B + (size_t)(ch)*32*ldb + col0; \
            _Pragma("unroll") \
            for (int i = 0; i < BN/32; i++){ \
                int t2 = tid + 256*i; int k = t2 / CH, c2 = t2 % CH; \
                CP16(sb2 + k*(BN*4) + (((c2 ^ (2*(k & 7))) & (CH-1)) << 4), \
                     Bg + (size_t)k*ldb + c2*4); \
            } \
        } \
        CPCOMMIT(); \
    } while(0)

    ISSUE(0, 0);
    ISSUE(1, 1);

    for (int ch = 0; ch < nch; ch++){
        const int p = ch % 3;
        if (ch + 2 < nch) ISSUE(ch+2, (ch+2)%3); else CPCOMMIT();
        CPWAIT(2);
        __syncthreads();

        const uint32_t sA = smem_base + p*STAGE;
        const uint32_t sB = sA + ABYTES;
        const uint32_t* Bf = reinterpret_cast<const uint32_t*>(smp + p*STAGE + ABYTES);

        #pragma unroll
        for (int ks = 0; ks < 4; ks++){
            uint32_t af[2][4], bfr[NT][2];
            #pragma unroll
            for (int mt = 0; mt < 2; mt++)
                ldsm4(af[mt], sA + aOff[mt] + ((((uint32_t)(2*ks) + aHi) ^ aR7[mt]) << 4));
            if (TRB){
                #pragma unroll
                for (int ntp = 0; ntp < NT/2; ntp++){
                    uint32_t r[4];
                    ldsm4(r, sB + bOff[ntp] + ((((uint32_t)(2*ks) + bHi) ^ bR7[ntp]) << 4));
                    bfr[2*ntp  ][0] = r[0]; bfr[2*ntp  ][1] = r[1];
                    bfr[2*ntp+1][0] = r[2]; bfr[2*ntp+1][1] = r[3];
                }
            } else {
                #pragma unroll
                for (int nt = 0; nt < NT; nt++){
                    int n = nwb + nt*8 + g;
                    int k1 = ks*8 + c;
                    bfr[nt][0] = Bf[ k1   *BN + (((n>>2) ^ (2*c  )) & (CH-1))*4 + (n&3)];
                    bfr[nt][1] = Bf[(k1+4)*BN + (((n>>2) ^ (2*c+8)) & (CH-1))*4 + (n&3)];
                }
            }
            #pragma unroll
            for (int mt = 0; mt < 2; mt++)
                #pragma unroll
                for (int nt = 0; nt < NT; nt++)
                    mma8(acc[mt][nt], af[mt], bfr[nt]);
        }
        __syncthreads();
    }

    #pragma unroll
    for (int mt = 0; mt < 2; mt++){
        int r0 = row0 + mwb + mt*16 + g;
        #pragma unroll
        for (int nt = 0; nt < NT; nt++){
            int cx = col0 + nwb + nt*8 + c*2;
            float4 v = acc[mt][nt];
            if (SCALE){ v.x*=scale; v.y*=scale; v.z*=scale; v.w*=scale; }
            if (BIAS){
                float b0 = bias[cx], b1 = bias[cx+1];
                v.x += b0; v.y += b1; v.z += b0; v.w += b1;
            }
            if (RELU){
                v.x = fmaxf(v.x, 0.f); v.y = fmaxf(v.y, 0.f);
                v.z = fmaxf(v.z, 0.f); v.w = fmaxf(v.w, 0.f);
            }
            if (RES){
                float2 r1 = *reinterpret_cast<const float2*>(&res[(size_t)r0*ldc + cx]);
                float2 r2 = *reinterpret_cast<const float2*>(&res[(size_t)(r0+8)*ldc + cx]);
                v.x += r1.x; v.y += r1.y; v.z += r2.x; v.w += r2.y;
            }
            if (RND){
                v.x = f2tf_f(v.x); v.y = f2tf_f(v.y);
                v.z = f2tf_f(v.z); v.w = f2tf_f(v.w);
            }
            *reinterpret_cast<float2*>(&C[(size_t)r0*ldc + cx])     = make_float2(v.x, v.y);
            *reinterpret_cast<float2*>(&C[(size_t)(r0+8)*ldc + cx]) = make_float2(v.z, v.w);
        }
    }
    #undef ISSUE
}

// =================== fused QK^T + mask + softmax ===================
// One CTA: 128 q-rows x all 256 k-cols for one (b,h). Writes normalized tf32 P.
// grid (TT/128, BATCH*NHD), block 256.
#define QS_STAGE (128*128 + 256*128)            // A 16KB + B 32KB
#define QS_SMEM  (2*QS_STAGE + 2048)            // 2 stages + reduction buffers
__global__ __launch_bounds__(256, 1)
void qksoft(const float* __restrict__ Q, const float* __restrict__ Kmat,
            long long sTok, const int* __restrict__ mask,
            float* __restrict__ P, int causal)
{
    constexpr int NT = 16;
    extern __shared__ char smp[];
    const uint32_t smem_base = (uint32_t)__cvta_generic_to_shared(smp);

    const int tid  = threadIdx.x;
    const int w    = tid >> 5, lane = tid & 31;
    const int g    = lane >> 2, c = lane & 3;
    const int row0 = blockIdx.x * 128;
    {
        const long long zb = blockIdx.y >> 3, zh = blockIdx.y & 7;
        Q    += zb*sTok + zh*HD;
        Kmat += zb*sTok + zh*HD;
        mask += zb*(long long)TT*TT;
        P    += zb*(long long)NHD*TT*TT + zh*(long long)TT*TT;
    }

    float4 acc[2][NT];
    #pragma unroll
    for (int mt = 0; mt < 2; mt++)
        #pragma unroll
        for (int nt = 0; nt < NT; nt++)
            acc[mt][nt] = make_float4(0.f, 0.f, 0.f, 0.f);

    const int mwb = (w & 3) * 32;
    const int nwb = (w >> 2) * 128;

    uint32_t aOff[2], aR7[2];
    const uint32_t aHi = lane >> 4;
    #pragma unroll
    for (int mt = 0; mt < 2; mt++){
        int rA = mwb + mt*16 + (lane & 15);
        aOff[mt] = (uint32_t)rA * 128u;
        aR7[mt]  = (uint32_t)(rA & 7);
    }
    uint32_t bOff[8], bR7[8];
    const uint32_t bHi = (lane >> 3) & 1;
    #pragma unroll
    for (int ntp = 0; ntp < 8; ntp++){
        int rB = nwb + ntp*16 + (lane & 7) + ((lane >> 4) << 3);
        bOff[ntp] = (uint32_t)rB * 128u;
        bR7[ntp]  = (uint32_t)(rB & 7);
    }

    #define QISSUE(ch, s) do { \
        const uint32_t sa = smem_base + (s)*QS_STAGE; \
        const float* Ag = Q + (size_t)row0*QKV + (ch)*32; \
        _Pragma("unroll") \
        for (int i = 0; i < 4; i++){ \
            int t2 = tid + 256*i; int m = t2 >> 3, c2 = t2 & 7; \
            CP16(sa + m*128 + ((c2 ^ (m & 7)) << 4), Ag + (size_t)m*QKV + c2*4); \
        } \
        const uint32_t sb2 = sa + 128*128; \
        const float* Bg = Kmat + (ch)*32; \
        _Pragma("unroll") \
        for (int i = 0; i < 8; i++){ \
            int t2 = tid + 256*i; int n = t2 >> 3, c2 = t2 & 7; \
            CP16(sb2 + n*128 + ((c2 ^ (n & 7)) << 4), Bg + (size_t)n*QKV + c2*4); \
        } \
        CPCOMMIT(); \
    } while(0)

    QISSUE(0, 0);
    QISSUE(1, 1);

    #pragma unroll
    for (int ch = 0; ch < 2; ch++){
        if (ch == 0) CPWAIT(1); else CPWAIT(0);
        __syncthreads();
        const uint32_t sA = smem_base + ch*QS_STAGE;
        const uint32_t sB = sA + 128*128;
        #pragma unroll
        for (int ks = 0; ks < 4; ks++){
            uint32_t af[2][4], bfr[NT][2];
            #pragma unroll
            for (int mt = 0; mt < 2; mt++)
                ldsm4(af[mt], sA + aOff[mt] + ((((uint32_t)(2*ks) + aHi) ^ aR7[mt]) << 4));
            #pragma unroll
            for (int ntp = 0; ntp < 8; ntp++){
                uint32_t r[4];
                ldsm4(r, sB + bOff[ntp] + ((((uint32_t)(2*ks) + bHi) ^ bR7[ntp]) << 4));
                bfr[2*ntp  ][0] = r[0]; bfr[2*ntp  ][1] = r[1];
                bfr[2*ntp+1][0] = r[2]; bfr[2*ntp+1][1] = r[3];
            }
            #pragma unroll
            for (int mt = 0; mt < 2; mt++)
                #pragma unroll
                for (int nt = 0; nt < NT; nt++)
                    mma8(acc[mt][nt], af[mt], bfr[nt]);
        }
        __syncthreads();
    }
    #undef QISSUE

    // ---- fused softmax epilogue ----
    float* redm = reinterpret_cast<float*>(smp + 2*QS_STAGE);   // [2][128]
    float* reds = redm + 256;                                    // [2][128]

    // pass 1: scale + mask -> row max
    float rmax[4] = {-3.4e38f, -3.4e38f, -3.4e38f, -3.4e38f};
    #pragma unroll
    for (int mt = 0; mt < 2; mt++){
        const int qi0 = row0 + mwb + mt*16 + g;
        const int qi1 = qi0 + 8;
        #pragma unroll
        for (int nt = 0; nt < NT; nt++){
            const int cx = nwb + nt*8 + c*2;
            float4 v = acc[mt][nt];
            v.x *= ATT_SCALE; v.y *= ATT_SCALE; v.z *= ATT_SCALE; v.w *= ATT_SCALE;
            int2 m0 = *reinterpret_cast<const int2*>(&mask[(size_t)qi0*TT + cx]);
            int2 m1 = *reinterpret_cast<const int2*>(&mask[(size_t)qi1*TT + cx]);
            bool okx = m0.x && (!causal || cx   <= qi0);
            bool oky = m0.y && (!causal || cx+1 <= qi0);
            bool okz = m1.x && (!causal || cx   <= qi1);
            bool okw = m1.y && (!causal || cx+1 <= qi1);
            v.x = okx ? v.x : NEGBIG;
            v.y = oky ? v.y : NEGBIG;
            v.z = okz ? v.z : NEGBIG;
            v.w = okw ? v.w : NEGBIG;
            acc[mt][nt] = v;
            rmax[mt*2+0] = fmaxf(rmax[mt*2+0], fmaxf(v.x, v.y));
            rmax[mt*2+1] = fmaxf(rmax[mt*2+1], fmaxf(v.z, v.w));
        }
    }
    #pragma unroll
    for (int h = 0; h < 4; h++){
        rmax[h] = fmaxf(rmax[h], __shfl_xor_sync(0xffffffffu, rmax[h], 1));
        rmax[h] = fmaxf(rmax[h], __shfl_xor_sync(0xffffffffu, rmax[h], 2));
    }
    const int half = w >> 2;
    if (c == 0){
        redm[half*128 + mwb      + g] = rmax[0];
        redm[half*128 + mwb +  8 + g] = rmax[1];
        redm[half*128 + mwb + 16 + g] = rmax[2];
        redm[half*128 + mwb + 24 + g] = rmax[3];
    }
    __syncthreads();
    float M[4];
    M[0] = fmaxf(redm[mwb      + g], redm[128 + mwb      + g]);
    M[1] = fmaxf(redm[mwb +  8 + g], redm[128 + mwb +  8 + g]);
    M[2] = fmaxf(redm[mwb + 16 + g], redm[128 + mwb + 16 + g]);
    M[3] = fmaxf(redm[mwb + 24 + g], redm[128 + mwb + 24 + g]);

    // pass 2: exp -> row sum
    float rsum[4] = {0.f, 0.f, 0.f, 0.f};
    #pragma unroll
    for (int mt = 0; mt < 2; mt++){
        #pragma unroll
        for (int nt = 0; nt < NT; nt++){
            float4 v = acc[mt][nt];
            v.x = expf(v.x - M[mt*2+0]);
            v.y = expf(v.y - M[mt*2+0]);
            v.z = expf(v.z - M[mt*2+1]);
            v.w = expf(v.w - M[mt*2+1]);
            acc[mt][nt] = v;
            rsum[mt*2+0] += v.x + v.y;
            rsum[mt*2+1] += v.z + v.w;
        }
    }
    #pragma unroll
    for (int h = 0; h < 4; h++){
        rsum[h] += __shfl_xor_sync(0xffffffffu, rsum[h], 1);
        rsum[h] += __shfl_xor_sync(0xffffffffu, rsum[h], 2);
    }
    if (c == 0){
        reds[half*128 + mwb      + g] = rsum[0];
        reds[half*128 + mwb +  8 + g] = rsum[1];
        reds[half*128 + mwb + 16 + g] = rsum[2];
        reds[half*128 + mwb + 24 + g] = rsum[3];
    }
    __syncthreads();
    float inv[4];
    inv[0] = 1.f / (reds[mwb      + g] + reds[128 + mwb      + g]);
    inv[1] = 1.f / (reds[mwb +  8 + g] + reds[128 + mwb +  8 + g]);
    inv[2] = 1.f / (reds[mwb + 16 + g] + reds[128 + mwb + 16 + g]);
    inv[3] = 1.f / (reds[mwb + 24 + g] + reds[128 + mwb + 24 + g]);

    // pass 3: normalize + round + store
    #pragma unroll
    for (int mt = 0; mt < 2; mt++){
        const int qi0 = row0 + mwb + mt*16 + g;
        const int qi1 = qi0 + 8;
        #pragma unroll
        for (int nt = 0; nt < NT; nt++){
            const int cx = nwb + nt*8 + c*2;
            float4 v = acc[mt][nt];
            float px = f2tf_f(v.x * inv[mt*2+0]);
            float py = f2tf_f(v.y * inv[mt*2+0]);
            float pz = f2tf_f(v.z * inv[mt*2+1]);
            float pw = f2tf_f(v.w * inv[mt*2+1]);
            *reinterpret_cast<float2*>(&P[(size_t)qi0*TT + cx]) = make_float2(px, py);
            *reinterpret_cast<float2*>(&P[(size_t)qi1*TT + cx]) = make_float2(pz, pw);
        }
    }
}

// ---------------- host orchestration ----------------
static float* symaddr(const void* sym){
    void* p = nullptr;
    cudaGetSymbolAddress(&p, sym);
    return (float*)p;
}

#define S3_128 (3*(128*128 + 128*128))
#define S3_64K (3*(128*128 + 32*64*4))

#define G_PROJ gemm_ca<128,true ,false,false,false,false,true >
#define G_PV   gemm_ca<64 ,false,false,false,false,false,true >
#define G_WO   gemm_ca<128,true ,true ,false,true ,false,false>
#define G_FF1  gemm_ca<128,true ,true ,true ,false,false,true >

extern "C" void kernel_launch(void* const* d_in, const int* in_sizes, int n_in,
                              void* d_out, int out_size)
{
    const float* x    = (const float*)d_in[0];
    const float* ca   = (const float*)d_in[1];
    const int*   x_m  = (const int*)  d_in[2];
    const int*   ca_m = (const int*)  d_in[3];
    const float* Wq_s = (const float*)d_in[4];
    const float* Wk_s = (const float*)d_in[5];
    const float* Wv_s = (const float*)d_in[6];
    const float* Wo_s = (const float*)d_in[7];
    const float* bo_s = (const float*)d_in[8];
    const float* Wq_c = (const float*)d_in[9];
    const float* Wk_c = (const float*)d_in[10];
    const float* Wv_c = (const float*)d_in[11];
    const float* Wo_c = (const float*)d_in[12];
    const float* bo_c = (const float*)d_in[13];
    const float* g1   = (const float*)d_in[14];
    const float* be1  = (const float*)d_in[15];
    const float* g2   = (const float*)d_in[16];
    const float* be2  = (const float*)d_in[17];
    const float* g3   = (const float*)d_in[18];
    const float* be3  = (const float*)d_in[19];
    const float* Wf1  = (const float*)d_in[20];
    const float* bf1  = (const float*)d_in[21];
    const float* Wf2  = (const float*)d_in[22];
    const float* bf2  = (const float*)d_in[23];
    float* out = (float*)d_out;

    float* p_ln   = symaddr(g_ln);
    float* p_qkv  = symaddr(g_qkv);
    float* p_att  = symaddr(g_att);
    float* p_x1   = symaddr(g_x1);
    float* p_x2   = symaddr(g_x2);
    float* p_sc   = symaddr(g_sc);
    float* p_h    = symaddr(g_h);
    float* p_wqs  = symaddr(g_wqkvs);
    float* p_wqc  = symaddr(g_wqkvc);
    float* p_wos  = symaddr(g_wos);
    float* p_woc  = symaddr(g_woc);
    float* p_wf1  = symaddr(g_wf1t);
    float* p_wf2  = symaddr(g_wf2t);

    static bool attrDone = false;
    if (!attrDone){
        cudaFuncSetAttribute(G_PROJ, cudaFuncAttributeMaxDynamicSharedMemorySize, S3_128);
        cudaFuncSetAttribute(G_PV,   cudaFuncAttributeMaxDynamicSharedMemorySize, S3_64K);
        cudaFuncSetAttribute(G_WO,   cudaFuncAttributeMaxDynamicSharedMemorySize, S3_128);
        cudaFuncSetAttribute(G_FF1,  cudaFuncAttributeMaxDynamicSharedMemorySize, S3_128);
        cudaFuncSetAttribute(qksoft, cudaFuncAttributeMaxDynamicSharedMemorySize, QS_SMEM);
        attrDone = true;
    }

    // ---- prepass: transpose + tf32-round all weights ----
    dim3 tb(32, 8);
    wtrans8<<<dim3(16,16,8), tb>>>(Wq_s, Wk_s, Wv_s, Wo_s, Wq_c, Wk_c, Wv_c, Wo_c,
                                   p_wqs, p_wos, p_wqc, p_woc);
    ttrans<<<dim3(FF/32, CC/32), tb>>>(Wf1, p_wf1, CC, FF);
    ttrans<<<dim3(CC/32, FF/32), tb>>>(Wf2, p_wf2, FF, CC);

    dim3 gQKV(QKV/128, MROWS/128, 1);
    dim3 gQc (CC/128,  MROWS/128, 1);
    dim3 gKVc(1024/128,MROWS/128, 1);
    dim3 gCC (CC/128,  MROWS/128, 1);
    dim3 gFF (FF/128,  MROWS/128, 1);
    dim3 gQS (TT/128, BATCH*NHD);
    dim3 gPV (1, TT/128, BATCH*NHD);

    const long long sTokQ = (long long)TT*QKV;
    const long long sTokC = (long long)TT*CC;
    const long long sScB  = (long long)NHD*TT*TT;
    const long long sScH  = (long long)TT*TT;

    // ===== self-attention =====
    ln_kernel<<<MROWS,128>>>(x, g1, be1, p_ln);
    G_PROJ<<<gQKV,256,S3_128>>>(p_ln, CC,0,0, p_wqs, CC,0,0, nullptr,nullptr, p_qkv, QKV,0,0, CC, 1.f);
    qksoft<<<gQS,256,QS_SMEM>>>(p_qkv, p_qkv + CC, sTokQ, x_m, p_sc, 1);
    G_PV<<<gPV,256,S3_64K>>>(p_sc, TT, sScB, sScH, p_qkv + 1024, QKV, sTokQ, HD,
                             nullptr, nullptr, p_att, CC, sTokC, HD, TT, 1.f);
    G_WO<<<gCC,256,S3_128>>>(p_att, CC,0,0, p_wos, CC,0,0, bo_s, x, p_x1, CC,0,0, CC, 1.f);

    // ===== cross-attention =====
    ln_kernel<<<MROWS,128>>>(p_x1, g2, be2, p_ln);
    G_PROJ<<<gQc,256,S3_128>>>(p_ln, CC,0,0, p_wqc, CC,0,0, nullptr,nullptr, p_qkv, QKV,0,0, CC, 1.f);
    G_PROJ<<<gKVc,256,S3_128>>>(ca, CC,0,0, p_wqc + (size_t)CC*CC, CC,0,0, nullptr,nullptr,
                                p_qkv + CC, QKV,0,0, CC, 1.f);
    qksoft<<<gQS,256,QS_SMEM>>>(p_qkv, p_qkv + CC, sTokQ, ca_m, p_sc, 0);
    G_PV<<<gPV,256,S3_64K>>>(p_sc, TT, sScB, sScH, p_qkv + 1024, QKV, sTokQ, HD,
                             nullptr, nullptr, p_att, CC, sTokC, HD, TT, 1.f);
    G_WO<<<gCC,256,S3_128>>>(p_att, CC,0,0, p_woc, CC,0,0, bo_c, p_x1, p_x2, CC,0,0, CC, 1.f);

    // ===== feed-forward =====
    ln_kernel<<<MROWS,128>>>(p_x2, g3, be3, p_ln);
    G_FF1<<<gFF,256,S3_128>>>(p_ln, CC,0,0, p_wf1, CC,0,0, bf1, nullptr, p_h, FF,0,0, CC, 1.f);
    G_WO <<<gCC,256,S3_128>>>(p_h, FF,0,0, p_wf2, FF,0,0, bf2, p_x2, out, CC,0,0, FF, 1.f);

    (void)in_sizes; (void)n_in; (void)out_size;
}

// round 7
// speedup vs baseline: 6.5695x; 1.5096x over previous
#include <cuda_runtime.h>
#include <cuda_fp16.h>
#include <cstdint>

#define BATCH 64
#define TT 256
#define CC 512
#define NHD 8
#define HD 64
#define MROWS (BATCH*TT)      // 16384
#define FF 2048
#define QKV 1536
#define ATT_SCALE 0.044194173824159216f   // 512^-0.5
#define NEGBIG (-1e9f)

// ---------------- scratch (device globals; no allocations) ----------------
__device__ __half g_ln  [MROWS*CC];
__device__ __half g_qkv [(size_t)MROWS*QKV];
__device__ __half g_att [MROWS*CC];
__device__ __half g_ca  [MROWS*CC];
__device__ __half g_sc  [(size_t)BATCH*NHD*TT*TT];   // normalized P (fp16)
__device__ __half g_h   [(size_t)MROWS*FF];
__device__ __half g_wqkvs[QKV*CC];
__device__ __half g_wqkvc[QKV*CC];
__device__ __half g_wos [CC*CC];
__device__ __half g_woc [CC*CC];
__device__ __half g_wf1t[FF*CC];
__device__ __half g_wf2t[CC*FF];
__device__ float  g_x1  [MROWS*CC];
__device__ float  g_x2  [MROWS*CC];

// ---------------- helpers ----------------
__device__ __forceinline__ void mma16(float4& d, const uint32_t* a, const uint32_t* b){
    asm volatile("mma.sync.aligned.m16n8k16.row.col.f32.f16.f16.f32 "
        "{%0,%1,%2,%3}, {%4,%5,%6,%7}, {%8,%9}, {%0,%1,%2,%3};"
        : "+f"(d.x), "+f"(d.y), "+f"(d.z), "+f"(d.w)
        : "r"(a[0]), "r"(a[1]), "r"(a[2]), "r"(a[3]), "r"(b[0]), "r"(b[1]));
}
__device__ __forceinline__ void ldsm4(uint32_t* r, uint32_t addr){
    asm volatile("ldmatrix.sync.aligned.m8n8.x4.shared.b16 {%0,%1,%2,%3}, [%4];"
        : "=r"(r[0]), "=r"(r[1]), "=r"(r[2]), "=r"(r[3]) : "r"(addr));
}
__device__ __forceinline__ void ldsm4t(uint32_t* r, uint32_t addr){
    asm volatile("ldmatrix.sync.aligned.m8n8.x4.trans.shared.b16 {%0,%1,%2,%3}, [%4];"
        : "=r"(r[0]), "=r"(r[1]), "=r"(r[2]), "=r"(r[3]) : "r"(addr));
}
#define CP16(d, s) asm volatile("cp.async.cg.shared.global [%0], [%1], 16;" :: "r"(d), "l"(s))
#define CPCOMMIT() asm volatile("cp.async.commit_group;" ::: "memory")
#define CPWAIT(n)  asm volatile("cp.async.wait_group %0;" :: "n"(n) : "memory")

__device__ __forceinline__ float warpSum(float v){
    #pragma unroll
    for (int o = 16; o; o >>= 1) v += __shfl_xor_sync(0xffffffffu, v, o);
    return v;
}
__device__ __forceinline__ float warpMax(float v){
    #pragma unroll
    for (int o = 16; o; o >>= 1) v = fmaxf(v, __shfl_xor_sync(0xffffffffu, v, o));
    return v;
}

// ---------------- prepass: weight transpose -> fp16 [N][K] ----------------
__global__ void wtrans8(const float* s0, const float* s1, const float* s2, const float* s3,
                        const float* s4, const float* s5, const float* s6, const float* s7,
                        __half* qkvs, __half* wos, __half* qkvc, __half* woc)
{
    int z = blockIdx.z;
    const float* src = (z==0)?s0:(z==1)?s1:(z==2)?s2:(z==3)?s3:(z==4)?s4:(z==5)?s5:(z==6)?s6:s7;
    __half* dst = (z<3) ? qkvs + (size_t)z*CC*CC
               : (z==3) ? wos
               : (z<7) ? qkvc + (size_t)(z-4)*CC*CC
               : woc;
    __shared__ float t[32][33];
    int bx = blockIdx.x*32, by = blockIdx.y*32;
    int x = threadIdx.x, y = threadIdx.y;
    #pragma unroll
    for (int i = 0; i < 32; i += 8)
        t[y+i][x] = src[(size_t)(by + y + i)*CC + bx + x];
    __syncthreads();
    #pragma unroll
    for (int i = 0; i < 32; i += 8)
        dst[(size_t)(bx + y + i)*CC + by + x] = __float2half_rn(t[x][y+i]);
}

__global__ void ttrans(const float* __restrict__ src, __half* __restrict__ dst, int R, int C)
{
    __shared__ float t[32][33];
    int bx = blockIdx.x*32, by = blockIdx.y*32;
    int x = threadIdx.x, y = threadIdx.y;
    #pragma unroll
    for (int i = 0; i < 32; i += 8)
        t[y+i][x] = src[(size_t)(by + y + i)*C + bx + x];
    __syncthreads();
    #pragma unroll
    for (int i = 0; i < 32; i += 8)
        dst[(size_t)(bx + y + i)*R + by + x] = __float2half_rn(t[x][y+i]);
}

__global__ void f2h_kernel(const float* __restrict__ src, __half* __restrict__ dst, int n4){
    int i = blockIdx.x*256 + threadIdx.x;
    if (i < n4){
        float4 v = reinterpret_cast<const float4*>(src)[i];
        __half2 a = __floats2half2_rn(v.x, v.y);
        __half2 b = __floats2half2_rn(v.z, v.w);
        reinterpret_cast<__half2*>(dst)[2*i]   = a;
        reinterpret_cast<__half2*>(dst)[2*i+1] = b;
    }
}

// ---------------- layernorm (fp16 output) ----------------
__global__ void ln_kernel(const float* __restrict__ x, const float* __restrict__ g,
                          const float* __restrict__ be, __half* __restrict__ y)
{
    int r = blockIdx.x;
    int t = threadIdx.x;
    const float4* xr = reinterpret_cast<const float4*>(x + (size_t)r*CC);
    float4 v = xr[t];
    float s  = v.x + v.y + v.z + v.w;
    float sq = v.x*v.x + v.y*v.y + v.z*v.z + v.w*v.w;

    __shared__ float rs[4], rq[4];
    int lane = t & 31, wid = t >> 5;
    s = warpSum(s); sq = warpSum(sq);
    if (lane == 0){ rs[wid] = s; rq[wid] = sq; }
    __syncthreads();
    if (t == 0){
        float a = rs[0]+rs[1]+rs[2]+rs[3];
        float b = rq[0]+rq[1]+rq[2]+rq[3];
        rs[0] = a * (1.0f/CC);
        rq[0] = b * (1.0f/CC);
    }
    __syncthreads();
    float mu  = rs[0];
    float var = rq[0] - mu*mu;
    float rstd = rsqrtf(var + 1e-5f);

    const float4* g4  = reinterpret_cast<const float4*>(g);
    const float4* be4 = reinterpret_cast<const float4*>(be);
    float4 gg = g4[t], bb = be4[t];
    __half2 o0 = __floats2half2_rn((v.x - mu)*rstd*gg.x + bb.x, (v.y - mu)*rstd*gg.y + bb.y);
    __half2 o1 = __floats2half2_rn((v.z - mu)*rstd*gg.z + bb.z, (v.w - mu)*rstd*gg.w + bb.w);
    __half2* yh = reinterpret_cast<__half2*>(y + (size_t)r*CC);
    yh[2*t]   = o0;
    yh[2*t+1] = o1;
}

// =================== fp16 mma.sync GEMM, cp.async 3-stage + ldmatrix ===================
// A[M,K] fp16 row-major. TRB=true: B fp16 [N][K]; TRB=false: B fp16 [K][N] (trans-ldmatrix).
// BM=128, BN in {128,64}. 256 threads = 8 warps (4M x 2N). BK=32.
template<int BN, bool TRB, bool BIAS, bool RELU, bool RES, bool HOUT>
__global__ __launch_bounds__(256, 2)
void gemm_h(const __half* __restrict__ A, int lda, long long sAb, long long sAh,
            const __half* __restrict__ B, int ldb, long long sBb, long long sBh,
            const float* __restrict__ bias, const float* __restrict__ res,
            void* __restrict__ Cv, int ldc, long long sCb, long long sCh, int K)
{
    constexpr int NT   = BN/16;            // n8 tiles per warp
    constexpr int WN   = BN/2;
    constexpr int ABYTES = 128*64;         // 8 KB
    constexpr int BBYTES = TRB ? BN*64 : 32*128;
    constexpr int STAGE  = ABYTES + BBYTES;

    extern __shared__ char smp[];
    const uint32_t smem_base = (uint32_t)__cvta_generic_to_shared(smp);

    const int tid  = threadIdx.x;
    const int w    = tid >> 5, lane = tid & 31;
    const int g    = lane >> 2, c = lane & 3;
    const int row0 = blockIdx.y * 128;
    const int col0 = blockIdx.x * BN;
    {
        const long long zb = blockIdx.z >> 3, zh = blockIdx.z & 7;
        A += zb*sAb + zh*sAh;
        B += zb*sBb + zh*sBh;
    }
    float* Cf = (float*)Cv;
    __half* Ch = (__half*)Cv;
    {
        const long long zb = blockIdx.z >> 3, zh = blockIdx.z & 7;
        Cf += zb*sCb + zh*sCh;
        Ch += zb*sCb + zh*sCh;
    }

    float4 acc[2][NT];
    #pragma unroll
    for (int mt = 0; mt < 2; mt++)
        #pragma unroll
        for (int nt = 0; nt < NT; nt++)
            acc[mt][nt] = make_float4(0.f, 0.f, 0.f, 0.f);

    const int nch = K >> 5;
    const int mwb = (w & 3) * 32;
    const int nwb = (w >> 2) * WN;

    // ldmatrix address precompute
    const int lrow = lane & 7;
    uint32_t aBase[2], aSw[2];
    const uint32_t aKc = (uint32_t)(lane >> 4);
    #pragma unroll
    for (int mt = 0; mt < 2; mt++){
        int m = mwb + mt*16 + ((lane>>3)&1)*8 + lrow;
        aBase[mt] = (uint32_t)m * 64u;
        aSw[mt]   = (uint32_t)((m>>1)&3);
    }
    uint32_t bBase[(NT+1)/2], bSw[(NT+1)/2];
    uint32_t bKc;
    if (TRB){
        bKc = (uint32_t)((lane>>3)&1);
        #pragma unroll
        for (int ng = 0; ng < NT/2; ng++){
            int n = nwb + ng*16 + (lane>>4)*8 + lrow;
            bBase[ng] = (uint32_t)n * 64u;
            bSw[ng]   = (uint32_t)((n>>1)&3);
        }
    } else {
        int kb = ((lane>>3)&1)*8 + lrow;      // 0..15 within k16
        bKc = (uint32_t)(kb & 7);             // swizzle key
        #pragma unroll
        for (int ng = 0; ng < NT/2; ng++){
            int nc = (nwb>>3) + ng*2 + (lane>>4);
            bBase[ng] = (uint32_t)kb*128u + ((((uint32_t)nc ^ bKc) & 7u) << 4);
        }
    }

    #define ISSUE(ch, s) do { \
        const uint32_t sa = smem_base + (s)*STAGE; \
        const __half* Ag = A + (size_t)row0*lda + (ch)*32; \
        _Pragma("unroll") \
        for (int i = 0; i < 2; i++){ \
            int t2 = tid + 256*i; int m = t2 >> 2, c2 = t2 & 3; \
            CP16(sa + m*64 + ((c2 ^ ((m>>1)&3)) << 4), Ag + (size_t)m*lda + c2*8); \
        } \
        const uint32_t sb2 = sa + ABYTES; \
        if (TRB){ \
            const __half* Bg = B + (size_t)col0*ldb + (ch)*32; \
            _Pragma("unroll") \
            for (int i = 0; i < BN/64; i++){ \
                int t2 = tid + 256*i; int n = t2 >> 2, c2 = t2 & 3; \
                CP16(sb2 + n*64 + ((c2 ^ ((n>>1)&3)) << 4), Bg + (size_t)n*ldb + c2*8); \
            } \
        } else { \
            const __half* Bg = B + (size_t)(ch)*32*ldb + col0; \
            { \
                int k = tid >> 3, c2 = tid & 7; \
                CP16(sb2 + k*128 + ((c2 ^ (k & 7)) << 4), Bg + (size_t)k*ldb + c2*8); \
            } \
        } \
        CPCOMMIT(); \
    } while(0)

    ISSUE(0, 0);
    ISSUE(1, 1);

    for (int ch = 0; ch < nch; ch++){
        const int p = ch % 3;
        if (ch + 2 < nch) ISSUE(ch+2, (ch+2)%3); else CPCOMMIT();
        CPWAIT(2);
        __syncthreads();

        const uint32_t sA = smem_base + p*STAGE;
        const uint32_t sB = sA + ABYTES;

        #pragma unroll
        for (int ks = 0; ks < 2; ks++){
            uint32_t af[2][4], bfr[NT][2];
            #pragma unroll
            for (int mt = 0; mt < 2; mt++)
                ldsm4(af[mt], sA + aBase[mt] + ((((uint32_t)(2*ks) + aKc) ^ aSw[mt]) << 4));
            if (TRB){
                #pragma unroll
                for (int ng = 0; ng < NT/2; ng++){
                    uint32_t r[4];
                    ldsm4(r, sB + bBase[ng] + ((((uint32_t)(2*ks) + bKc) ^ bSw[ng]) << 4));
                    bfr[2*ng  ][0] = r[0]; bfr[2*ng  ][1] = r[1];
                    bfr[2*ng+1][0] = r[2]; bfr[2*ng+1][1] = r[3];
                }
            } else {
                #pragma unroll
                for (int ng = 0; ng < NT/2; ng++){
                    uint32_t r[4];
                    ldsm4t(r, sB + (uint32_t)ks*2048u + bBase[ng]);
                    bfr[2*ng  ][0] = r[0]; bfr[2*ng  ][1] = r[1];
                    bfr[2*ng+1][0] = r[2]; bfr[2*ng+1][1] = r[3];
                }
            }
            #pragma unroll
            for (int mt = 0; mt < 2; mt++)
                #pragma unroll
                for (int nt = 0; nt < NT; nt++)
                    mma16(acc[mt][nt], af[mt], bfr[nt]);
        }
        __syncthreads();
    }

    // ---- epilogue ----
    #pragma unroll
    for (int mt = 0; mt < 2; mt++){
        int r0 = row0 + mwb + mt*16 + g;
        #pragma unroll
        for (int nt = 0; nt < NT; nt++){
            int cx = col0 + nwb + nt*8 + c*2;
            float4 v = acc[mt][nt];
            if (BIAS){
                float b0 = bias[cx], b1 = bias[cx+1];
                v.x += b0; v.y += b1; v.z += b0; v.w += b1;
            }
            if (RELU){
                v.x = fmaxf(v.x, 0.f); v.y = fmaxf(v.y, 0.f);
                v.z = fmaxf(v.z, 0.f); v.w = fmaxf(v.w, 0.f);
            }
            if (RES){
                float2 r1 = *reinterpret_cast<const float2*>(&res[(size_t)r0*ldc + cx]);
                float2 r2 = *reinterpret_cast<const float2*>(&res[(size_t)(r0+8)*ldc + cx]);
                v.x += r1.x; v.y += r1.y; v.z += r2.x; v.w += r2.y;
            }
            if (HOUT){
                *reinterpret_cast<__half2*>(&Ch[(size_t)r0*ldc + cx])     = __floats2half2_rn(v.x, v.y);
                *reinterpret_cast<__half2*>(&Ch[(size_t)(r0+8)*ldc + cx]) = __floats2half2_rn(v.z, v.w);
            } else {
                *reinterpret_cast<float2*>(&Cf[(size_t)r0*ldc + cx])     = make_float2(v.x, v.y);
                *reinterpret_cast<float2*>(&Cf[(size_t)(r0+8)*ldc + cx]) = make_float2(v.z, v.w);
            }
        }
    }
    #undef ISSUE
}

// =================== fused QK^T + mask + softmax (fp16 in/out) ===================
#define QS_STAGE (128*64 + 256*64)              // A 8KB + B 16KB
#define QS_SMEM  (2*QS_STAGE + 2048)
__global__ __launch_bounds__(256, 1)
void qksoft(const __half* __restrict__ Q, const __half* __restrict__ Kmat,
            long long sTok, const int* __restrict__ mask,
            __half* __restrict__ P, int causal)
{
    constexpr int NT = 16;
    extern __shared__ char smp[];
    const uint32_t smem_base = (uint32_t)__cvta_generic_to_shared(smp);

    const int tid  = threadIdx.x;
    const int w    = tid >> 5, lane = tid & 31;
    const int g    = lane >> 2, c = lane & 3;
    const int row0 = blockIdx.x * 128;
    {
        const long long zb = blockIdx.y >> 3, zh = blockIdx.y & 7;
        Q    += zb*sTok + zh*HD;
        Kmat += zb*sTok + zh*HD;
        mask += zb*(long long)TT*TT;
        P    += zb*(long long)NHD*TT*TT + zh*(long long)TT*TT;
    }

    float4 acc[2][NT];
    #pragma unroll
    for (int mt = 0; mt < 2; mt++)
        #pragma unroll
        for (int nt = 0; nt < NT; nt++)
            acc[mt][nt] = make_float4(0.f, 0.f, 0.f, 0.f);

    const int mwb = (w & 3) * 32;
    const int nwb = (w >> 2) * 128;

    const int lrow = lane & 7;
    uint32_t aBase[2], aSw[2];
    const uint32_t aKc = (uint32_t)(lane >> 4);
    #pragma unroll
    for (int mt = 0; mt < 2; mt++){
        int m = mwb + mt*16 + ((lane>>3)&1)*8 + lrow;
        aBase[mt] = (uint32_t)m * 64u;
        aSw[mt]   = (uint32_t)((m>>1)&3);
    }
    uint32_t bBase[8], bSw[8];
    const uint32_t bKc = (uint32_t)((lane>>3)&1);
    #pragma unroll
    for (int ng = 0; ng < 8; ng++){
        int n = nwb + ng*16 + (lane>>4)*8 + lrow;
        bBase[ng] = (uint32_t)n * 64u;
        bSw[ng]   = (uint32_t)((n>>1)&3);
    }

    #define QISSUE(ch, s) do { \
        const uint32_t sa = smem_base + (s)*QS_STAGE; \
        const __half* Ag = Q + (size_t)row0*QKV + (ch)*32; \
        _Pragma("unroll") \
        for (int i = 0; i < 2; i++){ \
            int t2 = tid + 256*i; int m = t2 >> 2, c2 = t2 & 3; \
            CP16(sa + m*64 + ((c2 ^ ((m>>1)&3)) << 4), Ag + (size_t)m*QKV + c2*8); \
        } \
        const uint32_t sb2 = sa + 128*64; \
        const __half* Bg = Kmat + (ch)*32; \
        _Pragma("unroll") \
        for (int i = 0; i < 4; i++){ \
            int t2 = tid + 256*i; int n = t2 >> 2, c2 = t2 & 3; \
            CP16(sb2 + n*64 + ((c2 ^ ((n>>1)&3)) << 4), Bg + (size_t)n*QKV + c2*8); \
        } \
        CPCOMMIT(); \
    } while(0)

    QISSUE(0, 0);
    QISSUE(1, 1);

    #pragma unroll
    for (int ch = 0; ch < 2; ch++){
        if (ch == 0) CPWAIT(1); else CPWAIT(0);
        __syncthreads();
        const uint32_t sA = smem_base + ch*QS_STAGE;
        const uint32_t sB = sA + 128*64;
        #pragma unroll
        for (int ks = 0; ks < 2; ks++){
            uint32_t af[2][4], bfr[NT][2];
            #pragma unroll
            for (int mt = 0; mt < 2; mt++)
                ldsm4(af[mt], sA + aBase[mt] + ((((uint32_t)(2*ks) + aKc) ^ aSw[mt]) << 4));
            #pragma unroll
            for (int ng = 0; ng < 8; ng++){
                uint32_t r[4];
                ldsm4(r, sB + bBase[ng] + ((((uint32_t)(2*ks) + bKc) ^ bSw[ng]) << 4));
                bfr[2*ng  ][0] = r[0]; bfr[2*ng  ][1] = r[1];
                bfr[2*ng+1][0] = r[2]; bfr[2*ng+1][1] = r[3];
            }
            #pragma unroll
            for (int mt = 0; mt < 2; mt++)
                #pragma unroll
                for (int nt = 0; nt < NT; nt++)
                    mma16(acc[mt][nt], af[mt], bfr[nt]);
        }
        __syncthreads();
    }
    #undef QISSUE

    // ---- fused softmax epilogue ----
    float* redm = reinterpret_cast<float*>(smp + 2*QS_STAGE);   // [2][128]
    float* reds = redm + 256;

    float rmax[4] = {-3.4e38f, -3.4e38f, -3.4e38f, -3.4e38f};
    #pragma unroll
    for (int mt = 0; mt < 2; mt++){
        const int qi0 = row0 + mwb + mt*16 + g;
        const int qi1 = qi0 + 8;
        #pragma unroll
        for (int nt = 0; nt < NT; nt++){
            const int cx = nwb + nt*8 + c*2;
            float4 v = acc[mt][nt];
            v.x *= ATT_SCALE; v.y *= ATT_SCALE; v.z *= ATT_SCALE; v.w *= ATT_SCALE;
            int2 m0 = *reinterpret_cast<const int2*>(&mask[(size_t)qi0*TT + cx]);
            int2 m1 = *reinterpret_cast<const int2*>(&mask[(size_t)qi1*TT + cx]);
            bool okx = m0.x && (!causal || cx   <= qi0);
            bool oky = m0.y && (!causal || cx+1 <= qi0);
            bool okz = m1.x && (!causal || cx   <= qi1);
            bool okw = m1.y && (!causal || cx+1 <= qi1);
            v.x = okx ? v.x : NEGBIG;
            v.y = oky ? v.y : NEGBIG;
            v.z = okz ? v.z : NEGBIG;
            v.w = okw ? v.w : NEGBIG;
            acc[mt][nt] = v;
            rmax[mt*2+0] = fmaxf(rmax[mt*2+0], fmaxf(v.x, v.y));
            rmax[mt*2+1] = fmaxf(rmax[mt*2+1], fmaxf(v.z, v.w));
        }
    }
    #pragma unroll
    for (int h = 0; h < 4; h++){
        rmax[h] = fmaxf(rmax[h], __shfl_xor_sync(0xffffffffu, rmax[h], 1));
        rmax[h] = fmaxf(rmax[h], __shfl_xor_sync(0xffffffffu, rmax[h], 2));
    }
    const int half_ = w >> 2;
    if (c == 0){
        redm[half_*128 + mwb      + g] = rmax[0];
        redm[half_*128 + mwb +  8 + g] = rmax[1];
        redm[half_*128 + mwb + 16 + g] = rmax[2];
        redm[half_*128 + mwb + 24 + g] = rmax[3];
    }
    __syncthreads();
    float M[4];
    M[0] = fmaxf(redm[mwb      + g], redm[128 + mwb      + g]);
    M[1] = fmaxf(redm[mwb +  8 + g], redm[128 + mwb +  8 + g]);
    M[2] = fmaxf(redm[mwb + 16 + g], redm[128 + mwb + 16 + g]);
    M[3] = fmaxf(redm[mwb + 24 + g], redm[128 + mwb + 24 + g]);

    float rsum[4] = {0.f, 0.f, 0.f, 0.f};
    #pragma unroll
    for (int mt = 0; mt < 2; mt++){
        #pragma unroll
        for (int nt = 0; nt < NT; nt++){
            float4 v = acc[mt][nt];
            v.x = expf(v.x - M[mt*2+0]);
            v.y = expf(v.y - M[mt*2+0]);
            v.z = expf(v.z - M[mt*2+1]);
            v.w = expf(v.w - M[mt*2+1]);
            acc[mt][nt] = v;
            rsum[mt*2+0] += v.x + v.y;
            rsum[mt*2+1] += v.z + v.w;
        }
    }
    #pragma unroll
    for (int h = 0; h < 4; h++){
        rsum[h] += __shfl_xor_sync(0xffffffffu, rsum[h], 1);
        rsum[h] += __shfl_xor_sync(0xffffffffu, rsum[h], 2);
    }
    if (c == 0){
        reds[half_*128 + mwb      + g] = rsum[0];
        reds[half_*128 + mwb +  8 + g] = rsum[1];
        reds[half_*128 + mwb + 16 + g] = rsum[2];
        reds[half_*128 + mwb + 24 + g] = rsum[3];
    }
    __syncthreads();
    float inv[4];
    inv[0] = 1.f / (reds[mwb      + g] + reds[128 + mwb      + g]);
    inv[1] = 1.f / (reds[mwb +  8 + g] + reds[128 + mwb +  8 + g]);
    inv[2] = 1.f / (reds[mwb + 16 + g] + reds[128 + mwb + 16 + g]);
    inv[3] = 1.f / (reds[mwb + 24 + g] + reds[128 + mwb + 24 + g]);

    #pragma unroll
    for (int mt = 0; mt < 2; mt++){
        const int qi0 = row0 + mwb + mt*16 + g;
        const int qi1 = qi0 + 8;
        #pragma unroll
        for (int nt = 0; nt < NT; nt++){
            const int cx = nwb + nt*8 + c*2;
            float4 v = acc[mt][nt];
            *reinterpret_cast<__half2*>(&P[(size_t)qi0*TT + cx]) =
                __floats2half2_rn(v.x * inv[mt*2+0], v.y * inv[mt*2+0]);
            *reinterpret_cast<__half2*>(&P[(size_t)qi1*TT + cx]) =
                __floats2half2_rn(v.z * inv[mt*2+1], v.w * inv[mt*2+1]);
        }
    }
}

// ---------------- host orchestration ----------------
template<typename T>
static T* symaddr(const void* sym){
    void* p = nullptr;
    cudaGetSymbolAddress(&p, sym);
    return (T*)p;
}

#define S3H  (3*(128*64 + 128*64))    // 49152
#define S3PV (3*(128*64 + 32*128))    // 36864

#define G_PROJ gemm_h<128,true ,false,false,false,true >
#define G_PV   gemm_h<64 ,false,false,false,false,true >
#define G_WO   gemm_h<128,true ,true ,false,true ,false>
#define G_FF1  gemm_h<128,true ,true ,true ,false,true >

extern "C" void kernel_launch(void* const* d_in, const int* in_sizes, int n_in,
                              void* d_out, int out_size)
{
    const float* x    = (const float*)d_in[0];
    const float* ca   = (const float*)d_in[1];
    const int*   x_m  = (const int*)  d_in[2];
    const int*   ca_m = (const int*)  d_in[3];
    const float* Wq_s = (const float*)d_in[4];
    const float* Wk_s = (const float*)d_in[5];
    const float* Wv_s = (const float*)d_in[6];
    const float* Wo_s = (const float*)d_in[7];
    const float* bo_s = (const float*)d_in[8];
    const float* Wq_c = (const float*)d_in[9];
    const float* Wk_c = (const float*)d_in[10];
    const float* Wv_c = (const float*)d_in[11];
    const float* Wo_c = (const float*)d_in[12];
    const float* bo_c = (const float*)d_in[13];
    const float* g1   = (const float*)d_in[14];
    const float* be1  = (const float*)d_in[15];
    const float* g2   = (const float*)d_in[16];
    const float* be2  = (const float*)d_in[17];
    const float* g3   = (const float*)d_in[18];
    const float* be3  = (const float*)d_in[19];
    const float* Wf1  = (const float*)d_in[20];
    const float* bf1  = (const float*)d_in[21];
    const float* Wf2  = (const float*)d_in[22];
    const float* bf2  = (const float*)d_in[23];
    float* out = (float*)d_out;

    __half* p_ln  = symaddr<__half>(g_ln);
    __half* p_qkv = symaddr<__half>(g_qkv);
    __half* p_att = symaddr<__half>(g_att);
    __half* p_ca  = symaddr<__half>(g_ca);
    __half* p_sc  = symaddr<__half>(g_sc);
    __half* p_h   = symaddr<__half>(g_h);
    __half* p_wqs = symaddr<__half>(g_wqkvs);
    __half* p_wqc = symaddr<__half>(g_wqkvc);
    __half* p_wos = symaddr<__half>(g_wos);
    __half* p_woc = symaddr<__half>(g_woc);
    __half* p_wf1 = symaddr<__half>(g_wf1t);
    __half* p_wf2 = symaddr<__half>(g_wf2t);
    float*  p_x1  = symaddr<float>(g_x1);
    float*  p_x2  = symaddr<float>(g_x2);

    static bool attrDone = false;
    if (!attrDone){
        cudaFuncSetAttribute(G_PROJ, cudaFuncAttributeMaxDynamicSharedMemorySize, S3H);
        cudaFuncSetAttribute(G_PV,   cudaFuncAttributeMaxDynamicSharedMemorySize, S3PV);
        cudaFuncSetAttribute(G_WO,   cudaFuncAttributeMaxDynamicSharedMemorySize, S3H);
        cudaFuncSetAttribute(G_FF1,  cudaFuncAttributeMaxDynamicSharedMemorySize, S3H);
        cudaFuncSetAttribute(qksoft, cudaFuncAttributeMaxDynamicSharedMemorySize, QS_SMEM);
        attrDone = true;
    }

    // ---- prepass ----
    dim3 tb(32, 8);
    wtrans8<<<dim3(16,16,8), tb>>>(Wq_s, Wk_s, Wv_s, Wo_s, Wq_c, Wk_c, Wv_c, Wo_c,
                                   p_wqs, p_wos, p_wqc, p_woc);
    ttrans<<<dim3(FF/32, CC/32), tb>>>(Wf1, p_wf1, CC, FF);
    ttrans<<<dim3(CC/32, FF/32), tb>>>(Wf2, p_wf2, FF, CC);
    f2h_kernel<<<(MROWS*CC/4+255)/256,256>>>(ca, p_ca, MROWS*CC/4);

    dim3 gQKV(QKV/128, MROWS/128, 1);
    dim3 gQc (CC/128,  MROWS/128, 1);
    dim3 gKVc(1024/128,MROWS/128, 1);
    dim3 gCC (CC/128,  MROWS/128, 1);
    dim3 gFF (FF/128,  MROWS/128, 1);
    dim3 gQS (TT/128, BATCH*NHD);
    dim3 gPV (1, TT/128, BATCH*NHD);

    const long long sTokQ = (long long)TT*QKV;
    const long long sTokC = (long long)TT*CC;
    const long long sScB  = (long long)NHD*TT*TT;
    const long long sScH  = (long long)TT*TT;

    // ===== self-attention =====
    ln_kernel<<<MROWS,128>>>(x, g1, be1, p_ln);
    G_PROJ<<<gQKV,256,S3H>>>(p_ln, CC,0,0, p_wqs, CC,0,0, nullptr,nullptr, p_qkv, QKV,0,0, CC);
    qksoft<<<gQS,256,QS_SMEM>>>(p_qkv, p_qkv + CC, sTokQ, x_m, p_sc, 1);
    G_PV<<<gPV,256,S3PV>>>(p_sc, TT, sScB, sScH, p_qkv + 1024, QKV, sTokQ, HD,
                           nullptr, nullptr, p_att, CC, sTokC, HD, TT);
    G_WO<<<gCC,256,S3H>>>(p_att, CC,0,0, p_wos, CC,0,0, bo_s, x, p_x1, CC,0,0, CC);

    // ===== cross-attention =====
    ln_kernel<<<MROWS,128>>>(p_x1, g2, be2, p_ln);
    G_PROJ<<<gQc,256,S3H>>>(p_ln, CC,0,0, p_wqc, CC,0,0, nullptr,nullptr, p_qkv, QKV,0,0, CC);
    G_PROJ<<<gKVc,256,S3H>>>(p_ca, CC,0,0, p_wqc + (size_t)CC*CC, CC,0,0, nullptr,nullptr,
                             p_qkv + CC, QKV,0,0, CC);
    qksoft<<<gQS,256,QS_SMEM>>>(p_qkv, p_qkv + CC, sTokQ, ca_m, p_sc, 0);
    G_PV<<<gPV,256,S3PV>>>(p_sc, TT, sScB, sScH, p_qkv + 1024, QKV, sTokQ, HD,
                           nullptr, nullptr, p_att, CC, sTokC, HD, TT);
    G_WO<<<gCC,256,S3H>>>(p_att, CC,0,0, p_woc, CC,0,0, bo_c, p_x1, p_x2, CC,0,0, CC);

    // ===== feed-forward =====
    ln_kernel<<<MROWS,128>>>(p_x2, g3, be3, p_ln);
    G_FF1<<<gFF,256,S3H>>>(p_ln, CC,0,0, p_wf1, CC,0,0, bf1, nullptr, p_h, FF,0,0, CC);
    G_WO <<<gCC,256,S3H>>>(p_h, FF,0,0, p_wf2, FF,0,0, bf2, p_x2, out, CC,0,0, FF);

    (void)in_sizes; (void)n_in; (void)out_size;
}

// round 8
// speedup vs baseline: 6.9704x; 1.0610x over previous
#include <cuda_runtime.h>
#include <cuda_fp16.h>
#include <cstdint>

#define BATCH 64
#define TT 256
#define CC 512
#define NHD 8
#define HD 64
#define MROWS (BATCH*TT)      // 16384
#define FF 2048
#define QKV 1536
#define ATT_SCALE 0.044194173824159216f   // 512^-0.5
#define NEGBIG (-1e9f)

// ---------------- scratch (device globals; no allocations) ----------------
__device__ __half g_ln  [MROWS*CC];
__device__ __half g_qkv [(size_t)MROWS*QKV];
__device__ __half g_att [MROWS*CC];
__device__ __half g_ca  [MROWS*CC];
__device__ __half g_h   [(size_t)MROWS*FF];
__device__ __half g_wqkvs[QKV*CC];
__device__ __half g_wqkvc[QKV*CC];
__device__ __half g_wos [CC*CC];
__device__ __half g_woc [CC*CC];
__device__ __half g_wf1t[FF*CC];
__device__ __half g_wf2t[CC*FF];
__device__ float  g_x1  [MROWS*CC];
__device__ float  g_x2  [MROWS*CC];

// ---------------- helpers ----------------
__device__ __forceinline__ void mma16(float4& d, const uint32_t* a, const uint32_t* b){
    asm volatile("mma.sync.aligned.m16n8k16.row.col.f32.f16.f16.f32 "
        "{%0,%1,%2,%3}, {%4,%5,%6,%7}, {%8,%9}, {%0,%1,%2,%3};"
        : "+f"(d.x), "+f"(d.y), "+f"(d.z), "+f"(d.w)
        : "r"(a[0]), "r"(a[1]), "r"(a[2]), "r"(a[3]), "r"(b[0]), "r"(b[1]));
}
__device__ __forceinline__ void ldsm4(uint32_t* r, uint32_t addr){
    asm volatile("ldmatrix.sync.aligned.m8n8.x4.shared.b16 {%0,%1,%2,%3}, [%4];"
        : "=r"(r[0]), "=r"(r[1]), "=r"(r[2]), "=r"(r[3]) : "r"(addr));
}
__device__ __forceinline__ void ldsm4t(uint32_t* r, uint32_t addr){
    asm volatile("ldmatrix.sync.aligned.m8n8.x4.trans.shared.b16 {%0,%1,%2,%3}, [%4];"
        : "=r"(r[0]), "=r"(r[1]), "=r"(r[2]), "=r"(r[3]) : "r"(addr));
}
__device__ __forceinline__ uint32_t h2pack(float a, float b){
    __half2 h = __floats2half2_rn(a, b);
    return *reinterpret_cast<uint32_t*>(&h);
}
#define CP16(d, s) asm volatile("cp.async.cg.shared.global [%0], [%1], 16;" :: "r"(d), "l"(s))
#define CPCOMMIT() asm volatile("cp.async.commit_group;" ::: "memory")
#define CPWAIT(n)  asm volatile("cp.async.wait_group %0;" :: "n"(n) : "memory")

__device__ __forceinline__ float warpSum(float v){
    #pragma unroll
    for (int o = 16; o; o >>= 1) v += __shfl_xor_sync(0xffffffffu, v, o);
    return v;
}

// ---------------- prepass: weight transpose -> fp16 [N][K] ----------------
__global__ void wtrans8(const float* s0, const float* s1, const float* s2, const float* s3,
                        const float* s4, const float* s5, const float* s6, const float* s7,
                        __half* qkvs, __half* wos, __half* qkvc, __half* woc)
{
    int z = blockIdx.z;
    const float* src = (z==0)?s0:(z==1)?s1:(z==2)?s2:(z==3)?s3:(z==4)?s4:(z==5)?s5:(z==6)?s6:s7;
    __half* dst = (z<3) ? qkvs + (size_t)z*CC*CC
               : (z==3) ? wos
               : (z<7) ? qkvc + (size_t)(z-4)*CC*CC
               : woc;
    __shared__ float t[32][33];
    int bx = blockIdx.x*32, by = blockIdx.y*32;
    int x = threadIdx.x, y = threadIdx.y;
    #pragma unroll
    for (int i = 0; i < 32; i += 8)
        t[y+i][x] = src[(size_t)(by + y + i)*CC + bx + x];
    __syncthreads();
    #pragma unroll
    for (int i = 0; i < 32; i += 8)
        dst[(size_t)(bx + y + i)*CC + by + x] = __float2half_rn(t[x][y+i]);
}

__global__ void ttrans(const float* __restrict__ src, __half* __restrict__ dst, int R, int C)
{
    __shared__ float t[32][33];
    int bx = blockIdx.x*32, by = blockIdx.y*32;
    int x = threadIdx.x, y = threadIdx.y;
    #pragma unroll
    for (int i = 0; i < 32; i += 8)
        t[y+i][x] = src[(size_t)(by + y + i)*C + bx + x];
    __syncthreads();
    #pragma unroll
    for (int i = 0; i < 32; i += 8)
        dst[(size_t)(bx + y + i)*R + by + x] = __float2half_rn(t[x][y+i]);
}

__global__ void f2h_kernel(const float* __restrict__ src, __half* __restrict__ dst, int n4){
    int i = blockIdx.x*256 + threadIdx.x;
    if (i < n4){
        float4 v = reinterpret_cast<const float4*>(src)[i];
        reinterpret_cast<__half2*>(dst)[2*i]   = __floats2half2_rn(v.x, v.y);
        reinterpret_cast<__half2*>(dst)[2*i+1] = __floats2half2_rn(v.z, v.w);
    }
}

// ---------------- layernorm (fp16 output) ----------------
__global__ void ln_kernel(const float* __restrict__ x, const float* __restrict__ g,
                          const float* __restrict__ be, __half* __restrict__ y)
{
    int r = blockIdx.x;
    int t = threadIdx.x;
    const float4* xr = reinterpret_cast<const float4*>(x + (size_t)r*CC);
    float4 v = xr[t];
    float s  = v.x + v.y + v.z + v.w;
    float sq = v.x*v.x + v.y*v.y + v.z*v.z + v.w*v.w;

    __shared__ float rs[4], rq[4];
    int lane = t & 31, wid = t >> 5;
    s = warpSum(s); sq = warpSum(sq);
    if (lane == 0){ rs[wid] = s; rq[wid] = sq; }
    __syncthreads();
    if (t == 0){
        float a = rs[0]+rs[1]+rs[2]+rs[3];
        float b = rq[0]+rq[1]+rq[2]+rq[3];
        rs[0] = a * (1.0f/CC);
        rq[0] = b * (1.0f/CC);
    }
    __syncthreads();
    float mu  = rs[0];
    float var = rq[0] - mu*mu;
    float rstd = rsqrtf(var + 1e-5f);

    const float4* g4  = reinterpret_cast<const float4*>(g);
    const float4* be4 = reinterpret_cast<const float4*>(be);
    float4 gg = g4[t], bb = be4[t];
    __half2 o0 = __floats2half2_rn((v.x - mu)*rstd*gg.x + bb.x, (v.y - mu)*rstd*gg.y + bb.y);
    __half2 o1 = __floats2half2_rn((v.z - mu)*rstd*gg.z + bb.z, (v.w - mu)*rstd*gg.w + bb.w);
    __half2* yh = reinterpret_cast<__half2*>(y + (size_t)r*CC);
    yh[2*t]   = o0;
    yh[2*t+1] = o1;
}

// =================== fp16 mma.sync GEMM, cp.async 3-stage + ldmatrix ===================
template<int BN, bool TRB, bool BIAS, bool RELU, bool RES, bool HOUT>
__global__ __launch_bounds__(256, 2)
void gemm_h(const __half* __restrict__ A, int lda, long long sAb, long long sAh,
            const __half* __restrict__ B, int ldb, long long sBb, long long sBh,
            const float* __restrict__ bias, const float* __restrict__ res,
            void* __restrict__ Cv, int ldc, long long sCb, long long sCh, int K)
{
    constexpr int NT   = BN/16;
    constexpr int WN   = BN/2;
    constexpr int ABYTES = 128*64;
    constexpr int BBYTES = TRB ? BN*64 : 32*128;
    constexpr int STAGE  = ABYTES + BBYTES;

    extern __shared__ char smp[];
    const uint32_t smem_base = (uint32_t)__cvta_generic_to_shared(smp);

    const int tid  = threadIdx.x;
    const int w    = tid >> 5, lane = tid & 31;
    const int g    = lane >> 2, c = lane & 3;
    const int row0 = blockIdx.y * 128;
    const int col0 = blockIdx.x * BN;
    {
        const long long zb = blockIdx.z >> 3, zh = blockIdx.z & 7;
        A += zb*sAb + zh*sAh;
        B += zb*sBb + zh*sBh;
    }
    float* Cf = (float*)Cv;
    __half* Ch = (__half*)Cv;
    {
        const long long zb = blockIdx.z >> 3, zh = blockIdx.z & 7;
        Cf += zb*sCb + zh*sCh;
        Ch += zb*sCb + zh*sCh;
    }

    float4 acc[2][NT];
    #pragma unroll
    for (int mt = 0; mt < 2; mt++)
        #pragma unroll
        for (int nt = 0; nt < NT; nt++)
            acc[mt][nt] = make_float4(0.f, 0.f, 0.f, 0.f);

    const int nch = K >> 5;
    const int mwb = (w & 3) * 32;
    const int nwb = (w >> 2) * WN;

    const int lrow = lane & 7;
    uint32_t aBase[2], aSw[2];
    const uint32_t aKc = (uint32_t)(lane >> 4);
    #pragma unroll
    for (int mt = 0; mt < 2; mt++){
        int m = mwb + mt*16 + ((lane>>3)&1)*8 + lrow;
        aBase[mt] = (uint32_t)m * 64u;
        aSw[mt]   = (uint32_t)((m>>1)&3);
    }
    uint32_t bBase[(NT+1)/2], bSw[(NT+1)/2];
    uint32_t bKc;
    if (TRB){
        bKc = (uint32_t)((lane>>3)&1);
        #pragma unroll
        for (int ng = 0; ng < NT/2; ng++){
            int n = nwb + ng*16 + (lane>>4)*8 + lrow;
            bBase[ng] = (uint32_t)n * 64u;
            bSw[ng]   = (uint32_t)((n>>1)&3);
        }
    } else {
        int kb = ((lane>>3)&1)*8 + lrow;
        bKc = (uint32_t)(kb & 7);
        #pragma unroll
        for (int ng = 0; ng < NT/2; ng++){
            int nc = (nwb>>3) + ng*2 + (lane>>4);
            bBase[ng] = (uint32_t)kb*128u + ((((uint32_t)nc ^ bKc) & 7u) << 4);
        }
    }

    #define ISSUE(ch, s) do { \
        const uint32_t sa = smem_base + (s)*STAGE; \
        const __half* Ag = A + (size_t)row0*lda + (ch)*32; \
        _Pragma("unroll") \
        for (int i = 0; i < 2; i++){ \
            int t2 = tid + 256*i; int m = t2 >> 2, c2 = t2 & 3; \
            CP16(sa + m*64 + ((c2 ^ ((m>>1)&3)) << 4), Ag + (size_t)m*lda + c2*8); \
        } \
        const uint32_t sb2 = sa + ABYTES; \
        if (TRB){ \
            const __half* Bg = B + (size_t)col0*ldb + (ch)*32; \
            _Pragma("unroll") \
            for (int i = 0; i < BN/64; i++){ \
                int t2 = tid + 256*i; int n = t2 >> 2, c2 = t2 & 3; \
                CP16(sb2 + n*64 + ((c2 ^ ((n>>1)&3)) << 4), Bg + (size_t)n*ldb + c2*8); \
            } \
        } else { \
            const __half* Bg = B + (size_t)(ch)*32*ldb + col0; \
            { \
                int k = tid >> 3, c2 = tid & 7; \
                CP16(sb2 + k*128 + ((c2 ^ (k & 7)) << 4), Bg + (size_t)k*ldb + c2*8); \
            } \
        } \
        CPCOMMIT(); \
    } while(0)

    ISSUE(0, 0);
    ISSUE(1, 1);

    for (int ch = 0; ch < nch; ch++){
        const int p = ch % 3;
        if (ch + 2 < nch) ISSUE(ch+2, (ch+2)%3); else CPCOMMIT();
        CPWAIT(2);
        __syncthreads();

        const uint32_t sA = smem_base + p*STAGE;
        const uint32_t sB = sA + ABYTES;

        #pragma unroll
        for (int ks = 0; ks < 2; ks++){
            uint32_t af[2][4], bfr[NT][2];
            #pragma unroll
            for (int mt = 0; mt < 2; mt++)
                ldsm4(af[mt], sA + aBase[mt] + ((((uint32_t)(2*ks) + aKc) ^ aSw[mt]) << 4));
            if (TRB){
                #pragma unroll
                for (int ng = 0; ng < NT/2; ng++){
                    uint32_t r[4];
                    ldsm4(r, sB + bBase[ng] + ((((uint32_t)(2*ks) + bKc) ^ bSw[ng]) << 4));
                    bfr[2*ng  ][0] = r[0]; bfr[2*ng  ][1] = r[1];
                    bfr[2*ng+1][0] = r[2]; bfr[2*ng+1][1] = r[3];
                }
            } else {
                #pragma unroll
                for (int ng = 0; ng < NT/2; ng++){
                    uint32_t r[4];
                    ldsm4t(r, sB + (uint32_t)ks*2048u + bBase[ng]);
                    bfr[2*ng  ][0] = r[0]; bfr[2*ng  ][1] = r[1];
                    bfr[2*ng+1][0] = r[2]; bfr[2*ng+1][1] = r[3];
                }
            }
            #pragma unroll
            for (int mt = 0; mt < 2; mt++)
                #pragma unroll
                for (int nt = 0; nt < NT; nt++)
                    mma16(acc[mt][nt], af[mt], bfr[nt]);
        }
        __syncthreads();
    }

    #pragma unroll
    for (int mt = 0; mt < 2; mt++){
        int r0 = row0 + mwb + mt*16 + g;
        #pragma unroll
        for (int nt = 0; nt < NT; nt++){
            int cx = col0 + nwb + nt*8 + c*2;
            float4 v = acc[mt][nt];
            if (BIAS){
                float b0 = bias[cx], b1 = bias[cx+1];
                v.x += b0; v.y += b1; v.z += b0; v.w += b1;
            }
            if (RELU){
                v.x = fmaxf(v.x, 0.f); v.y = fmaxf(v.y, 0.f);
                v.z = fmaxf(v.z, 0.f); v.w = fmaxf(v.w, 0.f);
            }
            if (RES){
                float2 r1 = *reinterpret_cast<const float2*>(&res[(size_t)r0*ldc + cx]);
                float2 r2 = *reinterpret_cast<const float2*>(&res[(size_t)(r0+8)*ldc + cx]);
                v.x += r1.x; v.y += r1.y; v.z += r2.x; v.w += r2.y;
            }
            if (HOUT){
                *reinterpret_cast<__half2*>(&Ch[(size_t)r0*ldc + cx])     = __floats2half2_rn(v.x, v.y);
                *reinterpret_cast<__half2*>(&Ch[(size_t)(r0+8)*ldc + cx]) = __floats2half2_rn(v.z, v.w);
            } else {
                *reinterpret_cast<float2*>(&Cf[(size_t)r0*ldc + cx])     = make_float2(v.x, v.y);
                *reinterpret_cast<float2*>(&Cf[(size_t)(r0+8)*ldc + cx]) = make_float2(v.z, v.w);
            }
        }
    }
    #undef ISSUE
}

// =================== fused attention: QK^T + mask + softmax + P@V ===================
// One CTA: 128 q-rows x 256 k x 64 d for one (b,h). grid (TT/128, BATCH*NHD).
#define AT_STAGE (128*64 + 256*64)              // QK: A 8KB + B 16KB
#define AT_OFF_V (2*AT_STAGE)                   // V tile 256x64 fp16 = 32KB
#define AT_OFF_R (AT_OFF_V + 256*128)           // reductions: 2KB
#define AT_SMEM  (AT_OFF_R + 2048)              // 83968; partial-sum aliases [0,33.8KB)
__global__ __launch_bounds__(256, 1)
void attn(const __half* __restrict__ Q, const __half* __restrict__ Kmat,
          const __half* __restrict__ V, long long sTok,
          const int* __restrict__ mask, __half* __restrict__ O, int causal)
{
    constexpr int NT = 16;
    extern __shared__ char smp[];
    const uint32_t smem_base = (uint32_t)__cvta_generic_to_shared(smp);

    const int tid  = threadIdx.x;
    const int w    = tid >> 5, lane = tid & 31;
    const int g    = lane >> 2, c = lane & 3;
    const int row0 = blockIdx.x * 128;
    {
        const long long zb = blockIdx.y >> 3, zh = blockIdx.y & 7;
        Q    += zb*sTok + zh*HD;
        Kmat += zb*sTok + zh*HD;
        V    += zb*sTok + zh*HD;
        mask += zb*(long long)TT*TT;
        O    += zb*(long long)TT*CC + zh*HD;
    }

    float4 acc[2][NT];
    #pragma unroll
    for (int mt = 0; mt < 2; mt++)
        #pragma unroll
        for (int nt = 0; nt < NT; nt++)
            acc[mt][nt] = make_float4(0.f, 0.f, 0.f, 0.f);

    const int mwb = (w & 3) * 32;
    const int nwb = (w >> 2) * 128;

    const int lrow = lane & 7;
    uint32_t aBase[2], aSw[2];
    const uint32_t aKc = (uint32_t)(lane >> 4);
    #pragma unroll
    for (int mt = 0; mt < 2; mt++){
        int m = mwb + mt*16 + ((lane>>3)&1)*8 + lrow;
        aBase[mt] = (uint32_t)m * 64u;
        aSw[mt]   = (uint32_t)((m>>1)&3);
    }
    uint32_t bBase[8], bSw[8];
    const uint32_t bKc = (uint32_t)((lane>>3)&1);
    #pragma unroll
    for (int ng = 0; ng < 8; ng++){
        int n = nwb + ng*16 + (lane>>4)*8 + lrow;
        bBase[ng] = (uint32_t)n * 64u;
        bSw[ng]   = (uint32_t)((n>>1)&3);
    }

    #define QISSUE(ch, s) do { \
        const uint32_t sa = smem_base + (s)*AT_STAGE; \
        const __half* Ag = Q + (size_t)row0*sTokLd + (ch)*32; \
        _Pragma("unroll") \
        for (int i = 0; i < 2; i++){ \
            int t2 = tid + 256*i; int m = t2 >> 2, c2 = t2 & 3; \
            CP16(sa + m*64 + ((c2 ^ ((m>>1)&3)) << 4), Ag + (size_t)m*sTokLd + c2*8); \
        } \
        const uint32_t sb2 = sa + 128*64; \
        const __half* Bg = Kmat + (ch)*32; \
        _Pragma("unroll") \
        for (int i = 0; i < 4; i++){ \
            int t2 = tid + 256*i; int n = t2 >> 2, c2 = t2 & 3; \
            CP16(sb2 + n*64 + ((c2 ^ ((n>>1)&3)) << 4), Bg + (size_t)n*sTokLd + c2*8); \
        } \
        CPCOMMIT(); \
    } while(0)

    const int sTokLd = QKV;  // row stride of q/k/v within the fused qkv buffer

    QISSUE(0, 0);
    // ---- V load (own commit group, overlapped with QK mainloop) ----
    {
        #pragma unroll
        for (int i = 0; i < 8; i++){
            int idx = tid + 256*i;
            int t2 = idx >> 3, c2 = idx & 7;
            CP16(smem_base + AT_OFF_V + t2*128 + ((c2 ^ (t2 & 7)) << 4),
                 V + (size_t)t2*sTokLd + c2*8);
        }
        CPCOMMIT();
    }
    QISSUE(1, 1);

    #pragma unroll
    for (int ch = 0; ch < 2; ch++){
        if (ch == 0) CPWAIT(2); else CPWAIT(0);
        __syncthreads();
        const uint32_t sA = smem_base + ch*AT_STAGE;
        const uint32_t sB = sA + 128*64;
        #pragma unroll
        for (int ks = 0; ks < 2; ks++){
            uint32_t af[2][4], bfr[NT][2];
            #pragma unroll
            for (int mt = 0; mt < 2; mt++)
                ldsm4(af[mt], sA + aBase[mt] + ((((uint32_t)(2*ks) + aKc) ^ aSw[mt]) << 4));
            #pragma unroll
            for (int ng = 0; ng < 8; ng++){
                uint32_t r[4];
                ldsm4(r, sB + bBase[ng] + ((((uint32_t)(2*ks) + bKc) ^ bSw[ng]) << 4));
                bfr[2*ng  ][0] = r[0]; bfr[2*ng  ][1] = r[1];
                bfr[2*ng+1][0] = r[2]; bfr[2*ng+1][1] = r[3];
            }
            #pragma unroll
            for (int mt = 0; mt < 2; mt++)
                #pragma unroll
                for (int nt = 0; nt < NT; nt++)
                    mma16(acc[mt][nt], af[mt], bfr[nt]);
        }
        __syncthreads();
    }
    #undef QISSUE

    // ---- softmax (registers + 2KB smem reductions) ----
    float* redm = reinterpret_cast<float*>(smp + AT_OFF_R);   // [2][128]
    float* reds = redm + 256;

    float rmax[4] = {-3.4e38f, -3.4e38f, -3.4e38f, -3.4e38f};
    #pragma unroll
    for (int mt = 0; mt < 2; mt++){
        const int qi0 = row0 + mwb + mt*16 + g;
        const int qi1 = qi0 + 8;
        #pragma unroll
        for (int nt = 0; nt < NT; nt++){
            const int cx = nwb + nt*8 + c*2;
            float4 v = acc[mt][nt];
            v.x *= ATT_SCALE; v.y *= ATT_SCALE; v.z *= ATT_SCALE; v.w *= ATT_SCALE;
            int2 m0 = *reinterpret_cast<const int2*>(&mask[(size_t)qi0*TT + cx]);
            int2 m1 = *reinterpret_cast<const int2*>(&mask[(size_t)qi1*TT + cx]);
            bool okx = m0.x && (!causal || cx   <= qi0);
            bool oky = m0.y && (!causal || cx+1 <= qi0);
            bool okz = m1.x && (!causal || cx   <= qi1);
            bool okw = m1.y && (!causal || cx+1 <= qi1);
            v.x = okx ? v.x : NEGBIG;
            v.y = oky ? v.y : NEGBIG;
            v.z = okz ? v.z : NEGBIG;
            v.w = okw ? v.w : NEGBIG;
            acc[mt][nt] = v;
            rmax[mt*2+0] = fmaxf(rmax[mt*2+0], fmaxf(v.x, v.y));
            rmax[mt*2+1] = fmaxf(rmax[mt*2+1], fmaxf(v.z, v.w));
        }
    }
    #pragma unroll
    for (int h = 0; h < 4; h++){
        rmax[h] = fmaxf(rmax[h], __shfl_xor_sync(0xffffffffu, rmax[h], 1));
        rmax[h] = fmaxf(rmax[h], __shfl_xor_sync(0xffffffffu, rmax[h], 2));
    }
    const int half_ = w >> 2;
    if (c == 0){
        redm[half_*128 + mwb      + g] = rmax[0];
        redm[half_*128 + mwb +  8 + g] = rmax[1];
        redm[half_*128 + mwb + 16 + g] = rmax[2];
        redm[half_*128 + mwb + 24 + g] = rmax[3];
    }
    __syncthreads();
    float M[4];
    M[0] = fmaxf(redm[mwb      + g], redm[128 + mwb      + g]);
    M[1] = fmaxf(redm[mwb +  8 + g], redm[128 + mwb +  8 + g]);
    M[2] = fmaxf(redm[mwb + 16 + g], redm[128 + mwb + 16 + g]);
    M[3] = fmaxf(redm[mwb + 24 + g], redm[128 + mwb + 24 + g]);

    float rsum[4] = {0.f, 0.f, 0.f, 0.f};
    #pragma unroll
    for (int mt = 0; mt < 2; mt++){
        #pragma unroll
        for (int nt = 0; nt < NT; nt++){
            float4 v = acc[mt][nt];
            v.x = __expf(v.x - M[mt*2+0]);
            v.y = __expf(v.y - M[mt*2+0]);
            v.z = __expf(v.z - M[mt*2+1]);
            v.w = __expf(v.w - M[mt*2+1]);
            acc[mt][nt] = v;
            rsum[mt*2+0] += v.x + v.y;
            rsum[mt*2+1] += v.z + v.w;
        }
    }
    #pragma unroll
    for (int h = 0; h < 4; h++){
        rsum[h] += __shfl_xor_sync(0xffffffffu, rsum[h], 1);
        rsum[h] += __shfl_xor_sync(0xffffffffu, rsum[h], 2);
    }
    if (c == 0){
        reds[half_*128 + mwb      + g] = rsum[0];
        reds[half_*128 + mwb +  8 + g] = rsum[1];
        reds[half_*128 + mwb + 16 + g] = rsum[2];
        reds[half_*128 + mwb + 24 + g] = rsum[3];
    }
    __syncthreads();
    float inv[4];
    inv[0] = 1.f / (reds[mwb      + g] + reds[128 + mwb      + g]);
    inv[1] = 1.f / (reds[mwb +  8 + g] + reds[128 + mwb +  8 + g]);
    inv[2] = 1.f / (reds[mwb + 16 + g] + reds[128 + mwb + 16 + g]);
    inv[3] = 1.f / (reds[mwb + 24 + g] + reds[128 + mwb + 24 + g]);

    // ---- convert P -> a-fragments (d-reg layout == a-frag layout) ----
    uint32_t pa[2][8][4];
    #pragma unroll
    for (int mt = 0; mt < 2; mt++){
        const float i0 = inv[mt*2+0], i1 = inv[mt*2+1];
        #pragma unroll
        for (int j = 0; j < 8; j++){
            float4 v0 = acc[mt][2*j], v1 = acc[mt][2*j+1];
            pa[mt][j][0] = h2pack(v0.x * i0, v0.y * i0);
            pa[mt][j][1] = h2pack(v0.z * i1, v0.w * i1);
            pa[mt][j][2] = h2pack(v1.x * i0, v1.y * i0);
            pa[mt][j][3] = h2pack(v1.z * i1, v1.w * i1);
        }
    }

    // ---- P @ V over this warp's 128-k half ----
    float4 accO[2][8];
    #pragma unroll
    for (int mt = 0; mt < 2; mt++)
        #pragma unroll
        for (int nt = 0; nt < 8; nt++)
            accO[mt][nt] = make_float4(0.f, 0.f, 0.f, 0.f);

    const int kb = ((lane>>3)&1)*8 + lrow;
    uint32_t vb[4];
    #pragma unroll
    for (int ng = 0; ng < 4; ng++){
        int nc = ng*2 + (lane>>4);
        vb[ng] = AT_OFF_V + (uint32_t)(nwb + kb)*128u + ((((uint32_t)nc ^ (uint32_t)(kb & 7)) & 7u) << 4);
    }
    #pragma unroll
    for (int j = 0; j < 8; j++){
        uint32_t bfr[8][2];
        #pragma unroll
        for (int ng = 0; ng < 4; ng++){
            uint32_t r[4];
            ldsm4t(r, smem_base + vb[ng] + (uint32_t)j*2048u);
            bfr[2*ng  ][0] = r[0]; bfr[2*ng  ][1] = r[1];
            bfr[2*ng+1][0] = r[2]; bfr[2*ng+1][1] = r[3];
        }
        #pragma unroll
        for (int mt = 0; mt < 2; mt++)
            #pragma unroll
            for (int nt = 0; nt < 8; nt++)
                mma16(accO[mt][nt], pa[mt][j], bfr[nt]);
    }

    // ---- cross-half reduction via smem (partial buffer aliases QK stages) ----
    float* ps = reinterpret_cast<float*>(smp);    // [128][66]
    if (half_ == 1){
        #pragma unroll
        for (int mt = 0; mt < 2; mt++){
            int rl = mwb + mt*16 + g;
            #pragma unroll
            for (int nt = 0; nt < 8; nt++){
                int cl = nt*8 + c*2;
                float4 v = accO[mt][nt];
                *reinterpret_cast<float2*>(&ps[(size_t)rl*66 + cl])     = make_float2(v.x, v.y);
                *reinterpret_cast<float2*>(&ps[(size_t)(rl+8)*66 + cl]) = make_float2(v.z, v.w);
            }
        }
    }
    __syncthreads();
    if (half_ == 0){
        #pragma unroll
        for (int mt = 0; mt < 2; mt++){
            int rl = mwb + mt*16 + g;
            #pragma unroll
            for (int nt = 0; nt < 8; nt++){
                int cl = nt*8 + c*2;
                float4 v = accO[mt][nt];
                float2 p0 = *reinterpret_cast<float2*>(&ps[(size_t)rl*66 + cl]);
                float2 p1 = *reinterpret_cast<float2*>(&ps[(size_t)(rl+8)*66 + cl]);
                *reinterpret_cast<__half2*>(&O[(size_t)(row0+rl)*CC + cl]) =
                    __floats2half2_rn(v.x + p0.x, v.y + p0.y);
                *reinterpret_cast<__half2*>(&O[(size_t)(row0+rl+8)*CC + cl]) =
                    __floats2half2_rn(v.z + p1.x, v.w + p1.y);
            }
        }
    }
}

// ---------------- host orchestration ----------------
template<typename T>
static T* symaddr(const void* sym){
    void* p = nullptr;
    cudaGetSymbolAddress(&p, sym);
    return (T*)p;
}

#define S3H  (3*(128*64 + 128*64))    // 49152

#define G_PROJ gemm_h<128,true ,false,false,false,true >
#define G_WO   gemm_h<128,true ,true ,false,true ,false>
#define G_FF1  gemm_h<128,true ,true ,true ,false,true >

extern "C" void kernel_launch(void* const* d_in, const int* in_sizes, int n_in,
                              void* d_out, int out_size)
{
    const float* x    = (const float*)d_in[0];
    const float* ca   = (const float*)d_in[1];
    const int*   x_m  = (const int*)  d_in[2];
    const int*   ca_m = (const int*)  d_in[3];
    const float* Wq_s = (const float*)d_in[4];
    const float* Wk_s = (const float*)d_in[5];
    const float* Wv_s = (const float*)d_in[6];
    const float* Wo_s = (const float*)d_in[7];
    const float* bo_s = (const float*)d_in[8];
    const float* Wq_c = (const float*)d_in[9];
    const float* Wk_c = (const float*)d_in[10];
    const float* Wv_c = (const float*)d_in[11];
    const float* Wo_c = (const float*)d_in[12];
    const float* bo_c = (const float*)d_in[13];
    const float* g1   = (const float*)d_in[14];
    const float* be1  = (const float*)d_in[15];
    const float* g2   = (const float*)d_in[16];
    const float* be2  = (const float*)d_in[17];
    const float* g3   = (const float*)d_in[18];
    const float* be3  = (const float*)d_in[19];
    const float* Wf1  = (const float*)d_in[20];
    const float* bf1  = (const float*)d_in[21];
    const float* Wf2  = (const float*)d_in[22];
    const float* bf2  = (const float*)d_in[23];
    float* out = (float*)d_out;

    __half* p_ln  = symaddr<__half>(g_ln);
    __half* p_qkv = symaddr<__half>(g_qkv);
    __half* p_att = symaddr<__half>(g_att);
    __half* p_ca  = symaddr<__half>(g_ca);
    __half* p_h   = symaddr<__half>(g_h);
    __half* p_wqs = symaddr<__half>(g_wqkvs);
    __half* p_wqc = symaddr<__half>(g_wqkvc);
    __half* p_wos = symaddr<__half>(g_wos);
    __half* p_woc = symaddr<__half>(g_woc);
    __half* p_wf1 = symaddr<__half>(g_wf1t);
    __half* p_wf2 = symaddr<__half>(g_wf2t);
    float*  p_x1  = symaddr<float>(g_x1);
    float*  p_x2  = symaddr<float>(g_x2);

    static bool attrDone = false;
    if (!attrDone){
        cudaFuncSetAttribute(G_PROJ, cudaFuncAttributeMaxDynamicSharedMemorySize, S3H);
        cudaFuncSetAttribute(G_WO,   cudaFuncAttributeMaxDynamicSharedMemorySize, S3H);
        cudaFuncSetAttribute(G_FF1,  cudaFuncAttributeMaxDynamicSharedMemorySize, S3H);
        cudaFuncSetAttribute(attn,   cudaFuncAttributeMaxDynamicSharedMemorySize, AT_SMEM);
        attrDone = true;
    }

    // ---- prepass ----
    dim3 tb(32, 8);
    wtrans8<<<dim3(16,16,8), tb>>>(Wq_s, Wk_s, Wv_s, Wo_s, Wq_c, Wk_c, Wv_c, Wo_c,
                                   p_wqs, p_wos, p_wqc, p_woc);
    ttrans<<<dim3(FF/32, CC/32), tb>>>(Wf1, p_wf1, CC, FF);
    ttrans<<<dim3(CC/32, FF/32), tb>>>(Wf2, p_wf2, FF, CC);
    f2h_kernel<<<(MROWS*CC/4+255)/256,256>>>(ca, p_ca, MROWS*CC/4);

    dim3 gQKV(QKV/128, MROWS/128, 1);
    dim3 gQc (CC/128,  MROWS/128, 1);
    dim3 gKVc(1024/128,MROWS/128, 1);
    dim3 gCC (CC/128,  MROWS/128, 1);
    dim3 gFF (FF/128,  MROWS/128, 1);
    dim3 gAT (TT/128, BATCH*NHD);

    const long long sTokQ = (long long)TT*QKV;
    const long long sTokC = (long long)TT*CC;

    // ===== self-attention =====
    ln_kernel<<<MROWS,128>>>(x, g1, be1, p_ln);
    G_PROJ<<<gQKV,256,S3H>>>(p_ln, CC,0,0, p_wqs, CC,0,0, nullptr,nullptr, p_qkv, QKV,0,0, CC);
    attn<<<gAT,256,AT_SMEM>>>(p_qkv, p_qkv + CC, p_qkv + 1024, sTokQ, x_m, p_att, 1);
    G_WO<<<gCC,256,S3H>>>(p_att, CC,0,0, p_wos, CC,0,0, bo_s, x, p_x1, CC,0,0, CC);

    // ===== cross-attention =====
    ln_kernel<<<MROWS,128>>>(p_x1, g2, be2, p_ln);
    G_PROJ<<<gQc,256,S3H>>>(p_ln, CC,0,0, p_wqc, CC,0,0, nullptr,nullptr, p_qkv, QKV,0,0, CC);
    G_PROJ<<<gKVc,256,S3H>>>(p_ca, CC,0,0, p_wqc + (size_t)CC*CC, CC,0,0, nullptr,nullptr,
                             p_qkv + CC, QKV,0,0, CC);
    attn<<<gAT,256,AT_SMEM>>>(p_qkv, p_qkv + CC, p_qkv + 1024, sTokQ, ca_m, p_att, 0);
    G_WO<<<gCC,256,S3H>>>(p_att, CC,0,0, p_woc, CC,0,0, bo_c, p_x1, p_x2, CC,0,0, CC);

    // ===== feed-forward =====
    ln_kernel<<<MROWS,128>>>(p_x2, g3, be3, p_ln);
    G_FF1<<<gFF,256,S3H>>>(p_ln, CC,0,0, p_wf1, CC,0,0, bf1, nullptr, p_h, FF,0,0, CC);
    G_WO <<<gCC,256,S3H>>>(p_h, FF,0,0, p_wf2, FF,0,0, bf2, p_x2, out, CC,0,0, FF);

    (void)in_sizes; (void)n_in; (void)out_size;
}

// round 9
// speedup vs baseline: 7.2802x; 1.0444x over previous
#include <cuda_runtime.h>
#include <cuda_fp16.h>
#include <cstdint>

#define BATCH 64
#define TT 256
#define CC 512
#define NHD 8
#define HD 64
#define MROWS (BATCH*TT)      // 16384
#define FF 2048
#define QKV 1536
#define ATT_SCALE 0.044194173824159216f   // 512^-0.5
#define NEGBIG (-1e9f)

// ---------------- scratch (device globals; no allocations) ----------------
__device__ __half g_ln  [MROWS*CC];
__device__ __half g_qkv [(size_t)MROWS*QKV];
__device__ __half g_att [MROWS*CC];
__device__ __half g_ca  [MROWS*CC];
__device__ __half g_h   [(size_t)MROWS*FF];
__device__ __half g_wqkvs[QKV*CC];
__device__ __half g_wqkvc[QKV*CC];
__device__ __half g_wos [CC*CC];
__device__ __half g_woc [CC*CC];
__device__ __half g_wf1t[FF*CC];
__device__ __half g_wf2t[CC*FF];
__device__ float  g_x1  [MROWS*CC];
__device__ float  g_x2  [MROWS*CC];

// ---------------- helpers ----------------
__device__ __forceinline__ void mma16(float4& d, const uint32_t* a, const uint32_t* b){
    asm volatile("mma.sync.aligned.m16n8k16.row.col.f32.f16.f16.f32 "
        "{%0,%1,%2,%3}, {%4,%5,%6,%7}, {%8,%9}, {%0,%1,%2,%3};"
        : "+f"(d.x), "+f"(d.y), "+f"(d.z), "+f"(d.w)
        : "r"(a[0]), "r"(a[1]), "r"(a[2]), "r"(a[3]), "r"(b[0]), "r"(b[1]));
}
__device__ __forceinline__ void ldsm4(uint32_t* r, uint32_t addr){
    asm volatile("ldmatrix.sync.aligned.m8n8.x4.shared.b16 {%0,%1,%2,%3}, [%4];"
        : "=r"(r[0]), "=r"(r[1]), "=r"(r[2]), "=r"(r[3]) : "r"(addr));
}
__device__ __forceinline__ void ldsm4t(uint32_t* r, uint32_t addr){
    asm volatile("ldmatrix.sync.aligned.m8n8.x4.trans.shared.b16 {%0,%1,%2,%3}, [%4];"
        : "=r"(r[0]), "=r"(r[1]), "=r"(r[2]), "=r"(r[3]) : "r"(addr));
}
__device__ __forceinline__ uint32_t h2pack(float a, float b){
    __half2 h = __floats2half2_rn(a, b);
    return *reinterpret_cast<uint32_t*>(&h);
}
#define CP16(d, s) asm volatile("cp.async.cg.shared.global [%0], [%1], 16;" :: "r"(d), "l"(s))
#define CPCOMMIT() asm volatile("cp.async.commit_group;" ::: "memory")
#define CPWAIT(n)  asm volatile("cp.async.wait_group %0;" :: "n"(n) : "memory")

__device__ __forceinline__ float warpSum(float v){
    #pragma unroll
    for (int o = 16; o; o >>= 1) v += __shfl_xor_sync(0xffffffffu, v, o);
    return v;
}

// ---------------- prepass: weight transpose -> fp16 [N][K] ----------------
__global__ void wtrans8(const float* s0, const float* s1, const float* s2, const float* s3,
                        const float* s4, const float* s5, const float* s6, const float* s7,
                        __half* qkvs, __half* wos, __half* qkvc, __half* woc)
{
    int z = blockIdx.z;
    const float* src = (z==0)?s0:(z==1)?s1:(z==2)?s2:(z==3)?s3:(z==4)?s4:(z==5)?s5:(z==6)?s6:s7;
    __half* dst = (z<3) ? qkvs + (size_t)z*CC*CC
               : (z==3) ? wos
               : (z<7) ? qkvc + (size_t)(z-4)*CC*CC
               : woc;
    __shared__ float t[32][33];
    int bx = blockIdx.x*32, by = blockIdx.y*32;
    int x = threadIdx.x, y = threadIdx.y;
    #pragma unroll
    for (int i = 0; i < 32; i += 8)
        t[y+i][x] = src[(size_t)(by + y + i)*CC + bx + x];
    __syncthreads();
    #pragma unroll
    for (int i = 0; i < 32; i += 8)
        dst[(size_t)(bx + y + i)*CC + by + x] = __float2half_rn(t[x][y+i]);
}

__global__ void ttrans(const float* __restrict__ src, __half* __restrict__ dst, int R, int C)
{
    __shared__ float t[32][33];
    int bx = blockIdx.x*32, by = blockIdx.y*32;
    int x = threadIdx.x, y = threadIdx.y;
    #pragma unroll
    for (int i = 0; i < 32; i += 8)
        t[y+i][x] = src[(size_t)(by + y + i)*C + bx + x];
    __syncthreads();
    #pragma unroll
    for (int i = 0; i < 32; i += 8)
        dst[(size_t)(bx + y + i)*R + by + x] = __float2half_rn(t[x][y+i]);
}

__global__ void f2h_kernel(const float* __restrict__ src, __half* __restrict__ dst, int n4){
    int i = blockIdx.x*256 + threadIdx.x;
    if (i < n4){
        float4 v = reinterpret_cast<const float4*>(src)[i];
        reinterpret_cast<__half2*>(dst)[2*i]   = __floats2half2_rn(v.x, v.y);
        reinterpret_cast<__half2*>(dst)[2*i+1] = __floats2half2_rn(v.z, v.w);
    }
}

// ---------------- layernorm (fp16 output) ----------------
__global__ void ln_kernel(const float* __restrict__ x, const float* __restrict__ g,
                          const float* __restrict__ be, __half* __restrict__ y)
{
    int r = blockIdx.x;
    int t = threadIdx.x;
    const float4* xr = reinterpret_cast<const float4*>(x + (size_t)r*CC);
    float4 v = xr[t];
    float s  = v.x + v.y + v.z + v.w;
    float sq = v.x*v.x + v.y*v.y + v.z*v.z + v.w*v.w;

    __shared__ float rs[4], rq[4];
    int lane = t & 31, wid = t >> 5;
    s = warpSum(s); sq = warpSum(sq);
    if (lane == 0){ rs[wid] = s; rq[wid] = sq; }
    __syncthreads();
    if (t == 0){
        float a = rs[0]+rs[1]+rs[2]+rs[3];
        float b = rq[0]+rq[1]+rq[2]+rq[3];
        rs[0] = a * (1.0f/CC);
        rq[0] = b * (1.0f/CC);
    }
    __syncthreads();
    float mu  = rs[0];
    float var = rq[0] - mu*mu;
    float rstd = rsqrtf(var + 1e-5f);

    const float4* g4  = reinterpret_cast<const float4*>(g);
    const float4* be4 = reinterpret_cast<const float4*>(be);
    float4 gg = g4[t], bb = be4[t];
    __half2 o0 = __floats2half2_rn((v.x - mu)*rstd*gg.x + bb.x, (v.y - mu)*rstd*gg.y + bb.y);
    __half2 o1 = __floats2half2_rn((v.z - mu)*rstd*gg.z + bb.z, (v.w - mu)*rstd*gg.w + bb.w);
    __half2* yh = reinterpret_cast<__half2*>(y + (size_t)r*CC);
    yh[2*t]   = o0;
    yh[2*t+1] = o1;
}

// =================== fp16 mma.sync GEMM: BK=64, TRB only, BN=128 ===================
// A[M,K] fp16 row-major; B fp16 [N][K]. BM=128, BN=128. 256 thr = 8 warps (4M x 2N).
// Stage: A 16KB + B 16KB (128B rows, swizzle chunk ^ (row&7)). 3 stages = 96KB.
template<bool BIAS, bool RELU, bool RES, bool HOUT>
__global__ __launch_bounds__(256, 2)
void gemm_h(const __half* __restrict__ A, int lda,
            const __half* __restrict__ B, int ldb,
            const float* __restrict__ bias, const float* __restrict__ res,
            void* __restrict__ Cv, int ldc, int K)
{
    constexpr int NT = 8;
    constexpr int ABYTES = 128*128;     // 16 KB
    constexpr int STAGE  = 2*ABYTES;    // 32 KB

    extern __shared__ char smp[];
    const uint32_t smem_base = (uint32_t)__cvta_generic_to_shared(smp);

    const int tid  = threadIdx.x;
    const int w    = tid >> 5, lane = tid & 31;
    const int g    = lane >> 2, c = lane & 3;
    const int row0 = blockIdx.y * 128;
    const int col0 = blockIdx.x * 128;

    float* Cf = (float*)Cv;
    __half* Ch = (__half*)Cv;

    float4 acc[2][NT];
    #pragma unroll
    for (int mt = 0; mt < 2; mt++)
        #pragma unroll
        for (int nt = 0; nt < NT; nt++)
            acc[mt][nt] = make_float4(0.f, 0.f, 0.f, 0.f);

    const int nch = K >> 6;
    const int mwb = (w & 3) * 32;
    const int nwb = (w >> 2) * 64;

    const int lrow = lane & 7;
    uint32_t aBase[2], aSw[2];
    const uint32_t aKc = (uint32_t)(lane >> 4);          // 0/1: k-chunk parity
    #pragma unroll
    for (int mt = 0; mt < 2; mt++){
        int m = mwb + mt*16 + ((lane>>3)&1)*8 + lrow;
        aBase[mt] = (uint32_t)m * 128u;
        aSw[mt]   = (uint32_t)(m & 7);
    }
    uint32_t bBase[NT/2], bSw[NT/2];
    const uint32_t bKc = (uint32_t)((lane>>3)&1);
    #pragma unroll
    for (int ng = 0; ng < NT/2; ng++){
        int n = nwb + ng*16 + (lane>>4)*8 + lrow;
        bBase[ng] = (uint32_t)n * 128u;
        bSw[ng]   = (uint32_t)(n & 7);
    }

    #define ISSUE(ch, s) do { \
        const uint32_t sa = smem_base + (s)*STAGE; \
        const __half* Ag = A + (size_t)row0*lda + (ch)*64; \
        _Pragma("unroll") \
        for (int i = 0; i < 4; i++){ \
            int t2 = tid + 256*i; int m = t2 >> 3, c2 = t2 & 7; \
            CP16(sa + m*128 + ((c2 ^ (m & 7)) << 4), Ag + (size_t)m*lda + c2*8); \
        } \
        const uint32_t sb2 = sa + ABYTES; \
        const __half* Bg = B + (size_t)col0*ldb + (ch)*64; \
        _Pragma("unroll") \
        for (int i = 0; i < 4; i++){ \
            int t2 = tid + 256*i; int n = t2 >> 3, c2 = t2 & 7; \
            CP16(sb2 + n*128 + ((c2 ^ (n & 7)) << 4), Bg + (size_t)n*ldb + c2*8); \
        } \
        CPCOMMIT(); \
    } while(0)

    ISSUE(0, 0);
    ISSUE(1, 1);

    for (int ch = 0; ch < nch; ch++){
        const int p = ch % 3;
        if (ch + 2 < nch) ISSUE(ch+2, (ch+2)%3); else CPCOMMIT();
        CPWAIT(2);
        __syncthreads();

        const uint32_t sA = smem_base + p*STAGE;
        const uint32_t sB = sA + ABYTES;

        #pragma unroll
        for (int ks = 0; ks < 4; ks++){
            uint32_t af[2][4], bfr[NT][2];
            #pragma unroll
            for (int mt = 0; mt < 2; mt++)
                ldsm4(af[mt], sA + aBase[mt] + ((((uint32_t)(2*ks) + aKc) ^ aSw[mt]) << 4));
            #pragma unroll
            for (int ng = 0; ng < NT/2; ng++){
                uint32_t r[4];
                ldsm4(r, sB + bBase[ng] + ((((uint32_t)(2*ks) + bKc) ^ bSw[ng]) << 4));
                bfr[2*ng  ][0] = r[0]; bfr[2*ng  ][1] = r[1];
                bfr[2*ng+1][0] = r[2]; bfr[2*ng+1][1] = r[3];
            }
            #pragma unroll
            for (int mt = 0; mt < 2; mt++)
                #pragma unroll
                for (int nt = 0; nt < NT; nt++)
                    mma16(acc[mt][nt], af[mt], bfr[nt]);
        }
        __syncthreads();
    }

    #pragma unroll
    for (int mt = 0; mt < 2; mt++){
        int r0 = row0 + mwb + mt*16 + g;
        #pragma unroll
        for (int nt = 0; nt < NT; nt++){
            int cx = col0 + nwb + nt*8 + c*2;
            float4 v = acc[mt][nt];
            if (BIAS){
                float b0 = bias[cx], b1 = bias[cx+1];
                v.x += b0; v.y += b1; v.z += b0; v.w += b1;
            }
            if (RELU){
                v.x = fmaxf(v.x, 0.f); v.y = fmaxf(v.y, 0.f);
                v.z = fmaxf(v.z, 0.f); v.w = fmaxf(v.w, 0.f);
            }
            if (RES){
                float2 r1 = *reinterpret_cast<const float2*>(&res[(size_t)r0*ldc + cx]);
                float2 r2 = *reinterpret_cast<const float2*>(&res[(size_t)(r0+8)*ldc + cx]);
                v.x += r1.x; v.y += r1.y; v.z += r2.x; v.w += r2.y;
            }
            if (HOUT){
                *reinterpret_cast<__half2*>(&Ch[(size_t)r0*ldc + cx])     = __floats2half2_rn(v.x, v.y);
                *reinterpret_cast<__half2*>(&Ch[(size_t)(r0+8)*ldc + cx]) = __floats2half2_rn(v.z, v.w);
            } else {
                *reinterpret_cast<float2*>(&Cf[(size_t)r0*ldc + cx])     = make_float2(v.x, v.y);
                *reinterpret_cast<float2*>(&Cf[(size_t)(r0+8)*ldc + cx]) = make_float2(v.z, v.w);
            }
        }
    }
    #undef ISSUE
}

// =================== fused attention: QK^T + mask + softmax + P@V ===================
#define AT_STAGE (128*64 + 256*64)              // QK: A 8KB + B 16KB
#define AT_OFF_V (2*AT_STAGE)                   // V tile 256x64 fp16 = 32KB
#define AT_OFF_R (AT_OFF_V + 256*128)           // reductions: 2KB
#define AT_SMEM  (AT_OFF_R + 2048)
__global__ __launch_bounds__(256, 1)
void attn(const __half* __restrict__ Q, const __half* __restrict__ Kmat,
          const __half* __restrict__ V, long long sTok,
          const int* __restrict__ mask, __half* __restrict__ O, int causal)
{
    constexpr int NT = 16;
    extern __shared__ char smp[];
    const uint32_t smem_base = (uint32_t)__cvta_generic_to_shared(smp);

    const int tid  = threadIdx.x;
    const int w    = tid >> 5, lane = tid & 31;
    const int g    = lane >> 2, c = lane & 3;
    const int row0 = blockIdx.x * 128;
    {
        const long long zb = blockIdx.y >> 3, zh = blockIdx.y & 7;
        Q    += zb*sTok + zh*HD;
        Kmat += zb*sTok + zh*HD;
        V    += zb*sTok + zh*HD;
        mask += zb*(long long)TT*TT;
        O    += zb*(long long)TT*CC + zh*HD;
    }

    float4 acc[2][NT];
    #pragma unroll
    for (int mt = 0; mt < 2; mt++)
        #pragma unroll
        for (int nt = 0; nt < NT; nt++)
            acc[mt][nt] = make_float4(0.f, 0.f, 0.f, 0.f);

    const int mwb = (w & 3) * 32;
    const int nwb = (w >> 2) * 128;

    const int lrow = lane & 7;
    uint32_t aBase[2], aSw[2];
    const uint32_t aKc = (uint32_t)(lane >> 4);
    #pragma unroll
    for (int mt = 0; mt < 2; mt++){
        int m = mwb + mt*16 + ((lane>>3)&1)*8 + lrow;
        aBase[mt] = (uint32_t)m * 64u;
        aSw[mt]   = (uint32_t)((m>>1)&3);
    }
    uint32_t bBase[8], bSw[8];
    const uint32_t bKc = (uint32_t)((lane>>3)&1);
    #pragma unroll
    for (int ng = 0; ng < 8; ng++){
        int n = nwb + ng*16 + (lane>>4)*8 + lrow;
        bBase[ng] = (uint32_t)n * 64u;
        bSw[ng]   = (uint32_t)((n>>1)&3);
    }

    #define QISSUE(ch, s) do { \
        const uint32_t sa = smem_base + (s)*AT_STAGE; \
        const __half* Ag = Q + (size_t)row0*sTokLd + (ch)*32; \
        _Pragma("unroll") \
        for (int i = 0; i < 2; i++){ \
            int t2 = tid + 256*i; int m = t2 >> 2, c2 = t2 & 3; \
            CP16(sa + m*64 + ((c2 ^ ((m>>1)&3)) << 4), Ag + (size_t)m*sTokLd + c2*8); \
        } \
        const uint32_t sb2 = sa + 128*64; \
        const __half* Bg = Kmat + (ch)*32; \
        _Pragma("unroll") \
        for (int i = 0; i < 4; i++){ \
            int t2 = tid + 256*i; int n = t2 >> 2, c2 = t2 & 3; \
            CP16(sb2 + n*64 + ((c2 ^ ((n>>1)&3)) << 4), Bg + (size_t)n*sTokLd + c2*8); \
        } \
        CPCOMMIT(); \
    } while(0)

    const int sTokLd = QKV;

    QISSUE(0, 0);
    {
        #pragma unroll
        for (int i = 0; i < 8; i++){
            int idx = tid + 256*i;
            int t2 = idx >> 3, c2 = idx & 7;
            CP16(smem_base + AT_OFF_V + t2*128 + ((c2 ^ (t2 & 7)) << 4),
                 V + (size_t)t2*sTokLd + c2*8);
        }
        CPCOMMIT();
    }
    QISSUE(1, 1);

    #pragma unroll
    for (int ch = 0; ch < 2; ch++){
        if (ch == 0) CPWAIT(2); else CPWAIT(0);
        __syncthreads();
        const uint32_t sA = smem_base + ch*AT_STAGE;
        const uint32_t sB = sA + 128*64;
        #pragma unroll
        for (int ks = 0; ks < 2; ks++){
            uint32_t af[2][4], bfr[NT][2];
            #pragma unroll
            for (int mt = 0; mt < 2; mt++)
                ldsm4(af[mt], sA + aBase[mt] + ((((uint32_t)(2*ks) + aKc) ^ aSw[mt]) << 4));
            #pragma unroll
            for (int ng = 0; ng < 8; ng++){
                uint32_t r[4];
                ldsm4(r, sB + bBase[ng] + ((((uint32_t)(2*ks) + bKc) ^ bSw[ng]) << 4));
                bfr[2*ng  ][0] = r[0]; bfr[2*ng  ][1] = r[1];
                bfr[2*ng+1][0] = r[2]; bfr[2*ng+1][1] = r[3];
            }
            #pragma unroll
            for (int mt = 0; mt < 2; mt++)
                #pragma unroll
                for (int nt = 0; nt < NT; nt++)
                    mma16(acc[mt][nt], af[mt], bfr[nt]);
        }
        __syncthreads();
    }
    #undef QISSUE

    float* redm = reinterpret_cast<float*>(smp + AT_OFF_R);
    float* reds = redm + 256;

    float rmax[4] = {-3.4e38f, -3.4e38f, -3.4e38f, -3.4e38f};
    #pragma unroll
    for (int mt = 0; mt < 2; mt++){
        const int qi0 = row0 + mwb + mt*16 + g;
        const int qi1 = qi0 + 8;
        #pragma unroll
        for (int nt = 0; nt < NT; nt++){
            const int cx = nwb + nt*8 + c*2;
            float4 v = acc[mt][nt];
            v.x *= ATT_SCALE; v.y *= ATT_SCALE; v.z *= ATT_SCALE; v.w *= ATT_SCALE;
            int2 m0 = *reinterpret_cast<const int2*>(&mask[(size_t)qi0*TT + cx]);
            int2 m1 = *reinterpret_cast<const int2*>(&mask[(size_t)qi1*TT + cx]);
            bool okx = m0.x && (!causal || cx   <= qi0);
            bool oky = m0.y && (!causal || cx+1 <= qi0);
            bool okz = m1.x && (!causal || cx   <= qi1);
            bool okw = m1.y && (!causal || cx+1 <= qi1);
            v.x = okx ? v.x : NEGBIG;
            v.y = oky ? v.y : NEGBIG;
            v.z = okz ? v.z : NEGBIG;
            v.w = okw ? v.w : NEGBIG;
            acc[mt][nt] = v;
            rmax[mt*2+0] = fmaxf(rmax[mt*2+0], fmaxf(v.x, v.y));
            rmax[mt*2+1] = fmaxf(rmax[mt*2+1], fmaxf(v.z, v.w));
        }
    }
    #pragma unroll
    for (int h = 0; h < 4; h++){
        rmax[h] = fmaxf(rmax[h], __shfl_xor_sync(0xffffffffu, rmax[h], 1));
        rmax[h] = fmaxf(rmax[h], __shfl_xor_sync(0xffffffffu, rmax[h], 2));
    }
    const int half_ = w >> 2;
    if (c == 0){
        redm[half_*128 + mwb      + g] = rmax[0];
        redm[half_*128 + mwb +  8 + g] = rmax[1];
        redm[half_*128 + mwb + 16 + g] = rmax[2];
        redm[half_*128 + mwb + 24 + g] = rmax[3];
    }
    __syncthreads();
    float M[4];
    M[0] = fmaxf(redm[mwb      + g], redm[128 + mwb      + g]);
    M[1] = fmaxf(redm[mwb +  8 + g], redm[128 + mwb +  8 + g]);
    M[2] = fmaxf(redm[mwb + 16 + g], redm[128 + mwb + 16 + g]);
    M[3] = fmaxf(redm[mwb + 24 + g], redm[128 + mwb + 24 + g]);

    float rsum[4] = {0.f, 0.f, 0.f, 0.f};
    #pragma unroll
    for (int mt = 0; mt < 2; mt++){
        #pragma unroll
        for (int nt = 0; nt < NT; nt++){
            float4 v = acc[mt][nt];
            v.x = __expf(v.x - M[mt*2+0]);
            v.y = __expf(v.y - M[mt*2+0]);
            v.z = __expf(v.z - M[mt*2+1]);
            v.w = __expf(v.w - M[mt*2+1]);
            acc[mt][nt] = v;
            rsum[mt*2+0] += v.x + v.y;
            rsum[mt*2+1] += v.z + v.w;
        }
    }
    #pragma unroll
    for (int h = 0; h < 4; h++){
        rsum[h] += __shfl_xor_sync(0xffffffffu, rsum[h], 1);
        rsum[h] += __shfl_xor_sync(0xffffffffu, rsum[h], 2);
    }
    if (c == 0){
        reds[half_*128 + mwb      + g] = rsum[0];
        reds[half_*128 + mwb +  8 + g] = rsum[1];
        reds[half_*128 + mwb + 16 + g] = rsum[2];
        reds[half_*128 + mwb + 24 + g] = rsum[3];
    }
    __syncthreads();
    float inv[4];
    inv[0] = 1.f / (reds[mwb      + g] + reds[128 + mwb      + g]);
    inv[1] = 1.f / (reds[mwb +  8 + g] + reds[128 + mwb +  8 + g]);
    inv[2] = 1.f / (reds[mwb + 16 + g] + reds[128 + mwb + 16 + g]);
    inv[3] = 1.f / (reds[mwb + 24 + g] + reds[128 + mwb + 24 + g]);

    uint32_t pa[2][8][4];
    #pragma unroll
    for (int mt = 0; mt < 2; mt++){
        const float i0 = inv[mt*2+0], i1 = inv[mt*2+1];
        #pragma unroll
        for (int j = 0; j < 8; j++){
            float4 v0 = acc[mt][2*j], v1 = acc[mt][2*j+1];
            pa[mt][j][0] = h2pack(v0.x * i0, v0.y * i0);
            pa[mt][j][1] = h2pack(v0.z * i1, v0.w * i1);
            pa[mt][j][2] = h2pack(v1.x * i0, v1.y * i0);
            pa[mt][j][3] = h2pack(v1.z * i1, v1.w * i1);
        }
    }

    float4 accO[2][8];
    #pragma unroll
    for (int mt = 0; mt < 2; mt++)
        #pragma unroll
        for (int nt = 0; nt < 8; nt++)
            accO[mt][nt] = make_float4(0.f, 0.f, 0.f, 0.f);

    const int kb = ((lane>>3)&1)*8 + lrow;
    uint32_t vb[4];
    #pragma unroll
    for (int ng = 0; ng < 4; ng++){
        int nc = ng*2 + (lane>>4);
        vb[ng] = AT_OFF_V + (uint32_t)(nwb + kb)*128u + ((((uint32_t)nc ^ (uint32_t)(kb & 7)) & 7u) << 4);
    }
    #pragma unroll
    for (int j = 0; j < 8; j++){
        uint32_t bfr[8][2];
        #pragma unroll
        for (int ng = 0; ng < 4; ng++){
            uint32_t r[4];
            ldsm4t(r, smem_base + vb[ng] + (uint32_t)j*2048u);
            bfr[2*ng  ][0] = r[0]; bfr[2*ng  ][1] = r[1];
            bfr[2*ng+1][0] = r[2]; bfr[2*ng+1][1] = r[3];
        }
        #pragma unroll
        for (int mt = 0; mt < 2; mt++)
            #pragma unroll
            for (int nt = 0; nt < 8; nt++)
                mma16(accO[mt][nt], pa[mt][j], bfr[nt]);
    }

    float* ps = reinterpret_cast<float*>(smp);    // [128][66]
    if (half_ == 1){
        #pragma unroll
        for (int mt = 0; mt < 2; mt++){
            int rl = mwb + mt*16 + g;
            #pragma unroll
            for (int nt = 0; nt < 8; nt++){
                int cl = nt*8 + c*2;
                float4 v = accO[mt][nt];
                *reinterpret_cast<float2*>(&ps[(size_t)rl*66 + cl])     = make_float2(v.x, v.y);
                *reinterpret_cast<float2*>(&ps[(size_t)(rl+8)*66 + cl]) = make_float2(v.z, v.w);
            }
        }
    }
    __syncthreads();
    if (half_ == 0){
        #pragma unroll
        for (int mt = 0; mt < 2; mt++){
            int rl = mwb + mt*16 + g;
            #pragma unroll
            for (int nt = 0; nt < 8; nt++){
                int cl = nt*8 + c*2;
                float4 v = accO[mt][nt];
                float2 p0 = *reinterpret_cast<float2*>(&ps[(size_t)rl*66 + cl]);
                float2 p1 = *reinterpret_cast<float2*>(&ps[(size_t)(rl+8)*66 + cl]);
                *reinterpret_cast<__half2*>(&O[(size_t)(row0+rl)*CC + cl]) =
                    __floats2half2_rn(v.x + p0.x, v.y + p0.y);
                *reinterpret_cast<__half2*>(&O[(size_t)(row0+rl+8)*CC + cl]) =
                    __floats2half2_rn(v.z + p1.x, v.w + p1.y);
            }
        }
    }
}

// ---------------- host orchestration ----------------
template<typename T>
static T* symaddr(const void* sym){
    void* p = nullptr;
    cudaGetSymbolAddress(&p, sym);
    return (T*)p;
}

#define S3H  (3*(128*128 + 128*128))   // 98304

#define G_PROJ gemm_h<false,false,false,true >
#define G_WO   gemm_h<true ,false,true ,false>
#define G_FF1  gemm_h<true ,true ,false,true >

extern "C" void kernel_launch(void* const* d_in, const int* in_sizes, int n_in,
                              void* d_out, int out_size)
{
    const float* x    = (const float*)d_in[0];
    const float* ca   = (const float*)d_in[1];
    const int*   x_m  = (const int*)  d_in[2];
    const int*   ca_m = (const int*)  d_in[3];
    const float* Wq_s = (const float*)d_in[4];
    const float* Wk_s = (const float*)d_in[5];
    const float* Wv_s = (const float*)d_in[6];
    const float* Wo_s = (const float*)d_in[7];
    const float* bo_s = (const float*)d_in[8];
    const float* Wq_c = (const float*)d_in[9];
    const float* Wk_c = (const float*)d_in[10];
    const float* Wv_c = (const float*)d_in[11];
    const float* Wo_c = (const float*)d_in[12];
    const float* bo_c = (const float*)d_in[13];
    const float* g1   = (const float*)d_in[14];
    const float* be1  = (const float*)d_in[15];
    const float* g2   = (const float*)d_in[16];
    const float* be2  = (const float*)d_in[17];
    const float* g3   = (const float*)d_in[18];
    const float* be3  = (const float*)d_in[19];
    const float* Wf1  = (const float*)d_in[20];
    const float* bf1  = (const float*)d_in[21];
    const float* Wf2  = (const float*)d_in[22];
    const float* bf2  = (const float*)d_in[23];
    float* out = (float*)d_out;

    __half* p_ln  = symaddr<__half>(g_ln);
    __half* p_qkv = symaddr<__half>(g_qkv);
    __half* p_att = symaddr<__half>(g_att);
    __half* p_ca  = symaddr<__half>(g_ca);
    __half* p_h   = symaddr<__half>(g_h);
    __half* p_wqs = symaddr<__half>(g_wqkvs);
    __half* p_wqc = symaddr<__half>(g_wqkvc);
    __half* p_wos = symaddr<__half>(g_wos);
    __half* p_woc = symaddr<__half>(g_woc);
    __half* p_wf1 = symaddr<__half>(g_wf1t);
    __half* p_wf2 = symaddr<__half>(g_wf2t);
    float*  p_x1  = symaddr<float>(g_x1);
    float*  p_x2  = symaddr<float>(g_x2);

    static bool attrDone = false;
    if (!attrDone){
        cudaFuncSetAttribute(G_PROJ, cudaFuncAttributeMaxDynamicSharedMemorySize, S3H);
        cudaFuncSetAttribute(G_WO,   cudaFuncAttributeMaxDynamicSharedMemorySize, S3H);
        cudaFuncSetAttribute(G_FF1,  cudaFuncAttributeMaxDynamicSharedMemorySize, S3H);
        cudaFuncSetAttribute(attn,   cudaFuncAttributeMaxDynamicSharedMemorySize, AT_SMEM);
        attrDone = true;
    }

    // ---- prepass ----
    dim3 tb(32, 8);
    wtrans8<<<dim3(16,16,8), tb>>>(Wq_s, Wk_s, Wv_s, Wo_s, Wq_c, Wk_c, Wv_c, Wo_c,
                                   p_wqs, p_wos, p_wqc, p_woc);
    ttrans<<<dim3(FF/32, CC/32), tb>>>(Wf1, p_wf1, CC, FF);
    ttrans<<<dim3(CC/32, FF/32), tb>>>(Wf2, p_wf2, FF, CC);
    f2h_kernel<<<(MROWS*CC/4+255)/256,256>>>(ca, p_ca, MROWS*CC/4);

    dim3 gQKV(QKV/128, MROWS/128, 1);
    dim3 gQc (CC/128,  MROWS/128, 1);
    dim3 gKVc(1024/128,MROWS/128, 1);
    dim3 gCC (CC/128,  MROWS/128, 1);
    dim3 gFF (FF/128,  MROWS/128, 1);
    dim3 gAT (TT/128, BATCH*NHD);

    const long long sTokQ = (long long)TT*QKV;

    // ===== self-attention =====
    ln_kernel<<<MROWS,128>>>(x, g1, be1, p_ln);
    G_PROJ<<<gQKV,256,S3H>>>(p_ln, CC, p_wqs, CC, nullptr, nullptr, p_qkv, QKV, CC);
    attn<<<gAT,256,AT_SMEM>>>(p_qkv, p_qkv + CC, p_qkv + 1024, sTokQ, x_m, p_att, 1);
    G_WO<<<gCC,256,S3H>>>(p_att, CC, p_wos, CC, bo_s, x, p_x1, CC, CC);

    // ===== cross-attention =====
    ln_kernel<<<MROWS,128>>>(p_x1, g2, be2, p_ln);
    G_PROJ<<<gQc,256,S3H>>>(p_ln, CC, p_wqc, CC, nullptr, nullptr, p_qkv, QKV, CC);
    G_PROJ<<<gKVc,256,S3H>>>(p_ca, CC, p_wqc + (size_t)CC*CC, CC, nullptr, nullptr,
                             p_qkv + CC, QKV, CC);
    attn<<<gAT,256,AT_SMEM>>>(p_qkv, p_qkv + CC, p_qkv + 1024, sTokQ, ca_m, p_att, 0);
    G_WO<<<gCC,256,S3H>>>(p_att, CC, p_woc, CC, bo_c, p_x1, p_x2, CC, CC);

    // ===== feed-forward =====
    ln_kernel<<<MROWS,128>>>(p_x2, g3, be3, p_ln);
    G_FF1<<<gFF,256,S3H>>>(p_ln, CC, p_wf1, CC, bf1, nullptr, p_h, FF, CC);
    G_WO <<<gCC,256,S3H>>>(p_h, FF, p_wf2, FF, bf2, p_x2, out, CC, FF);

    (void)in_sizes; (void)n_in; (void)out_size;
}

// round 10
// speedup vs baseline: 7.4006x; 1.0165x over previous
#include <cuda_runtime.h>
#include <cuda_fp16.h>
#include <cstdint>

#define BATCH 64
#define TT 256
#define CC 512
#define NHD 8
#define HD 64
#define MROWS (BATCH*TT)      // 16384
#define FF 2048
#define QKV 1536
#define ATT_SCALE 0.044194173824159216f   // 512^-0.5
#define NEGBIG (-1e9f)

// ---------------- scratch (device globals; no allocations) ----------------
__device__ __half g_ln  [MROWS*CC];
__device__ __half g_qkv [(size_t)MROWS*QKV];
__device__ __half g_qc  [MROWS*CC];                  // cross-attn Q
__device__ __half g_kvc [(size_t)MROWS*1024];        // cross-attn K|V
__device__ __half g_att [MROWS*CC];
__device__ __half g_ca  [MROWS*CC];
__device__ __half g_h   [(size_t)MROWS*FF];
__device__ __half g_wqkvs[QKV*CC];
__device__ __half g_wqkvc[QKV*CC];
__device__ __half g_wos [CC*CC];
__device__ __half g_woc [CC*CC];
__device__ __half g_wf1t[FF*CC];
__device__ __half g_wf2t[CC*FF];
__device__ float  g_x1  [MROWS*CC];
__device__ float  g_x2  [MROWS*CC];

// ---------------- helpers ----------------
__device__ __forceinline__ void mma16(float4& d, const uint32_t* a, const uint32_t* b){
    asm volatile("mma.sync.aligned.m16n8k16.row.col.f32.f16.f16.f32 "
        "{%0,%1,%2,%3}, {%4,%5,%6,%7}, {%8,%9}, {%0,%1,%2,%3};"
        : "+f"(d.x), "+f"(d.y), "+f"(d.z), "+f"(d.w)
        : "r"(a[0]), "r"(a[1]), "r"(a[2]), "r"(a[3]), "r"(b[0]), "r"(b[1]));
}
__device__ __forceinline__ void ldsm4(uint32_t* r, uint32_t addr){
    asm volatile("ldmatrix.sync.aligned.m8n8.x4.shared.b16 {%0,%1,%2,%3}, [%4];"
        : "=r"(r[0]), "=r"(r[1]), "=r"(r[2]), "=r"(r[3]) : "r"(addr));
}
__device__ __forceinline__ void ldsm4t(uint32_t* r, uint32_t addr){
    asm volatile("ldmatrix.sync.aligned.m8n8.x4.trans.shared.b16 {%0,%1,%2,%3}, [%4];"
        : "=r"(r[0]), "=r"(r[1]), "=r"(r[2]), "=r"(r[3]) : "r"(addr));
}
__device__ __forceinline__ uint32_t h2pack(float a, float b){
    __half2 h = __floats2half2_rn(a, b);
    return *reinterpret_cast<uint32_t*>(&h);
}
#define CP16(d, s) asm volatile("cp.async.cg.shared.global [%0], [%1], 16;" :: "r"(d), "l"(s))
#define CPCOMMIT() asm volatile("cp.async.commit_group;" ::: "memory")
#define CPWAIT(n)  asm volatile("cp.async.wait_group %0;" :: "n"(n) : "memory")

__device__ __forceinline__ float warpSum(float v){
    #pragma unroll
    for (int o = 16; o; o >>= 1) v += __shfl_xor_sync(0xffffffffu, v, o);
    return v;
}

// ---------------- prepass: weight transpose -> fp16 [N][K] ----------------
__global__ void wtrans8(const float* s0, const float* s1, const float* s2, const float* s3,
                        const float* s4, const float* s5, const float* s6, const float* s7,
                        __half* qkvs, __half* wos, __half* qkvc, __half* woc)
{
    int z = blockIdx.z;
    const float* src = (z==0)?s0:(z==1)?s1:(z==2)?s2:(z==3)?s3:(z==4)?s4:(z==5)?s5:(z==6)?s6:s7;
    __half* dst = (z<3) ? qkvs + (size_t)z*CC*CC
               : (z==3) ? wos
               : (z<7) ? qkvc + (size_t)(z-4)*CC*CC
               : woc;
    __shared__ float t[32][33];
    int bx = blockIdx.x*32, by = blockIdx.y*32;
    int x = threadIdx.x, y = threadIdx.y;
    #pragma unroll
    for (int i = 0; i < 32; i += 8)
        t[y+i][x] = src[(size_t)(by + y + i)*CC + bx + x];
    __syncthreads();
    #pragma unroll
    for (int i = 0; i < 32; i += 8)
        dst[(size_t)(bx + y + i)*CC + by + x] = __float2half_rn(t[x][y+i]);
}

__global__ void ttrans(const float* __restrict__ src, __half* __restrict__ dst, int R, int C)
{
    __shared__ float t[32][33];
    int bx = blockIdx.x*32, by = blockIdx.y*32;
    int x = threadIdx.x, y = threadIdx.y;
    #pragma unroll
    for (int i = 0; i < 32; i += 8)
        t[y+i][x] = src[(size_t)(by + y + i)*C + bx + x];
    __syncthreads();
    #pragma unroll
    for (int i = 0; i < 32; i += 8)
        dst[(size_t)(bx + y + i)*R + by + x] = __float2half_rn(t[x][y+i]);
}

__global__ void f2h_kernel(const float* __restrict__ src, __half* __restrict__ dst, int n4){
    int i = blockIdx.x*256 + threadIdx.x;
    if (i < n4){
        float4 v = reinterpret_cast<const float4*>(src)[i];
        reinterpret_cast<__half2*>(dst)[2*i]   = __floats2half2_rn(v.x, v.y);
        reinterpret_cast<__half2*>(dst)[2*i+1] = __floats2half2_rn(v.z, v.w);
    }
}

// ---------------- layernorm (fp16 output) ----------------
__global__ void ln_kernel(const float* __restrict__ x, const float* __restrict__ g,
                          const float* __restrict__ be, __half* __restrict__ y)
{
    int r = blockIdx.x;
    int t = threadIdx.x;
    const float4* xr = reinterpret_cast<const float4*>(x + (size_t)r*CC);
    float4 v = xr[t];
    float s  = v.x + v.y + v.z + v.w;
    float sq = v.x*v.x + v.y*v.y + v.z*v.z + v.w*v.w;

    __shared__ float rs[4], rq[4];
    int lane = t & 31, wid = t >> 5;
    s = warpSum(s); sq = warpSum(sq);
    if (lane == 0){ rs[wid] = s; rq[wid] = sq; }
    __syncthreads();
    if (t == 0){
        float a = rs[0]+rs[1]+rs[2]+rs[3];
        float b = rq[0]+rq[1]+rq[2]+rq[3];
        rs[0] = a * (1.0f/CC);
        rq[0] = b * (1.0f/CC);
    }
    __syncthreads();
    float mu  = rs[0];
    float var = rq[0] - mu*mu;
    float rstd = rsqrtf(var + 1e-5f);

    const float4* g4  = reinterpret_cast<const float4*>(g);
    const float4* be4 = reinterpret_cast<const float4*>(be);
    float4 gg = g4[t], bb = be4[t];
    __half2 o0 = __floats2half2_rn((v.x - mu)*rstd*gg.x + bb.x, (v.y - mu)*rstd*gg.y + bb.y);
    __half2 o1 = __floats2half2_rn((v.z - mu)*rstd*gg.z + bb.z, (v.w - mu)*rstd*gg.w + bb.w);
    __half2* yh = reinterpret_cast<__half2*>(y + (size_t)r*CC);
    yh[2*t]   = o0;
    yh[2*t+1] = o1;
}

// =================== fp16 mma.sync GEMM: BK=64, B [N][K], BN=128 ===================
template<bool BIAS, bool RELU, bool RES, bool HOUT>
__global__ __launch_bounds__(256, 2)
void gemm_h(const __half* __restrict__ A, int lda,
            const __half* __restrict__ B, int ldb,
            const float* __restrict__ bias, const float* __restrict__ res,
            void* __restrict__ Cv, int ldc, int K)
{
    constexpr int NT = 8;
    constexpr int ABYTES = 128*128;
    constexpr int STAGE  = 2*ABYTES;

    extern __shared__ char smp[];
    const uint32_t smem_base = (uint32_t)__cvta_generic_to_shared(smp);

    const int tid  = threadIdx.x;
    const int w    = tid >> 5, lane = tid & 31;
    const int g    = lane >> 2, c = lane & 3;
    const int row0 = blockIdx.y * 128;
    const int col0 = blockIdx.x * 128;

    float* Cf = (float*)Cv;
    __half* Ch = (__half*)Cv;

    float4 acc[2][NT];
    #pragma unroll
    for (int mt = 0; mt < 2; mt++)
        #pragma unroll
        for (int nt = 0; nt < NT; nt++)
            acc[mt][nt] = make_float4(0.f, 0.f, 0.f, 0.f);

    const int nch = K >> 6;
    const int mwb = (w & 3) * 32;
    const int nwb = (w >> 2) * 64;

    const int lrow = lane & 7;
    uint32_t aBase[2], aSw[2];
    const uint32_t aKc = (uint32_t)(lane >> 4);
    #pragma unroll
    for (int mt = 0; mt < 2; mt++){
        int m = mwb + mt*16 + ((lane>>3)&1)*8 + lrow;
        aBase[mt] = (uint32_t)m * 128u;
        aSw[mt]   = (uint32_t)(m & 7);
    }
    uint32_t bBase[NT/2], bSw[NT/2];
    const uint32_t bKc = (uint32_t)((lane>>3)&1);
    #pragma unroll
    for (int ng = 0; ng < NT/2; ng++){
        int n = nwb + ng*16 + (lane>>4)*8 + lrow;
        bBase[ng] = (uint32_t)n * 128u;
        bSw[ng]   = (uint32_t)(n & 7);
    }

    #define ISSUE(ch, s) do { \
        const uint32_t sa = smem_base + (s)*STAGE; \
        const __half* Ag = A + (size_t)row0*lda + (ch)*64; \
        _Pragma("unroll") \
        for (int i = 0; i < 4; i++){ \
            int t2 = tid + 256*i; int m = t2 >> 3, c2 = t2 & 7; \
            CP16(sa + m*128 + ((c2 ^ (m & 7)) << 4), Ag + (size_t)m*lda + c2*8); \
        } \
        const uint32_t sb2 = sa + ABYTES; \
        const __half* Bg = B + (size_t)col0*ldb + (ch)*64; \
        _Pragma("unroll") \
        for (int i = 0; i < 4; i++){ \
            int t2 = tid + 256*i; int n = t2 >> 3, c2 = t2 & 7; \
            CP16(sb2 + n*128 + ((c2 ^ (n & 7)) << 4), Bg + (size_t)n*ldb + c2*8); \
        } \
        CPCOMMIT(); \
    } while(0)

    ISSUE(0, 0);
    ISSUE(1, 1);

    for (int ch = 0; ch < nch; ch++){
        const int p = ch % 3;
        if (ch + 2 < nch) ISSUE(ch+2, (ch+2)%3); else CPCOMMIT();
        CPWAIT(2);
        __syncthreads();

        const uint32_t sA = smem_base + p*STAGE;
        const uint32_t sB = sA + ABYTES;

        #pragma unroll
        for (int ks = 0; ks < 4; ks++){
            uint32_t af[2][4], bfr[NT][2];
            #pragma unroll
            for (int mt = 0; mt < 2; mt++)
                ldsm4(af[mt], sA + aBase[mt] + ((((uint32_t)(2*ks) + aKc) ^ aSw[mt]) << 4));
            #pragma unroll
            for (int ng = 0; ng < NT/2; ng++){
                uint32_t r[4];
                ldsm4(r, sB + bBase[ng] + ((((uint32_t)(2*ks) + bKc) ^ bSw[ng]) << 4));
                bfr[2*ng  ][0] = r[0]; bfr[2*ng  ][1] = r[1];
                bfr[2*ng+1][0] = r[2]; bfr[2*ng+1][1] = r[3];
            }
            #pragma unroll
            for (int mt = 0; mt < 2; mt++)
                #pragma unroll
                for (int nt = 0; nt < NT; nt++)
                    mma16(acc[mt][nt], af[mt], bfr[nt]);
        }
        __syncthreads();
    }

    #pragma unroll
    for (int mt = 0; mt < 2; mt++){
        int r0 = row0 + mwb + mt*16 + g;
        #pragma unroll
        for (int nt = 0; nt < NT; nt++){
            int cx = col0 + nwb + nt*8 + c*2;
            float4 v = acc[mt][nt];
            if (BIAS){
                float b0 = bias[cx], b1 = bias[cx+1];
                v.x += b0; v.y += b1; v.z += b0; v.w += b1;
            }
            if (RELU){
                v.x = fmaxf(v.x, 0.f); v.y = fmaxf(v.y, 0.f);
                v.z = fmaxf(v.z, 0.f); v.w = fmaxf(v.w, 0.f);
            }
            if (RES){
                float2 r1 = *reinterpret_cast<const float2*>(&res[(size_t)r0*ldc + cx]);
                float2 r2 = *reinterpret_cast<const float2*>(&res[(size_t)(r0+8)*ldc + cx]);
                v.x += r1.x; v.y += r1.y; v.z += r2.x; v.w += r2.y;
            }
            if (HOUT){
                *reinterpret_cast<__half2*>(&Ch[(size_t)r0*ldc + cx])     = __floats2half2_rn(v.x, v.y);
                *reinterpret_cast<__half2*>(&Ch[(size_t)(r0+8)*ldc + cx]) = __floats2half2_rn(v.z, v.w);
            } else {
                *reinterpret_cast<float2*>(&Cf[(size_t)r0*ldc + cx])     = make_float2(v.x, v.y);
                *reinterpret_cast<float2*>(&Cf[(size_t)(r0+8)*ldc + cx]) = make_float2(v.z, v.w);
            }
        }
    }
    #undef ISSUE
}

// =================== fused attention: QK^T + mask + softmax + P@V ===================
#define AT_STAGE (128*64 + 256*64)
#define AT_OFF_V (2*AT_STAGE)
#define AT_OFF_R (AT_OFF_V + 256*128)
#define AT_SMEM  (AT_OFF_R + 2048)
__global__ __launch_bounds__(256, 1)
void attn(const __half* __restrict__ Q, int ldq,
          const __half* __restrict__ Kmat, const __half* __restrict__ V, int ldkv,
          const int* __restrict__ mask, __half* __restrict__ O, int causal)
{
    constexpr int NT = 16;
    extern __shared__ char smp[];
    const uint32_t smem_base = (uint32_t)__cvta_generic_to_shared(smp);

    const int tid  = threadIdx.x;
    const int w    = tid >> 5, lane = tid & 31;
    const int g    = lane >> 2, c = lane & 3;
    const int row0 = blockIdx.x * 128;
    {
        const long long zb = blockIdx.y >> 3, zh = blockIdx.y & 7;
        Q    += zb*(long long)TT*ldq  + zh*HD;
        Kmat += zb*(long long)TT*ldkv + zh*HD;
        V    += zb*(long long)TT*ldkv + zh*HD;
        mask += zb*(long long)TT*TT;
        O    += zb*(long long)TT*CC + zh*HD;
    }

    float4 acc[2][NT];
    #pragma unroll
    for (int mt = 0; mt < 2; mt++)
        #pragma unroll
        for (int nt = 0; nt < NT; nt++)
            acc[mt][nt] = make_float4(0.f, 0.f, 0.f, 0.f);

    const int mwb = (w & 3) * 32;
    const int nwb = (w >> 2) * 128;

    const int lrow = lane & 7;
    uint32_t aBase[2], aSw[2];
    const uint32_t aKc = (uint32_t)(lane >> 4);
    #pragma unroll
    for (int mt = 0; mt < 2; mt++){
        int m = mwb + mt*16 + ((lane>>3)&1)*8 + lrow;
        aBase[mt] = (uint32_t)m * 64u;
        aSw[mt]   = (uint32_t)((m>>1)&3);
    }
    uint32_t bBase[8], bSw[8];
    const uint32_t bKc = (uint32_t)((lane>>3)&1);
    #pragma unroll
    for (int ng = 0; ng < 8; ng++){
        int n = nwb + ng*16 + (lane>>4)*8 + lrow;
        bBase[ng] = (uint32_t)n * 64u;
        bSw[ng]   = (uint32_t)((n>>1)&3);
    }

    #define QISSUE(ch, s) do { \
        const uint32_t sa = smem_base + (s)*AT_STAGE; \
        const __half* Ag = Q + (size_t)row0*ldq + (ch)*32; \
        _Pragma("unroll") \
        for (int i = 0; i < 2; i++){ \
            int t2 = tid + 256*i; int m = t2 >> 2, c2 = t2 & 3; \
            CP16(sa + m*64 + ((c2 ^ ((m>>1)&3)) << 4), Ag + (size_t)m*ldq + c2*8); \
        } \
        const uint32_t sb2 = sa + 128*64; \
        const __half* Bg = Kmat + (ch)*32; \
        _Pragma("unroll") \
        for (int i = 0; i < 4; i++){ \
            int t2 = tid + 256*i; int n = t2 >> 2, c2 = t2 & 3; \
            CP16(sb2 + n*64 + ((c2 ^ ((n>>1)&3)) << 4), Bg + (size_t)n*ldkv + c2*8); \
        } \
        CPCOMMIT(); \
    } while(0)

    QISSUE(0, 0);
    {
        #pragma unroll
        for (int i = 0; i < 8; i++){
            int idx = tid + 256*i;
            int t2 = idx >> 3, c2 = idx & 7;
            CP16(smem_base + AT_OFF_V + t2*128 + ((c2 ^ (t2 & 7)) << 4),
                 V + (size_t)t2*ldkv + c2*8);
        }
        CPCOMMIT();
    }
    QISSUE(1, 1);

    #pragma unroll
    for (int ch = 0; ch < 2; ch++){
        if (ch == 0) CPWAIT(2); else CPWAIT(0);
        __syncthreads();
        const uint32_t sA = smem_base + ch*AT_STAGE;
        const uint32_t sB = sA + 128*64;
        #pragma unroll
        for (int ks = 0; ks < 2; ks++){
            uint32_t af[2][4], bfr[NT][2];
            #pragma unroll
            for (int mt = 0; mt < 2; mt++)
                ldsm4(af[mt], sA + aBase[mt] + ((((uint32_t)(2*ks) + aKc) ^ aSw[mt]) << 4));
            #pragma unroll
            for (int ng = 0; ng < 8; ng++){
                uint32_t r[4];
                ldsm4(r, sB + bBase[ng] + ((((uint32_t)(2*ks) + bKc) ^ bSw[ng]) << 4));
                bfr[2*ng  ][0] = r[0]; bfr[2*ng  ][1] = r[1];
                bfr[2*ng+1][0] = r[2]; bfr[2*ng+1][1] = r[3];
            }
            #pragma unroll
            for (int mt = 0; mt < 2; mt++)
                #pragma unroll
                for (int nt = 0; nt < NT; nt++)
                    mma16(acc[mt][nt], af[mt], bfr[nt]);
        }
        __syncthreads();
    }
    #undef QISSUE

    float* redm = reinterpret_cast<float*>(smp + AT_OFF_R);
    float* reds = redm + 256;

    float rmax[4] = {-3.4e38f, -3.4e38f, -3.4e38f, -3.4e38f};
    #pragma unroll
    for (int mt = 0; mt < 2; mt++){
        const int qi0 = row0 + mwb + mt*16 + g;
        const int qi1 = qi0 + 8;
        #pragma unroll
        for (int nt = 0; nt < NT; nt++){
            const int cx = nwb + nt*8 + c*2;
            float4 v = acc[mt][nt];
            v.x *= ATT_SCALE; v.y *= ATT_SCALE; v.z *= ATT_SCALE; v.w *= ATT_SCALE;
            int2 m0 = *reinterpret_cast<const int2*>(&mask[(size_t)qi0*TT + cx]);
            int2 m1 = *reinterpret_cast<const int2*>(&mask[(size_t)qi1*TT + cx]);
            bool okx = m0.x && (!causal || cx   <= qi0);
            bool oky = m0.y && (!causal || cx+1 <= qi0);
            bool okz = m1.x && (!causal || cx   <= qi1);
            bool okw = m1.y && (!causal || cx+1 <= qi1);
            v.x = okx ? v.x : NEGBIG;
            v.y = oky ? v.y : NEGBIG;
            v.z = okz ? v.z : NEGBIG;
            v.w = okw ? v.w : NEGBIG;
            acc[mt][nt] = v;
            rmax[mt*2+0] = fmaxf(rmax[mt*2+0], fmaxf(v.x, v.y));
            rmax[mt*2+1] = fmaxf(rmax[mt*2+1], fmaxf(v.z, v.w));
        }
    }
    #pragma unroll
    for (int h = 0; h < 4; h++){
        rmax[h] = fmaxf(rmax[h], __shfl_xor_sync(0xffffffffu, rmax[h], 1));
        rmax[h] = fmaxf(rmax[h], __shfl_xor_sync(0xffffffffu, rmax[h], 2));
    }
    const int half_ = w >> 2;
    if (c == 0){
        redm[half_*128 + mwb      + g] = rmax[0];
        redm[half_*128 + mwb +  8 + g] = rmax[1];
        redm[half_*128 + mwb + 16 + g] = rmax[2];
        redm[half_*128 + mwb + 24 + g] = rmax[3];
    }
    __syncthreads();
    float M[4];
    M[0] = fmaxf(redm[mwb      + g], redm[128 + mwb      + g]);
    M[1] = fmaxf(redm[mwb +  8 + g], redm[128 + mwb +  8 + g]);
    M[2] = fmaxf(redm[mwb + 16 + g], redm[128 + mwb + 16 + g]);
    M[3] = fmaxf(redm[mwb + 24 + g], redm[128 + mwb + 24 + g]);

    float rsum[4] = {0.f, 0.f, 0.f, 0.f};
    #pragma unroll
    for (int mt = 0; mt < 2; mt++){
        #pragma unroll
        for (int nt = 0; nt < NT; nt++){
            float4 v = acc[mt][nt];
            v.x = __expf(v.x - M[mt*2+0]);
            v.y = __expf(v.y - M[mt*2+0]);
            v.z = __expf(v.z - M[mt*2+1]);
            v.w = __expf(v.w - M[mt*2+1]);
            acc[mt][nt] = v;
            rsum[mt*2+0] += v.x + v.y;
            rsum[mt*2+1] += v.z + v.w;
        }
    }
    #pragma unroll
    for (int h = 0; h < 4; h++){
        rsum[h] += __shfl_xor_sync(0xffffffffu, rsum[h], 1);
        rsum[h] += __shfl_xor_sync(0xffffffffu, rsum[h], 2);
    }
    if (c == 0){
        reds[half_*128 + mwb      + g] = rsum[0];
        reds[half_*128 + mwb +  8 + g] = rsum[1];
        reds[half_*128 + mwb + 16 + g] = rsum[2];
        reds[half_*128 + mwb + 24 + g] = rsum[3];
    }
    __syncthreads();
    float inv[4];
    inv[0] = 1.f / (reds[mwb      + g] + reds[128 + mwb      + g]);
    inv[1] = 1.f / (reds[mwb +  8 + g] + reds[128 + mwb +  8 + g]);
    inv[2] = 1.f / (reds[mwb + 16 + g] + reds[128 + mwb + 16 + g]);
    inv[3] = 1.f / (reds[mwb + 24 + g] + reds[128 + mwb + 24 + g]);

    uint32_t pa[2][8][4];
    #pragma unroll
    for (int mt = 0; mt < 2; mt++){
        const float i0 = inv[mt*2+0], i1 = inv[mt*2+1];
        #pragma unroll
        for (int j = 0; j < 8; j++){
            float4 v0 = acc[mt][2*j], v1 = acc[mt][2*j+1];
            pa[mt][j][0] = h2pack(v0.x * i0, v0.y * i0);
            pa[mt][j][1] = h2pack(v0.z * i1, v0.w * i1);
            pa[mt][j][2] = h2pack(v1.x * i0, v1.y * i0);
            pa[mt][j][3] = h2pack(v1.z * i1, v1.w * i1);
        }
    }

    float4 accO[2][8];
    #pragma unroll
    for (int mt = 0; mt < 2; mt++)
        #pragma unroll
        for (int nt = 0; nt < 8; nt++)
            accO[mt][nt] = make_float4(0.f, 0.f, 0.f, 0.f);

    const int kb = ((lane>>3)&1)*8 + lrow;
    uint32_t vb[4];
    #pragma unroll
    for (int ng = 0; ng < 4; ng++){
        int nc = ng*2 + (lane>>4);
        vb[ng] = AT_OFF_V + (uint32_t)(nwb + kb)*128u + ((((uint32_t)nc ^ (uint32_t)(kb & 7)) & 7u) << 4);
    }
    #pragma unroll
    for (int j = 0; j < 8; j++){
        uint32_t bfr[8][2];
        #pragma unroll
        for (int ng = 0; ng < 4; ng++){
            uint32_t r[4];
            ldsm4t(r, smem_base + vb[ng] + (uint32_t)j*2048u);
            bfr[2*ng  ][0] = r[0]; bfr[2*ng  ][1] = r[1];
            bfr[2*ng+1][0] = r[2]; bfr[2*ng+1][1] = r[3];
        }
        #pragma unroll
        for (int mt = 0; mt < 2; mt++)
            #pragma unroll
            for (int nt = 0; nt < 8; nt++)
                mma16(accO[mt][nt], pa[mt][j], bfr[nt]);
    }

    float* ps = reinterpret_cast<float*>(smp);    // [128][66]
    if (half_ == 1){
        #pragma unroll
        for (int mt = 0; mt < 2; mt++){
            int rl = mwb + mt*16 + g;
            #pragma unroll
            for (int nt = 0; nt < 8; nt++){
                int cl = nt*8 + c*2;
                float4 v = accO[mt][nt];
                *reinterpret_cast<float2*>(&ps[(size_t)rl*66 + cl])     = make_float2(v.x, v.y);
                *reinterpret_cast<float2*>(&ps[(size_t)(rl+8)*66 + cl]) = make_float2(v.z, v.w);
            }
        }
    }
    __syncthreads();
    if (half_ == 0){
        #pragma unroll
        for (int mt = 0; mt < 2; mt++){
            int rl = mwb + mt*16 + g;
            #pragma unroll
            for (int nt = 0; nt < 8; nt++){
                int cl = nt*8 + c*2;
                float4 v = accO[mt][nt];
                float2 p0 = *reinterpret_cast<float2*>(&ps[(size_t)rl*66 + cl]);
                float2 p1 = *reinterpret_cast<float2*>(&ps[(size_t)(rl+8)*66 + cl]);
                *reinterpret_cast<__half2*>(&O[(size_t)(row0+rl)*CC + cl]) =
                    __floats2half2_rn(v.x + p0.x, v.y + p0.y);
                *reinterpret_cast<__half2*>(&O[(size_t)(row0+rl+8)*CC + cl]) =
                    __floats2half2_rn(v.z + p1.x, v.w + p1.y);
            }
        }
    }
}

// ---------------- host orchestration ----------------
template<typename T>
static T* symaddr(const void* sym){
    void* p = nullptr;
    cudaGetSymbolAddress(&p, sym);
    return (T*)p;
}

#define S3H  (3*(128*128 + 128*128))   // 98304

#define G_PROJ gemm_h<false,false,false,true >
#define G_WO   gemm_h<true ,false,true ,false>
#define G_FF1  gemm_h<true ,true ,false,true >

extern "C" void kernel_launch(void* const* d_in, const int* in_sizes, int n_in,
                              void* d_out, int out_size)
{
    const float* x    = (const float*)d_in[0];
    const float* ca   = (const float*)d_in[1];
    const int*   x_m  = (const int*)  d_in[2];
    const int*   ca_m = (const int*)  d_in[3];
    const float* Wq_s = (const float*)d_in[4];
    const float* Wk_s = (const float*)d_in[5];
    const float* Wv_s = (const float*)d_in[6];
    const float* Wo_s = (const float*)d_in[7];
    const float* bo_s = (const float*)d_in[8];
    const float* Wq_c = (const float*)d_in[9];
    const float* Wk_c = (const float*)d_in[10];
    const float* Wv_c = (const float*)d_in[11];
    const float* Wo_c = (const float*)d_in[12];
    const float* bo_c = (const float*)d_in[13];
    const float* g1   = (const float*)d_in[14];
    const float* be1  = (const float*)d_in[15];
    const float* g2   = (const float*)d_in[16];
    const float* be2  = (const float*)d_in[17];
    const float* g3   = (const float*)d_in[18];
    const float* be3  = (const float*)d_in[19];
    const float* Wf1  = (const float*)d_in[20];
    const float* bf1  = (const float*)d_in[21];
    const float* Wf2  = (const float*)d_in[22];
    const float* bf2  = (const float*)d_in[23];
    float* out = (float*)d_out;

    __half* p_ln  = symaddr<__half>(g_ln);
    __half* p_qkv = symaddr<__half>(g_qkv);
    __half* p_qc  = symaddr<__half>(g_qc);
    __half* p_kvc = symaddr<__half>(g_kvc);
    __half* p_att = symaddr<__half>(g_att);
    __half* p_ca  = symaddr<__half>(g_ca);
    __half* p_h   = symaddr<__half>(g_h);
    __half* p_wqs = symaddr<__half>(g_wqkvs);
    __half* p_wqc = symaddr<__half>(g_wqkvc);
    __half* p_wos = symaddr<__half>(g_wos);
    __half* p_woc = symaddr<__half>(g_woc);
    __half* p_wf1 = symaddr<__half>(g_wf1t);
    __half* p_wf2 = symaddr<__half>(g_wf2t);
    float*  p_x1  = symaddr<float>(g_x1);
    float*  p_x2  = symaddr<float>(g_x2);

    static cudaStream_t s1 = nullptr;
    static cudaEvent_t evRoot = nullptr, evW = nullptr, evW2 = nullptr, evKV = nullptr;
    static bool initDone = false;
    if (!initDone){
        cudaFuncSetAttribute(G_PROJ, cudaFuncAttributeMaxDynamicSharedMemorySize, S3H);
        cudaFuncSetAttribute(G_WO,   cudaFuncAttributeMaxDynamicSharedMemorySize, S3H);
        cudaFuncSetAttribute(G_FF1,  cudaFuncAttributeMaxDynamicSharedMemorySize, S3H);
        cudaFuncSetAttribute(attn,   cudaFuncAttributeMaxDynamicSharedMemorySize, AT_SMEM);
        cudaStreamCreateWithFlags(&s1, cudaStreamNonBlocking);
        cudaEventCreateWithFlags(&evRoot, cudaEventDisableTiming);
        cudaEventCreateWithFlags(&evW,    cudaEventDisableTiming);
        cudaEventCreateWithFlags(&evW2,   cudaEventDisableTiming);
        cudaEventCreateWithFlags(&evKV,   cudaEventDisableTiming);
        initDone = true;
    }

    dim3 tb(32, 8);
    dim3 gQKV(QKV/128, MROWS/128, 1);
    dim3 gQc (CC/128,  MROWS/128, 1);
    dim3 gKVc(1024/128,MROWS/128, 1);
    dim3 gCC (CC/128,  MROWS/128, 1);
    dim3 gFF (FF/128,  MROWS/128, 1);
    dim3 gAT (TT/128, BATCH*NHD);

    // ===== fork side stream: prepass + cross K/V projection =====
    cudaEventRecord(evRoot, 0);
    cudaStreamWaitEvent(s1, evRoot, 0);
    wtrans8<<<dim3(16,16,8), tb, 0, s1>>>(Wq_s, Wk_s, Wv_s, Wo_s, Wq_c, Wk_c, Wv_c, Wo_c,
                                          p_wqs, p_wos, p_wqc, p_woc);
    cudaEventRecord(evW, s1);
    ttrans<<<dim3(FF/32, CC/32), tb, 0, s1>>>(Wf1, p_wf1, CC, FF);
    ttrans<<<dim3(CC/32, FF/32), tb, 0, s1>>>(Wf2, p_wf2, FF, CC);
    cudaEventRecord(evW2, s1);
    f2h_kernel<<<(MROWS*CC/4+255)/256, 256, 0, s1>>>(ca, p_ca, MROWS*CC/4);
    G_PROJ<<<gKVc,256,S3H,s1>>>(p_ca, CC, p_wqc + (size_t)CC*CC, CC, nullptr, nullptr,
                                p_kvc, 1024, CC);
    cudaEventRecord(evKV, s1);

    // ===== main chain (default stream) =====
    // self-attention
    ln_kernel<<<MROWS,128>>>(x, g1, be1, p_ln);
    cudaStreamWaitEvent(0, evW, 0);
    G_PROJ<<<gQKV,256,S3H>>>(p_ln, CC, p_wqs, CC, nullptr, nullptr, p_qkv, QKV, CC);
    attn<<<gAT,256,AT_SMEM>>>(p_qkv, QKV, p_qkv + CC, p_qkv + 1024, QKV, x_m, p_att, 1);
    G_WO<<<gCC,256,S3H>>>(p_att, CC, p_wos, CC, bo_s, x, p_x1, CC, CC);

    // cross-attention
    ln_kernel<<<MROWS,128>>>(p_x1, g2, be2, p_ln);
    G_PROJ<<<gQc,256,S3H>>>(p_ln, CC, p_wqc, CC, nullptr, nullptr, p_qc, CC, CC);
    cudaStreamWaitEvent(0, evKV, 0);
    attn<<<gAT,256,AT_SMEM>>>(p_qc, CC, p_kvc, p_kvc + CC, 1024, ca_m, p_att, 0);
    G_WO<<<gCC,256,S3H>>>(p_att, CC, p_woc, CC, bo_c, p_x1, p_x2, CC, CC);

    // feed-forward
    ln_kernel<<<MROWS,128>>>(p_x2, g3, be3, p_ln);
    cudaStreamWaitEvent(0, evW2, 0);
    G_FF1<<<gFF,256,S3H>>>(p_ln, CC, p_wf1, CC, bf1, nullptr, p_h, FF, CC);
    G_WO <<<gCC,256,S3H>>>(p_h, FF, p_wf2, FF, bf2, p_x2, out, CC, FF);

    (void)in_sizes; (void)n_in; (void)out_size;
}